// round 1
// baseline (speedup 1.0000x reference)
#include <cuda_runtime.h>
#include <math.h>

// ---------------- problem constants ----------------
#define NSAMP 256
#define CIN   2304
#define CH    512
#define HH    7
#define WW    7
#define HW    49
#define NG    16         // groups
#define GSZ   16         // samples per group
#define K_RED (CIN*9)    // 20736
#define K_CC  (CH*9)     // 4608
#define FEAT_ELEMS (NSAMP*CH*HW)   // 6422528
#define EPSG  1e-5f
#define ATT_SCALE 0.044194173824159216f  // 1/sqrt(512)

// ---------------- scratch (device globals; no allocation) ----------------
__device__ float g_wtR [K_RED*CH];
__device__ float g_wtK1[K_CC*CH];
__device__ float g_wtV1[K_CC*CH];
__device__ float g_wtK2[K_CC*CH];
__device__ float g_wtV2[K_CC*CH];
__device__ float g_wtC1[K_CC*CH];
__device__ float g_wtC2[K_CC*CH];

__device__ float g_feat [FEAT_ELEMS];
__device__ float g_q1   [FEAT_ELEMS];   // later reused as h1
__device__ float g_q2   [FEAT_ELEMS];   // later reused as h2
__device__ float g_k1   [FEAT_ELEMS];
__device__ float g_v1   [FEAT_ELEMS];
__device__ float g_k2   [FEAT_ELEMS];
__device__ float g_v2   [FEAT_ELEMS];
__device__ float g_vir1 [FEAT_ELEMS];
__device__ float g_vir2 [FEAT_ELEMS];
__device__ float g_stats[1024];         // mu1, rstd1, mu2, rstd2 (256 each)

// ---------------- weight transpose: w[co][k] -> wt[k][co] ----------------
__global__ void transpose_k(const float* __restrict__ src, float* __restrict__ dst,
                            int rows /*Cout*/, int cols /*K*/) {
    __shared__ float tile[32][33];
    int c0 = blockIdx.x * 32, r0 = blockIdx.y * 32;
    int x = threadIdx.x, y = threadIdx.y;   // 32 x 8
    #pragma unroll
    for (int i = 0; i < 32; i += 8) {
        int r = r0 + y + i, c = c0 + x;
        tile[y + i][x] = (r < rows && c < cols) ? src[r * cols + c] : 0.f;
    }
    __syncthreads();
    #pragma unroll
    for (int i = 0; i < 32; i += 8) {
        int r = r0 + x, c = c0 + y + i;
        if (c < cols && r < rows) dst[c * rows + r] = tile[x][y + i];
    }
}

// ---------------- implicit-GEMM conv (3x3, pad 1, 7x7) ----------------
// out[n,co,p] = sum_k A[m,k] * Wt[k,co], m=(n,p), k=(ci,dy,dx)
#define BM 64
#define BN 64
#define BK 16
__global__ void conv_gemm(const float* __restrict__ in,    // (N, Cin, 7, 7)
                          const float* __restrict__ wt,    // (K, Cout)
                          const float* __restrict__ addsrc,// (N, Cout, 49) or null
                          float* __restrict__ out,         // (N, Cout, 49)
                          int Cin) {
    const int K = Cin * 9;
    __shared__ float As[BK][BM];
    __shared__ float Bs[BK][BN];
    __shared__ int rowBase[BM];
    __shared__ int rowY[BM];
    __shared__ int rowX[BM];

    const int m0 = blockIdx.x * BM;
    const int n0 = blockIdx.y * BN;
    const int tid = threadIdx.x;           // 256

    for (int r = tid; r < BM; r += 256) {
        int m = m0 + r;
        int nn = m / HW, p = m - nn * HW;
        rowBase[r] = nn * Cin * HW;
        rowY[r] = p / WW;
        rowX[r] = p - (p / WW) * WW;
    }
    __syncthreads();

    float acc[4][4] = {};
    const int ty = tid >> 4, tx = tid & 15;

    for (int k0 = 0; k0 < K; k0 += BK) {
        #pragma unroll
        for (int i = 0; i < 4; i++) {
            int e = tid + i * 256;
            int kk = e >> 6, r = e & 63;
            int k = k0 + kk;
            int ci = k / 9, t = k - ci * 9;
            int dy = t / 3 - 1, dx = t - (t / 3) * 3 - 1;
            int yy = rowY[r] + dy, xx = rowX[r] + dx;
            float v = 0.f;
            if ((unsigned)yy < 7u && (unsigned)xx < 7u)
                v = in[rowBase[r] + ci * HW + yy * WW + xx];
            As[kk][r] = v;
        }
        #pragma unroll
        for (int i = 0; i < 4; i++) {
            int e = tid + i * 256;
            int kk = e >> 6, cc = e & 63;
            Bs[kk][cc] = wt[(k0 + kk) * CH + n0 + cc];
        }
        __syncthreads();
        #pragma unroll
        for (int kk = 0; kk < BK; kk++) {
            float4 a4 = *reinterpret_cast<const float4*>(&As[kk][ty * 4]);
            float4 b4 = *reinterpret_cast<const float4*>(&Bs[kk][tx * 4]);
            float a[4] = {a4.x, a4.y, a4.z, a4.w};
            float b[4] = {b4.x, b4.y, b4.z, b4.w};
            #pragma unroll
            for (int i = 0; i < 4; i++)
                #pragma unroll
                for (int j = 0; j < 4; j++)
                    acc[i][j] += a[i] * b[j];
        }
        __syncthreads();
    }

    #pragma unroll
    for (int i = 0; i < 4; i++) {
        int m = m0 + ty * 4 + i;
        int nn = m / HW, p = m - nn * HW;
        #pragma unroll
        for (int j = 0; j < 4; j++) {
            int co = n0 + tx * 4 + j;
            int idx = (nn * CH + co) * HW + p;
            float v = acc[i][j];
            if (addsrc) v += addsrc[idx];
            out[idx] = v;
        }
    }
}

// ---------------- q-conv: spatially-constant input conv ----------------
// s[n] = [status[n,scol], rois[n,1..4]];  q[n,co,y,x] = sum over valid taps
__global__ void q_conv(const float* __restrict__ status, const float* __restrict__ rois,
                       const float* __restrict__ wq, float* __restrict__ out, int scol) {
    int idx = blockIdx.x * 256 + threadIdx.x;
    if (idx >= NSAMP * CH * HW) return;
    int p = idx % HW;
    int t2 = idx / HW;
    int co = t2 % CH;
    int n = t2 / CH;
    int y = p / WW, x = p - (p / WW) * WW;
    float s[5];
    s[0] = status[n * 2 + scol];
    s[1] = rois[n * 5 + 1];
    s[2] = rois[n * 5 + 2];
    s[3] = rois[n * 5 + 3];
    s[4] = rois[n * 5 + 4];
    const float* w = wq + co * 45;
    float acc = 0.f;
    #pragma unroll
    for (int ci = 0; ci < 5; ci++) {
        #pragma unroll
        for (int dy = 0; dy < 3; dy++) {
            #pragma unroll
            for (int dx = 0; dx < 3; dx++) {
                int yy = y + dy - 1, xx = x + dx - 1;
                if ((unsigned)yy < 7u && (unsigned)xx < 7u)
                    acc += w[ci * 9 + dy * 3 + dx] * s[ci];
            }
        }
    }
    out[idx] = acc;
}

// ---------------- attention: per (g, hw): att=QK^T, softmax, virt=att V ----
#define CCH 256
__global__ void attn_kernel(const float* __restrict__ q, const float* __restrict__ k,
                            const float* __restrict__ v, float* __restrict__ virt) {
    int hw = blockIdx.x;   // 0..48
    int g  = blockIdx.y;   // 0..15
    __shared__ float bufA[GSZ][CCH + 1];
    __shared__ float bufB[GSZ][CCH + 1];
    __shared__ float att [GSZ][GSZ + 1];
    __shared__ float attn[GSZ][GSZ + 1];

    int tid = threadIdx.x;            // 256
    int i = tid >> 4, j = tid & 15;
    float a = 0.f;

    for (int c0 = 0; c0 < CH; c0 += CCH) {
        for (int e = tid; e < GSZ * CCH; e += 256) {
            int r = e >> 8, c = e & 255;
            int gidx = ((g * GSZ + r) * CH + c0 + c) * HW + hw;
            bufA[r][c] = q[gidx];
            bufB[r][c] = k[gidx];
        }
        __syncthreads();
        #pragma unroll 8
        for (int c = 0; c < CCH; c++)
            a += bufA[i][c] * bufB[j][c];
        __syncthreads();
    }
    att[i][j] = a * ATT_SCALE;
    __syncthreads();

    // softmax over j for row i
    float mx = att[i][0];
    #pragma unroll
    for (int jj = 1; jj < GSZ; jj++) mx = fmaxf(mx, att[i][jj]);
    float sum = 0.f;
    #pragma unroll
    for (int jj = 0; jj < GSZ; jj++) sum += expf(att[i][jj] - mx);
    attn[i][j] = expf(att[i][j] - mx) / sum;
    __syncthreads();

    // virt[i][c] = sum_j attn[i][j] * v[j][c]
    for (int c0 = 0; c0 < CH; c0 += CCH) {
        for (int e = tid; e < GSZ * CCH; e += 256) {
            int r = e >> 8, c = e & 255;
            bufA[r][c] = v[((g * GSZ + r) * CH + c0 + c) * HW + hw];
        }
        __syncthreads();
        for (int e = tid; e < GSZ * CCH; e += 256) {
            int r = e >> 8, c = e & 255;
            float s = 0.f;
            #pragma unroll
            for (int jj = 0; jj < GSZ; jj++) s += attn[r][jj] * bufA[jj][c];
            virt[((g * GSZ + r) * CH + c0 + c) * HW + hw] = s;
        }
        __syncthreads();
    }
}

// ---------------- groupnorm stats (per-sample mean/var over C*HW) ----------
__global__ void gn_stats(const float* __restrict__ x, float* __restrict__ mu,
                         float* __restrict__ rstd) {
    __shared__ float ss[256], sq[256];
    int n = blockIdx.x;
    const float* p = x + n * CH * HW;
    float a = 0.f, b = 0.f;
    for (int e = threadIdx.x; e < CH * HW; e += 256) {
        float v = p[e];
        a += v; b += v * v;
    }
    ss[threadIdx.x] = a; sq[threadIdx.x] = b;
    __syncthreads();
    for (int s = 128; s > 0; s >>= 1) {
        if (threadIdx.x < s) { ss[threadIdx.x] += ss[threadIdx.x + s]; sq[threadIdx.x] += sq[threadIdx.x + s]; }
        __syncthreads();
    }
    if (threadIdx.x == 0) {
        float m = ss[0] / (float)(CH * HW);
        float var = sq[0] / (float)(CH * HW) - m * m;
        mu[n] = m;
        rstd[n] = rsqrtf(var + EPSG);
    }
}

// ---------------- normalize + affine + relu ----------------
__global__ void norm_relu(const float* __restrict__ x, const float* __restrict__ mu,
                          const float* __restrict__ rstd, const float* __restrict__ gamma,
                          const float* __restrict__ beta, float* __restrict__ out) {
    int idx = blockIdx.x * 256 + threadIdx.x;
    if (idx >= FEAT_ELEMS) return;
    int n = idx / (CH * HW);
    int c = (idx / HW) % CH;
    float v = (x[idx] - mu[n]) * rstd[n];
    v = v * gamma[c] + beta[c];
    out[idx] = fmaxf(v, 0.f);
}

// ---------------- launcher ----------------
extern "C" void kernel_launch(void* const* d_in, const int* in_sizes, int n_in,
                              void* d_out, int out_size) {
    const float* status = (const float*)d_in[0];
    const float* rois   = (const float*)d_in[1];
    const float* bbox   = (const float*)d_in[2];
    const float* wR     = (const float*)d_in[3];
    const float* wQ1    = (const float*)d_in[4];
    const float* wQ2    = (const float*)d_in[5];
    const float* wK1    = (const float*)d_in[6];
    const float* wV1    = (const float*)d_in[7];
    const float* wK2    = (const float*)d_in[8];
    const float* wV2    = (const float*)d_in[9];
    const float* wC1    = (const float*)d_in[10];
    const float* wC2    = (const float*)d_in[11];
    const float* gamma  = (const float*)d_in[12];
    const float* beta   = (const float*)d_in[13];
    float* out1 = (float*)d_out;
    float* out2 = out1 + FEAT_ELEMS;

    float *wtR, *wtK1, *wtV1, *wtK2, *wtV2, *wtC1, *wtC2;
    float *feat, *q1, *q2, *k1, *v1, *k2, *v2, *vir1, *vir2, *stats;
    cudaGetSymbolAddress((void**)&wtR,  g_wtR);
    cudaGetSymbolAddress((void**)&wtK1, g_wtK1);
    cudaGetSymbolAddress((void**)&wtV1, g_wtV1);
    cudaGetSymbolAddress((void**)&wtK2, g_wtK2);
    cudaGetSymbolAddress((void**)&wtV2, g_wtV2);
    cudaGetSymbolAddress((void**)&wtC1, g_wtC1);
    cudaGetSymbolAddress((void**)&wtC2, g_wtC2);
    cudaGetSymbolAddress((void**)&feat, g_feat);
    cudaGetSymbolAddress((void**)&q1,   g_q1);
    cudaGetSymbolAddress((void**)&q2,   g_q2);
    cudaGetSymbolAddress((void**)&k1,   g_k1);
    cudaGetSymbolAddress((void**)&v1,   g_v1);
    cudaGetSymbolAddress((void**)&k2,   g_k2);
    cudaGetSymbolAddress((void**)&v2,   g_v2);
    cudaGetSymbolAddress((void**)&vir1, g_vir1);
    cudaGetSymbolAddress((void**)&vir2, g_vir2);
    cudaGetSymbolAddress((void**)&stats, g_stats);

    dim3 tb(32, 8);
    // weight transposes
    transpose_k<<<dim3((K_RED + 31) / 32, CH / 32), tb>>>(wR,  wtR,  CH, K_RED);
    transpose_k<<<dim3((K_CC  + 31) / 32, CH / 32), tb>>>(wK1, wtK1, CH, K_CC);
    transpose_k<<<dim3((K_CC  + 31) / 32, CH / 32), tb>>>(wV1, wtV1, CH, K_CC);
    transpose_k<<<dim3((K_CC  + 31) / 32, CH / 32), tb>>>(wK2, wtK2, CH, K_CC);
    transpose_k<<<dim3((K_CC  + 31) / 32, CH / 32), tb>>>(wV2, wtV2, CH, K_CC);
    transpose_k<<<dim3((K_CC  + 31) / 32, CH / 32), tb>>>(wC1, wtC1, CH, K_CC);
    transpose_k<<<dim3((K_CC  + 31) / 32, CH / 32), tb>>>(wC2, wtC2, CH, K_CC);

    const dim3 cg(NSAMP * HW / BM, CH / BN);   // (196, 8)
    // feat = conv(bbox_feat, w_reduce)
    conv_gemm<<<cg, 256>>>(bbox, wtR, nullptr, feat, CIN);

    // q convs (spatially-constant input)
    q_conv<<<(FEAT_ELEMS + 255) / 256, 256>>>(status, rois, wQ1, q1, 0);
    q_conv<<<(FEAT_ELEMS + 255) / 256, 256>>>(status, rois, wQ2, q2, 1);

    // k/v convs from feat
    conv_gemm<<<cg, 256>>>(feat, wtK1, nullptr, k1, CH);
    conv_gemm<<<cg, 256>>>(feat, wtV1, nullptr, v1, CH);
    conv_gemm<<<cg, 256>>>(feat, wtK2, nullptr, k2, CH);
    conv_gemm<<<cg, 256>>>(feat, wtV2, nullptr, v2, CH);

    // attention per branch
    attn_kernel<<<dim3(HW, NG), 256>>>(q1, k1, v1, vir1);
    attn_kernel<<<dim3(HW, NG), 256>>>(q2, k2, v2, vir2);

    // groupnorm stats
    gn_stats<<<NSAMP, 256>>>(vir1, stats + 0,   stats + 256);
    gn_stats<<<NSAMP, 256>>>(vir2, stats + 512, stats + 768);

    // normalize+relu (reuse q buffers as h)
    norm_relu<<<(FEAT_ELEMS + 255) / 256, 256>>>(vir1, stats + 0,   stats + 256, gamma, beta, q1);
    norm_relu<<<(FEAT_ELEMS + 255) / 256, 256>>>(vir2, stats + 512, stats + 768, gamma, beta, q2);

    // out = feat + conv(h, w_c)
    conv_gemm<<<cg, 256>>>(q1, wtC1, feat, out1, CH);
    conv_gemm<<<cg, 256>>>(q2, wtC2, feat, out2, CH);
}

// round 3
// speedup vs baseline: 2.5551x; 2.5551x over previous
#include <cuda_runtime.h>
#include <cuda_bf16.h>
#include <cstdint>
#include <math.h>

// ---------------- problem constants ----------------
#define NSAMP 256
#define CIN   2304
#define CH    512
#define HW    49
#define NG    16
#define GSZ   16
#define K_RED (CIN*9)    // 20736
#define K_CC  (CH*9)     // 4608
#define FEAT_ELEMS (NSAMP*CH*HW)   // 6422528
#define EPSG  1e-5f
#define ATT_SCALE 0.044194173824159216f  // 1/sqrt(512)

// ---------------- scratch (device globals; no allocation) ----------------
__device__ float g_feat [FEAT_ELEMS];
__device__ float g_q1   [FEAT_ELEMS];   // later reused as h1
__device__ float g_q2   [FEAT_ELEMS];   // later reused as h2
__device__ float g_k1   [FEAT_ELEMS];
__device__ float g_v1   [FEAT_ELEMS];
__device__ float g_k2   [FEAT_ELEMS];
__device__ float g_v2   [FEAT_ELEMS];
__device__ float g_vir1 [FEAT_ELEMS];
__device__ float g_vir2 [FEAT_ELEMS];
__device__ float g_stats[1024];

// split weights (bf16 hi/lo), native [co][K] layout
__device__ __nv_bfloat16 g_wRhi[K_RED*CH],  g_wRlo[K_RED*CH];
__device__ __nv_bfloat16 g_wK1hi[K_CC*CH],  g_wK1lo[K_CC*CH];
__device__ __nv_bfloat16 g_wV1hi[K_CC*CH],  g_wV1lo[K_CC*CH];
__device__ __nv_bfloat16 g_wK2hi[K_CC*CH],  g_wK2lo[K_CC*CH];
__device__ __nv_bfloat16 g_wV2hi[K_CC*CH],  g_wV2lo[K_CC*CH];
__device__ __nv_bfloat16 g_wC1hi[K_CC*CH],  g_wC1lo[K_CC*CH];
__device__ __nv_bfloat16 g_wC2hi[K_CC*CH],  g_wC2lo[K_CC*CH];

// ---------------- weight split kernel ----------------
__global__ void split_w(const float* __restrict__ w, __nv_bfloat16* __restrict__ hi,
                        __nv_bfloat16* __restrict__ lo, int n) {
    int i = blockIdx.x * 256 + threadIdx.x;
    if (i >= n) return;
    float v = w[i];
    __nv_bfloat16 h = __float2bfloat16(v);
    float r = v - __bfloat162float(h);
    hi[i] = h;
    lo[i] = __float2bfloat16(r);
}

// ---------------- bf16 mma.sync helper ----------------
__device__ __forceinline__ void mma_bf16(float* d, const uint32_t* a, const uint32_t* b) {
    asm volatile(
        "mma.sync.aligned.m16n8k16.row.col.f32.bf16.bf16.f32 "
        "{%0,%1,%2,%3}, {%4,%5,%6,%7}, {%8,%9}, {%0,%1,%2,%3};\n"
        : "+f"(d[0]), "+f"(d[1]), "+f"(d[2]), "+f"(d[3])
        : "r"(a[0]), "r"(a[1]), "r"(a[2]), "r"(a[3]), "r"(b[0]), "r"(b[1]));
}

// ---------------- HMMA implicit-GEMM conv (3x3, pad 1, 7x7) ----------------
// out[n,co,p] = sum_k im2col[m,k] * w[co,k];  m=(n,p)
// CTA tile 128x128, 8 warps (2 x 4), warp tile 64x32, K chunk 32 (2 ksteps).
#define KC   32
#define KCP  40           // padded SMEM row stride (bf16 units) = 80 bytes

__global__ void __launch_bounds__(256, 2)
conv_mma(const float* __restrict__ in,
         const __nv_bfloat16* __restrict__ whi,
         const __nv_bfloat16* __restrict__ wlo,
         const float* __restrict__ addsrc, float* __restrict__ out, int Cin) {
    const int K = Cin * 9;
    const int NC = K / KC;

    __shared__ __nv_bfloat16 sAhi[128 * KCP];
    __shared__ __nv_bfloat16 sAlo[128 * KCP];
    __shared__ __nv_bfloat16 sBhi[128 * KCP];
    __shared__ __nv_bfloat16 sBlo[128 * KCP];

    const int tid = threadIdx.x;
    const int wid = tid >> 5, lane = tid & 31;
    const int g = lane >> 2, tg = lane & 3;
    const int m0 = blockIdx.x * 128;
    const int n0 = blockIdx.y * 128;
    const int wm = (wid & 1) * 64;      // warp M offset
    const int wn = (wid >> 1) * 32;     // warp N offset

    // A-gather geometry: thread covers rows r = (lane>>3) + 4*wid + 32*ii,
    // k-cols kk = (lane&7) + 8*jj
    const int rr = lane >> 3;
    const int kk8 = lane & 7;
    int rbase[4], ryv[4], rxv[4];
#pragma unroll
    for (int ii = 0; ii < 4; ii++) {
        int r = rr + 4 * wid + 32 * ii;
        int m = m0 + r;
        int n = m / 49, p = m - 49 * n;
        rbase[ii] = n * Cin * 49;
        ryv[ii] = p / 7;
        rxv[ii] = p - 7 * (p / 7);
    }

    float acc[4][4][4];
#pragma unroll
    for (int t = 0; t < 4; t++)
#pragma unroll
        for (int u = 0; u < 4; u++)
#pragma unroll
            for (int e = 0; e < 4; e++) acc[t][u][e] = 0.f;

    for (int c = 0; c < NC; c++) {
        const int k0 = c * KC;
        __syncthreads();   // protect smem reuse from previous iter's compute

        // ---- A tile: im2col gather + bf16 hi/lo split ----
#pragma unroll
        for (int jj = 0; jj < 4; jj++) {
            int kk = kk8 + 8 * jj;
            int k = k0 + kk;
            int ci = k / 9, t9 = k - 9 * ci;
            int dy = t9 / 3 - 1, dx = t9 - 3 * (t9 / 3) - 1;
            int coff = ci * 49 + dy * 7 + dx;
#pragma unroll
            for (int ii = 0; ii < 4; ii++) {
                int yy = ryv[ii] + dy, xx = rxv[ii] + dx;
                float v = 0.f;
                if ((unsigned)yy < 7u && (unsigned)xx < 7u)
                    v = in[rbase[ii] + coff + ryv[ii] * 7 + rxv[ii]];
                __nv_bfloat16 h = __float2bfloat16(v);
                float rres = v - __bfloat162float(h);
                int r = rr + 4 * wid + 32 * ii;
                sAhi[r * KCP + kk] = h;
                sAlo[r * KCP + kk] = __float2bfloat16(rres);
            }
        }
        // ---- B tile: pre-split weights, native layout, vector loads ----
#pragma unroll
        for (int i = 0; i < 2; i++) {
            int e = tid + 256 * i;          // 0..511 (uint4 = 8 bf16)
            int row = e >> 2, seg = e & 3;
            size_t goff = (size_t)(n0 + row) * K + k0 + seg * 8;
            *reinterpret_cast<uint4*>(&sBhi[row * KCP + seg * 8]) =
                *reinterpret_cast<const uint4*>(whi + goff);
            *reinterpret_cast<uint4*>(&sBlo[row * KCP + seg * 8]) =
                *reinterpret_cast<const uint4*>(wlo + goff);
        }
        __syncthreads();

        // ---- compute: 2 ksteps of 16 ----
#pragma unroll
        for (int s = 0; s < 2; s++) {
            uint32_t bhi[4][2], blo[4][2];
            const int bk = 16 * s + tg * 2;
#pragma unroll
            for (int u = 0; u < 4; u++) {
                int bn = wn + 8 * u + g;
                bhi[u][0] = *reinterpret_cast<const uint32_t*>(&sBhi[bn * KCP + bk]);
                bhi[u][1] = *reinterpret_cast<const uint32_t*>(&sBhi[bn * KCP + bk + 8]);
                blo[u][0] = *reinterpret_cast<const uint32_t*>(&sBlo[bn * KCP + bk]);
                blo[u][1] = *reinterpret_cast<const uint32_t*>(&sBlo[bn * KCP + bk + 8]);
            }
#pragma unroll
            for (int t = 0; t < 4; t++) {
                uint32_t ahi[4], alo[4];
                int arow = wm + 16 * t + g;
                int acol = 16 * s + tg * 2;
                ahi[0] = *reinterpret_cast<const uint32_t*>(&sAhi[arow * KCP + acol]);
                ahi[1] = *reinterpret_cast<const uint32_t*>(&sAhi[(arow + 8) * KCP + acol]);
                ahi[2] = *reinterpret_cast<const uint32_t*>(&sAhi[arow * KCP + acol + 8]);
                ahi[3] = *reinterpret_cast<const uint32_t*>(&sAhi[(arow + 8) * KCP + acol + 8]);
                alo[0] = *reinterpret_cast<const uint32_t*>(&sAlo[arow * KCP + acol]);
                alo[1] = *reinterpret_cast<const uint32_t*>(&sAlo[(arow + 8) * KCP + acol]);
                alo[2] = *reinterpret_cast<const uint32_t*>(&sAlo[arow * KCP + acol + 8]);
                alo[3] = *reinterpret_cast<const uint32_t*>(&sAlo[(arow + 8) * KCP + acol + 8]);
#pragma unroll
                for (int u = 0; u < 4; u++) {
                    mma_bf16(acc[t][u], ahi, bhi[u]);
                    mma_bf16(acc[t][u], ahi, blo[u]);
                    mma_bf16(acc[t][u], alo, bhi[u]);
                }
            }
        }
    }

    // ---- epilogue ----
#pragma unroll
    for (int t = 0; t < 4; t++) {
#pragma unroll
        for (int h = 0; h < 2; h++) {
            int row = m0 + wm + 16 * t + g + 8 * h;
            int n = row / 49, p = row - 49 * n;
            size_t base = (size_t)n * CH * 49 + p;
#pragma unroll
            for (int u = 0; u < 4; u++) {
                int col = n0 + wn + 8 * u + tg * 2;
                size_t i0 = base + (size_t)col * 49;
                float v0 = acc[t][u][2 * h];
                float v1 = acc[t][u][2 * h + 1];
                if (addsrc) { v0 += addsrc[i0]; v1 += addsrc[i0 + 49]; }
                out[i0] = v0;
                out[i0 + 49] = v1;
            }
        }
    }
}

// ---------------- q-conv: spatially-constant input conv ----------------
__global__ void q_conv(const float* __restrict__ status, const float* __restrict__ rois,
                       const float* __restrict__ wq, float* __restrict__ out, int scol) {
    int idx = blockIdx.x * 256 + threadIdx.x;
    if (idx >= NSAMP * CH * HW) return;
    int p = idx % HW;
    int t2 = idx / HW;
    int co = t2 % CH;
    int n = t2 / CH;
    int y = p / 7, x = p - (p / 7) * 7;
    float s[5];
    s[0] = status[n * 2 + scol];
    s[1] = rois[n * 5 + 1];
    s[2] = rois[n * 5 + 2];
    s[3] = rois[n * 5 + 3];
    s[4] = rois[n * 5 + 4];
    const float* w = wq + co * 45;
    float acc = 0.f;
#pragma unroll
    for (int ci = 0; ci < 5; ci++)
#pragma unroll
        for (int dy = 0; dy < 3; dy++)
#pragma unroll
            for (int dx = 0; dx < 3; dx++) {
                int yy = y + dy - 1, xx = x + dx - 1;
                if ((unsigned)yy < 7u && (unsigned)xx < 7u)
                    acc += w[ci * 9 + dy * 3 + dx] * s[ci];
            }
    out[idx] = acc;
}

// ---------------- attention per (g, hw) ----------------
#define CCH 256
__global__ void attn_kernel(const float* __restrict__ q, const float* __restrict__ k,
                            const float* __restrict__ v, float* __restrict__ virt) {
    int hw = blockIdx.x;
    int gg = blockIdx.y;
    __shared__ float bufA[GSZ][CCH + 1];
    __shared__ float bufB[GSZ][CCH + 1];
    __shared__ float att[GSZ][GSZ + 1];
    __shared__ float attn[GSZ][GSZ + 1];

    int tid = threadIdx.x;
    int i = tid >> 4, j = tid & 15;
    float a = 0.f;

    for (int c0 = 0; c0 < CH; c0 += CCH) {
        for (int e = tid; e < GSZ * CCH; e += 256) {
            int r = e >> 8, c = e & 255;
            int gidx = ((gg * GSZ + r) * CH + c0 + c) * HW + hw;
            bufA[r][c] = q[gidx];
            bufB[r][c] = k[gidx];
        }
        __syncthreads();
#pragma unroll 8
        for (int c = 0; c < CCH; c++)
            a += bufA[i][c] * bufB[j][c];
        __syncthreads();
    }
    att[i][j] = a * ATT_SCALE;
    __syncthreads();

    float mx = att[i][0];
#pragma unroll
    for (int jj = 1; jj < GSZ; jj++) mx = fmaxf(mx, att[i][jj]);
    float sum = 0.f;
#pragma unroll
    for (int jj = 0; jj < GSZ; jj++) sum += expf(att[i][jj] - mx);
    attn[i][j] = expf(att[i][j] - mx) / sum;
    __syncthreads();

    for (int c0 = 0; c0 < CH; c0 += CCH) {
        for (int e = tid; e < GSZ * CCH; e += 256) {
            int r = e >> 8, c = e & 255;
            bufA[r][c] = v[((gg * GSZ + r) * CH + c0 + c) * HW + hw];
        }
        __syncthreads();
        for (int e = tid; e < GSZ * CCH; e += 256) {
            int r = e >> 8, c = e & 255;
            float s = 0.f;
#pragma unroll
            for (int jj = 0; jj < GSZ; jj++) s += attn[r][jj] * bufA[jj][c];
            virt[((gg * GSZ + r) * CH + c0 + c) * HW + hw] = s;
        }
        __syncthreads();
    }
}

// ---------------- groupnorm stats ----------------
__global__ void gn_stats(const float* __restrict__ x, float* __restrict__ mu,
                         float* __restrict__ rstd) {
    __shared__ float ss[256], sq[256];
    int n = blockIdx.x;
    const float* p = x + n * CH * HW;
    float a = 0.f, b = 0.f;
    for (int e = threadIdx.x; e < CH * HW; e += 256) {
        float v = p[e];
        a += v; b += v * v;
    }
    ss[threadIdx.x] = a; sq[threadIdx.x] = b;
    __syncthreads();
    for (int s = 128; s > 0; s >>= 1) {
        if (threadIdx.x < s) { ss[threadIdx.x] += ss[threadIdx.x + s]; sq[threadIdx.x] += sq[threadIdx.x + s]; }
        __syncthreads();
    }
    if (threadIdx.x == 0) {
        float m = ss[0] / (float)(CH * HW);
        float var = sq[0] / (float)(CH * HW) - m * m;
        mu[n] = m;
        rstd[n] = rsqrtf(var + EPSG);
    }
}

// ---------------- normalize + affine + relu ----------------
__global__ void norm_relu(const float* __restrict__ x, const float* __restrict__ mu,
                          const float* __restrict__ rstd, const float* __restrict__ gamma,
                          const float* __restrict__ beta, float* __restrict__ out) {
    int idx = blockIdx.x * 256 + threadIdx.x;
    if (idx >= FEAT_ELEMS) return;
    int n = idx / (CH * HW);
    int c = (idx / HW) % CH;
    float v = (x[idx] - mu[n]) * rstd[n];
    v = v * gamma[c] + beta[c];
    out[idx] = fmaxf(v, 0.f);
}

// ---------------- launcher ----------------
extern "C" void kernel_launch(void* const* d_in, const int* in_sizes, int n_in,
                              void* d_out, int out_size) {
    const float* status = (const float*)d_in[0];
    const float* rois   = (const float*)d_in[1];
    const float* bbox   = (const float*)d_in[2];
    const float* wR     = (const float*)d_in[3];
    const float* wQ1    = (const float*)d_in[4];
    const float* wQ2    = (const float*)d_in[5];
    const float* wK1    = (const float*)d_in[6];
    const float* wV1    = (const float*)d_in[7];
    const float* wK2    = (const float*)d_in[8];
    const float* wV2    = (const float*)d_in[9];
    const float* wC1    = (const float*)d_in[10];
    const float* wC2    = (const float*)d_in[11];
    const float* gamma  = (const float*)d_in[12];
    const float* beta   = (const float*)d_in[13];
    float* out1 = (float*)d_out;
    float* out2 = out1 + FEAT_ELEMS;

    float *feat, *q1, *q2, *k1, *v1, *k2, *v2, *vir1, *vir2, *stats;
    cudaGetSymbolAddress((void**)&feat, g_feat);
    cudaGetSymbolAddress((void**)&q1,   g_q1);
    cudaGetSymbolAddress((void**)&q2,   g_q2);
    cudaGetSymbolAddress((void**)&k1,   g_k1);
    cudaGetSymbolAddress((void**)&v1,   g_v1);
    cudaGetSymbolAddress((void**)&k2,   g_k2);
    cudaGetSymbolAddress((void**)&v2,   g_v2);
    cudaGetSymbolAddress((void**)&vir1, g_vir1);
    cudaGetSymbolAddress((void**)&vir2, g_vir2);
    cudaGetSymbolAddress((void**)&stats, g_stats);

    __nv_bfloat16 *wRhi, *wRlo, *wK1hi, *wK1lo, *wV1hi, *wV1lo;
    __nv_bfloat16 *wK2hi, *wK2lo, *wV2hi, *wV2lo, *wC1hi, *wC1lo, *wC2hi, *wC2lo;
    cudaGetSymbolAddress((void**)&wRhi,  g_wRhi);  cudaGetSymbolAddress((void**)&wRlo,  g_wRlo);
    cudaGetSymbolAddress((void**)&wK1hi, g_wK1hi); cudaGetSymbolAddress((void**)&wK1lo, g_wK1lo);
    cudaGetSymbolAddress((void**)&wV1hi, g_wV1hi); cudaGetSymbolAddress((void**)&wV1lo, g_wV1lo);
    cudaGetSymbolAddress((void**)&wK2hi, g_wK2hi); cudaGetSymbolAddress((void**)&wK2lo, g_wK2lo);
    cudaGetSymbolAddress((void**)&wV2hi, g_wV2hi); cudaGetSymbolAddress((void**)&wV2lo, g_wV2lo);
    cudaGetSymbolAddress((void**)&wC1hi, g_wC1hi); cudaGetSymbolAddress((void**)&wC1lo, g_wC1lo);
    cudaGetSymbolAddress((void**)&wC2hi, g_wC2hi); cudaGetSymbolAddress((void**)&wC2lo, g_wC2lo);

    // weight splits
    const int nR = K_RED * CH, nC = K_CC * CH;
    split_w<<<(nR + 255) / 256, 256>>>(wR,  wRhi,  wRlo,  nR);
    split_w<<<(nC + 255) / 256, 256>>>(wK1, wK1hi, wK1lo, nC);
    split_w<<<(nC + 255) / 256, 256>>>(wV1, wV1hi, wV1lo, nC);
    split_w<<<(nC + 255) / 256, 256>>>(wK2, wK2hi, wK2lo, nC);
    split_w<<<(nC + 255) / 256, 256>>>(wV2, wV2hi, wV2lo, nC);
    split_w<<<(nC + 255) / 256, 256>>>(wC1, wC1hi, wC1lo, nC);
    split_w<<<(nC + 255) / 256, 256>>>(wC2, wC2hi, wC2lo, nC);

    const dim3 cg(NSAMP * HW / 128, CH / 128);   // (98, 4)

    // feat = conv(bbox_feat, w_reduce)
    conv_mma<<<cg, 256>>>(bbox, wRhi, wRlo, nullptr, feat, CIN);

    // q convs (spatially-constant input)
    q_conv<<<(FEAT_ELEMS + 255) / 256, 256>>>(status, rois, wQ1, q1, 0);
    q_conv<<<(FEAT_ELEMS + 255) / 256, 256>>>(status, rois, wQ2, q2, 1);

    // k/v convs from feat
    conv_mma<<<cg, 256>>>(feat, wK1hi, wK1lo, nullptr, k1, CH);
    conv_mma<<<cg, 256>>>(feat, wV1hi, wV1lo, nullptr, v1, CH);
    conv_mma<<<cg, 256>>>(feat, wK2hi, wK2lo, nullptr, k2, CH);
    conv_mma<<<cg, 256>>>(feat, wV2hi, wV2lo, nullptr, v2, CH);

    // attention per branch
    attn_kernel<<<dim3(HW, NG), 256>>>(q1, k1, v1, vir1);
    attn_kernel<<<dim3(HW, NG), 256>>>(q2, k2, v2, vir2);

    // groupnorm stats
    gn_stats<<<NSAMP, 256>>>(vir1, stats + 0,   stats + 256);
    gn_stats<<<NSAMP, 256>>>(vir2, stats + 512, stats + 768);

    // normalize+relu (reuse q buffers as h)
    norm_relu<<<(FEAT_ELEMS + 255) / 256, 256>>>(vir1, stats + 0,   stats + 256, gamma, beta, q1);
    norm_relu<<<(FEAT_ELEMS + 255) / 256, 256>>>(vir2, stats + 512, stats + 768, gamma, beta, q2);

    // out = feat + conv(h, w_c)
    conv_mma<<<cg, 256>>>(q1, wC1hi, wC1lo, feat, out1, CH);
    conv_mma<<<cg, 256>>>(q2, wC2hi, wC2lo, feat, out2, CH);
}

// round 4
// speedup vs baseline: 2.5618x; 1.0026x over previous
#include <cuda_runtime.h>
#include <cuda_bf16.h>
#include <cstdint>
#include <math.h>

// ---------------- problem constants ----------------
#define NSAMP 256
#define CIN   2304
#define CH    512
#define HW    49
#define NG    16
#define GSZ   16
#define K_RED (CIN*9)    // 20736
#define K_CC  (CH*9)     // 4608
#define FEAT_ELEMS (NSAMP*CH*HW)   // 6422528
#define EPSG  1e-5f
#define ATT_SCALE 0.044194173824159216f  // 1/sqrt(512)

// ---------------- scratch (device globals; no allocation) ----------------
__device__ float g_feat [FEAT_ELEMS];
__device__ float g_q1   [FEAT_ELEMS];   // later reused as h1
__device__ float g_q2   [FEAT_ELEMS];   // later reused as h2
__device__ float g_k1   [FEAT_ELEMS];
__device__ float g_v1   [FEAT_ELEMS];
__device__ float g_k2   [FEAT_ELEMS];
__device__ float g_v2   [FEAT_ELEMS];
__device__ float g_vir1 [FEAT_ELEMS];
__device__ float g_vir2 [FEAT_ELEMS];
__device__ float g_stats[1024];

// split weights (bf16 hi/lo), native [co][K] layout
__device__ __nv_bfloat16 g_wRhi[K_RED*CH],  g_wRlo[K_RED*CH];
__device__ __nv_bfloat16 g_wK1hi[K_CC*CH],  g_wK1lo[K_CC*CH];
__device__ __nv_bfloat16 g_wV1hi[K_CC*CH],  g_wV1lo[K_CC*CH];
__device__ __nv_bfloat16 g_wK2hi[K_CC*CH],  g_wK2lo[K_CC*CH];
__device__ __nv_bfloat16 g_wV2hi[K_CC*CH],  g_wV2lo[K_CC*CH];
__device__ __nv_bfloat16 g_wC1hi[K_CC*CH],  g_wC1lo[K_CC*CH];
__device__ __nv_bfloat16 g_wC2hi[K_CC*CH],  g_wC2lo[K_CC*CH];

// ---------------- weight split kernel ----------------
__global__ void split_w(const float* __restrict__ w, __nv_bfloat16* __restrict__ hi,
                        __nv_bfloat16* __restrict__ lo, int n) {
    int i = blockIdx.x * 256 + threadIdx.x;
    if (i >= n) return;
    float v = w[i];
    __nv_bfloat16 h = __float2bfloat16(v);
    float r = v - __bfloat162float(h);
    hi[i] = h;
    lo[i] = __float2bfloat16(r);
}

// ---------------- helpers ----------------
__device__ __forceinline__ uint32_t smem_u32(const void* p) {
    uint32_t a;
    asm("{ .reg .u64 t; cvta.to.shared.u64 t, %1; cvt.u32.u64 %0, t; }" : "=r"(a) : "l"(p));
    return a;
}
__device__ __forceinline__ void cp_async16(uint32_t dst, const void* src) {
    asm volatile("cp.async.cg.shared.global [%0], [%1], 16;" :: "r"(dst), "l"(src));
}
__device__ __forceinline__ void mma_bf16(float* d, const uint32_t* a, const uint32_t* b) {
    asm volatile(
        "mma.sync.aligned.m16n8k16.row.col.f32.bf16.bf16.f32 "
        "{%0,%1,%2,%3}, {%4,%5,%6,%7}, {%8,%9}, {%0,%1,%2,%3};\n"
        : "+f"(d[0]), "+f"(d[1]), "+f"(d[2]), "+f"(d[3])
        : "r"(a[0]), "r"(a[1]), "r"(a[2]), "r"(a[3]), "r"(b[0]), "r"(b[1]));
}

// ---------------- batched HMMA implicit-GEMM conv ----------------
// Per conv: out[n,co,p] = sum_k im2col[m,k] * w[co,k]
// CTA tile 128x128, 8 warps (2x4), warp tile 64x32, K chunk 32, double-buffered.
#define KC   32
#define KCP  40                     // padded SMEM row stride (bf16 units)
#define MAT  (128*KCP)              // 5120 bf16 per matrix
#define BUFE (4*MAT)                // elems per buffer (Ahi,Alo,Bhi,Blo)
#define SMEM_BYTES (2*BUFE*2)       // 81920 bytes

struct ConvBatch {
    const float* in[4];
    const __nv_bfloat16* whi[4];
    const __nv_bfloat16* wlo[4];
    float* out[4];
    const float* addsrc;
};

__global__ void __launch_bounds__(256, 2)
conv_mma(ConvBatch P, int Cin) {
    extern __shared__ __nv_bfloat16 smem[];
    const int K = Cin * 9;
    const int NC = K / KC;
    const int cv = blockIdx.z;
    const float* __restrict__ in = P.in[cv];
    const __nv_bfloat16* __restrict__ whi = P.whi[cv];
    const __nv_bfloat16* __restrict__ wlo = P.wlo[cv];
    float* __restrict__ out = P.out[cv];
    const float* addsrc = P.addsrc;

    const int tid = threadIdx.x;
    const int wid = tid >> 5, lane = tid & 31;
    const int g = lane >> 2, tg = lane & 3;
    const int m0 = blockIdx.x * 128;
    const int n0 = blockIdx.y * 128;
    const int wm = (wid & 1) * 64;
    const int wn = (wid >> 1) * 32;

    // A-gather geometry
    const int rr = lane >> 3;
    const int kk8 = lane & 7;
    int rbase[4], ryv[4], rxv[4];
#pragma unroll
    for (int ii = 0; ii < 4; ii++) {
        int r = rr + 4 * wid + 32 * ii;
        int m = m0 + r;
        int n = m / 49, p = m - 49 * n;
        rbase[ii] = n * Cin * 49;
        ryv[ii] = p / 7;
        rxv[ii] = p - 7 * (p / 7);
    }

    // ---- tile fill helpers (as lambdas over buffer base) ----
    auto fill_tile = [&](int k0, __nv_bfloat16* base) {
        __nv_bfloat16* sAhi = base;
        __nv_bfloat16* sAlo = base + MAT;
        // A: im2col gather + hi/lo split
#pragma unroll
        for (int jj = 0; jj < 4; jj++) {
            int kk = kk8 + 8 * jj;
            int k = k0 + kk;
            int ci = k / 9, t9 = k - 9 * ci;
            int dy = t9 / 3 - 1, dx = t9 - 3 * (t9 / 3) - 1;
            int coff = ci * 49 + dy * 7 + dx;
#pragma unroll
            for (int ii = 0; ii < 4; ii++) {
                int yy = ryv[ii] + dy, xx = rxv[ii] + dx;
                float v = 0.f;
                if ((unsigned)yy < 7u && (unsigned)xx < 7u)
                    v = in[rbase[ii] + coff + ryv[ii] * 7 + rxv[ii]];
                __nv_bfloat16 h = __float2bfloat16(v);
                int r = rr + 4 * wid + 32 * ii;
                sAhi[r * KCP + kk] = h;
                sAlo[r * KCP + kk] = __float2bfloat16(v - __bfloat162float(h));
            }
        }
        // B: cp.async 16B chunks (4 per thread total: 2 hi + 2 lo)
        __nv_bfloat16* sBhi = base + 2 * MAT;
        __nv_bfloat16* sBlo = base + 3 * MAT;
#pragma unroll
        for (int i = 0; i < 2; i++) {
            int e = tid + 256 * i;
            int row = e >> 2, seg = e & 3;
            size_t goff = (size_t)(n0 + row) * K + k0 + seg * 8;
            cp_async16(smem_u32(&sBhi[row * KCP + seg * 8]), whi + goff);
            cp_async16(smem_u32(&sBlo[row * KCP + seg * 8]), wlo + goff);
        }
        asm volatile("cp.async.commit_group;" ::: "memory");
    };

    float acc[4][4][4];
#pragma unroll
    for (int t = 0; t < 4; t++)
#pragma unroll
        for (int u = 0; u < 4; u++)
#pragma unroll
            for (int e = 0; e < 4; e++) acc[t][u][e] = 0.f;

    // prologue: fill buffer 0
    fill_tile(0, smem);
    asm volatile("cp.async.wait_group 0;" ::: "memory");
    __syncthreads();

    for (int c = 0; c < NC; c++) {
        __nv_bfloat16* cur = smem + (c & 1) * BUFE;
        if (c + 1 < NC)
            fill_tile((c + 1) * KC, smem + ((c + 1) & 1) * BUFE);

        // ---- compute from cur ----
        __nv_bfloat16* sAhi = cur;
        __nv_bfloat16* sAlo = cur + MAT;
        __nv_bfloat16* sBhi = cur + 2 * MAT;
        __nv_bfloat16* sBlo = cur + 3 * MAT;
#pragma unroll
        for (int s = 0; s < 2; s++) {
            uint32_t bhi[4][2], blo[4][2];
            const int bk = 16 * s + tg * 2;
#pragma unroll
            for (int u = 0; u < 4; u++) {
                int bn = wn + 8 * u + g;
                bhi[u][0] = *reinterpret_cast<const uint32_t*>(&sBhi[bn * KCP + bk]);
                bhi[u][1] = *reinterpret_cast<const uint32_t*>(&sBhi[bn * KCP + bk + 8]);
                blo[u][0] = *reinterpret_cast<const uint32_t*>(&sBlo[bn * KCP + bk]);
                blo[u][1] = *reinterpret_cast<const uint32_t*>(&sBlo[bn * KCP + bk + 8]);
            }
#pragma unroll
            for (int t = 0; t < 4; t++) {
                uint32_t ahi[4], alo[4];
                int arow = wm + 16 * t + g;
                int acol = 16 * s + tg * 2;
                ahi[0] = *reinterpret_cast<const uint32_t*>(&sAhi[arow * KCP + acol]);
                ahi[1] = *reinterpret_cast<const uint32_t*>(&sAhi[(arow + 8) * KCP + acol]);
                ahi[2] = *reinterpret_cast<const uint32_t*>(&sAhi[arow * KCP + acol + 8]);
                ahi[3] = *reinterpret_cast<const uint32_t*>(&sAhi[(arow + 8) * KCP + acol + 8]);
                alo[0] = *reinterpret_cast<const uint32_t*>(&sAlo[arow * KCP + acol]);
                alo[1] = *reinterpret_cast<const uint32_t*>(&sAlo[(arow + 8) * KCP + acol]);
                alo[2] = *reinterpret_cast<const uint32_t*>(&sAlo[arow * KCP + acol + 8]);
                alo[3] = *reinterpret_cast<const uint32_t*>(&sAlo[(arow + 8) * KCP + acol + 8]);
#pragma unroll
                for (int u = 0; u < 4; u++) {
                    mma_bf16(acc[t][u], ahi, bhi[u]);
                    mma_bf16(acc[t][u], ahi, blo[u]);
                    mma_bf16(acc[t][u], alo, bhi[u]);
                }
            }
        }
        asm volatile("cp.async.wait_group 0;" ::: "memory");
        __syncthreads();
    }

    // ---- epilogue ----
#pragma unroll
    for (int t = 0; t < 4; t++) {
#pragma unroll
        for (int h = 0; h < 2; h++) {
            int row = m0 + wm + 16 * t + g + 8 * h;
            int n = row / 49, p = row - 49 * n;
            size_t base = (size_t)n * CH * 49 + p;
#pragma unroll
            for (int u = 0; u < 4; u++) {
                int col = n0 + wn + 8 * u + tg * 2;
                size_t i0 = base + (size_t)col * 49;
                float v0 = acc[t][u][2 * h];
                float v1 = acc[t][u][2 * h + 1];
                if (addsrc) { v0 += addsrc[i0]; v1 += addsrc[i0 + 49]; }
                out[i0] = v0;
                out[i0 + 49] = v1;
            }
        }
    }
}

// ---------------- q-conv (spatially-constant input), z = branch ----------
__global__ void q_conv2(const float* __restrict__ status, const float* __restrict__ rois,
                        const float* __restrict__ wq1, const float* __restrict__ wq2,
                        float* __restrict__ o1, float* __restrict__ o2) {
    int idx = blockIdx.x * 256 + threadIdx.x;
    if (idx >= NSAMP * CH * HW) return;
    int scol = blockIdx.y;
    const float* wq = scol ? wq2 : wq1;
    float* out = scol ? o2 : o1;
    int p = idx % HW;
    int t2 = idx / HW;
    int co = t2 % CH;
    int n = t2 / CH;
    int y = p / 7, x = p - (p / 7) * 7;
    float s[5];
    s[0] = status[n * 2 + scol];
    s[1] = rois[n * 5 + 1];
    s[2] = rois[n * 5 + 2];
    s[3] = rois[n * 5 + 3];
    s[4] = rois[n * 5 + 4];
    const float* w = wq + co * 45;
    float acc = 0.f;
#pragma unroll
    for (int ci = 0; ci < 5; ci++)
#pragma unroll
        for (int dy = 0; dy < 3; dy++)
#pragma unroll
            for (int dx = 0; dx < 3; dx++) {
                int yy = y + dy - 1, xx = x + dx - 1;
                if ((unsigned)yy < 7u && (unsigned)xx < 7u)
                    acc += w[ci * 9 + dy * 3 + dx] * s[ci];
            }
    out[idx] = acc;
}

// ---------------- attention per (hw, g), z = branch ----------------
#define CCH 256
__global__ void attn2(const float* __restrict__ q1, const float* __restrict__ k1,
                      const float* __restrict__ v1, float* __restrict__ w1,
                      const float* __restrict__ q2, const float* __restrict__ k2,
                      const float* __restrict__ v2, float* __restrict__ w2) {
    int hw = blockIdx.x;
    int gg = blockIdx.y;
    int br = blockIdx.z;
    const float* q = br ? q2 : q1;
    const float* k = br ? k2 : k1;
    const float* v = br ? v2 : v1;
    float* virt = br ? w2 : w1;

    __shared__ float bufA[GSZ][CCH + 1];
    __shared__ float bufB[GSZ][CCH + 1];
    __shared__ float att[GSZ][GSZ + 1];
    __shared__ float attn[GSZ][GSZ + 1];

    int tid = threadIdx.x;
    int i = tid >> 4, j = tid & 15;
    float a = 0.f;

    for (int c0 = 0; c0 < CH; c0 += CCH) {
        for (int e = tid; e < GSZ * CCH; e += 256) {
            int r = e >> 8, c = e & 255;
            int gidx = ((gg * GSZ + r) * CH + c0 + c) * HW + hw;
            bufA[r][c] = q[gidx];
            bufB[r][c] = k[gidx];
        }
        __syncthreads();
#pragma unroll 8
        for (int c = 0; c < CCH; c++)
            a += bufA[i][c] * bufB[j][c];
        __syncthreads();
    }
    att[i][j] = a * ATT_SCALE;
    __syncthreads();

    float mx = att[i][0];
#pragma unroll
    for (int jj = 1; jj < GSZ; jj++) mx = fmaxf(mx, att[i][jj]);
    float sum = 0.f;
#pragma unroll
    for (int jj = 0; jj < GSZ; jj++) sum += expf(att[i][jj] - mx);
    attn[i][j] = expf(att[i][j] - mx) / sum;
    __syncthreads();

    for (int c0 = 0; c0 < CH; c0 += CCH) {
        for (int e = tid; e < GSZ * CCH; e += 256) {
            int r = e >> 8, c = e & 255;
            bufA[r][c] = v[((gg * GSZ + r) * CH + c0 + c) * HW + hw];
        }
        __syncthreads();
        for (int e = tid; e < GSZ * CCH; e += 256) {
            int r = e >> 8, c = e & 255;
            float s = 0.f;
#pragma unroll
            for (int jj = 0; jj < GSZ; jj++) s += attn[r][jj] * bufA[jj][c];
            virt[((gg * GSZ + r) * CH + c0 + c) * HW + hw] = s;
        }
        __syncthreads();
    }
}

// ---------------- groupnorm stats, both branches in one launch ----------
__global__ void gn_stats2(const float* __restrict__ x1, const float* __restrict__ x2,
                          float* __restrict__ stats) {
    __shared__ float ss[256], sq[256];
    int blk = blockIdx.x;            // 0..511
    int br = blk >> 8, n = blk & 255;
    const float* p = (br ? x2 : x1) + (size_t)n * CH * HW;
    float a = 0.f, b = 0.f;
    for (int e = threadIdx.x; e < CH * HW; e += 256) {
        float v = p[e];
        a += v; b += v * v;
    }
    ss[threadIdx.x] = a; sq[threadIdx.x] = b;
    __syncthreads();
    for (int s = 128; s > 0; s >>= 1) {
        if (threadIdx.x < s) { ss[threadIdx.x] += ss[threadIdx.x + s]; sq[threadIdx.x] += sq[threadIdx.x + s]; }
        __syncthreads();
    }
    if (threadIdx.x == 0) {
        float m = ss[0] / (float)(CH * HW);
        float var = sq[0] / (float)(CH * HW) - m * m;
        stats[br * 512 + n] = m;
        stats[br * 512 + 256 + n] = rsqrtf(var + EPSG);
    }
}

// ---------------- normalize + affine + relu, both branches ----------------
__global__ void norm_relu2(const float* __restrict__ x1, const float* __restrict__ x2,
                           const float* __restrict__ stats,
                           const float* __restrict__ gamma, const float* __restrict__ beta,
                           float* __restrict__ o1, float* __restrict__ o2) {
    int idx = blockIdx.x * 256 + threadIdx.x;
    int br = blockIdx.y;
    if (idx >= FEAT_ELEMS) return;
    const float* x = br ? x2 : x1;
    float* out = br ? o2 : o1;
    int n = idx / (CH * HW);
    int c = (idx / HW) % CH;
    float v = (x[idx] - stats[br * 512 + n]) * stats[br * 512 + 256 + n];
    v = v * gamma[c] + beta[c];
    out[idx] = fmaxf(v, 0.f);
}

// ---------------- launcher ----------------
extern "C" void kernel_launch(void* const* d_in, const int* in_sizes, int n_in,
                              void* d_out, int out_size) {
    const float* status = (const float*)d_in[0];
    const float* rois   = (const float*)d_in[1];
    const float* bbox   = (const float*)d_in[2];
    const float* wR     = (const float*)d_in[3];
    const float* wQ1    = (const float*)d_in[4];
    const float* wQ2    = (const float*)d_in[5];
    const float* wK1    = (const float*)d_in[6];
    const float* wV1    = (const float*)d_in[7];
    const float* wK2    = (const float*)d_in[8];
    const float* wV2    = (const float*)d_in[9];
    const float* wC1    = (const float*)d_in[10];
    const float* wC2    = (const float*)d_in[11];
    const float* gamma  = (const float*)d_in[12];
    const float* beta   = (const float*)d_in[13];
    float* out1 = (float*)d_out;
    float* out2 = out1 + FEAT_ELEMS;

    float *feat, *q1, *q2, *k1, *v1, *k2, *v2, *vir1, *vir2, *stats;
    cudaGetSymbolAddress((void**)&feat, g_feat);
    cudaGetSymbolAddress((void**)&q1,   g_q1);
    cudaGetSymbolAddress((void**)&q2,   g_q2);
    cudaGetSymbolAddress((void**)&k1,   g_k1);
    cudaGetSymbolAddress((void**)&v1,   g_v1);
    cudaGetSymbolAddress((void**)&k2,   g_k2);
    cudaGetSymbolAddress((void**)&v2,   g_v2);
    cudaGetSymbolAddress((void**)&vir1, g_vir1);
    cudaGetSymbolAddress((void**)&vir2, g_vir2);
    cudaGetSymbolAddress((void**)&stats, g_stats);

    __nv_bfloat16 *wRhi, *wRlo, *wK1hi, *wK1lo, *wV1hi, *wV1lo;
    __nv_bfloat16 *wK2hi, *wK2lo, *wV2hi, *wV2lo, *wC1hi, *wC1lo, *wC2hi, *wC2lo;
    cudaGetSymbolAddress((void**)&wRhi,  g_wRhi);  cudaGetSymbolAddress((void**)&wRlo,  g_wRlo);
    cudaGetSymbolAddress((void**)&wK1hi, g_wK1hi); cudaGetSymbolAddress((void**)&wK1lo, g_wK1lo);
    cudaGetSymbolAddress((void**)&wV1hi, g_wV1hi); cudaGetSymbolAddress((void**)&wV1lo, g_wV1lo);
    cudaGetSymbolAddress((void**)&wK2hi, g_wK2hi); cudaGetSymbolAddress((void**)&wK2lo, g_wK2lo);
    cudaGetSymbolAddress((void**)&wV2hi, g_wV2hi); cudaGetSymbolAddress((void**)&wV2lo, g_wV2lo);
    cudaGetSymbolAddress((void**)&wC1hi, g_wC1hi); cudaGetSymbolAddress((void**)&wC1lo, g_wC1lo);
    cudaGetSymbolAddress((void**)&wC2hi, g_wC2hi); cudaGetSymbolAddress((void**)&wC2lo, g_wC2lo);

    cudaFuncSetAttribute(conv_mma, cudaFuncAttributeMaxDynamicSharedMemorySize, SMEM_BYTES);

    // weight splits
    const int nR = K_RED * CH, nC = K_CC * CH;
    split_w<<<(nR + 255) / 256, 256>>>(wR,  wRhi,  wRlo,  nR);
    split_w<<<(nC + 255) / 256, 256>>>(wK1, wK1hi, wK1lo, nC);
    split_w<<<(nC + 255) / 256, 256>>>(wV1, wV1hi, wV1lo, nC);
    split_w<<<(nC + 255) / 256, 256>>>(wK2, wK2hi, wK2lo, nC);
    split_w<<<(nC + 255) / 256, 256>>>(wV2, wV2hi, wV2lo, nC);
    split_w<<<(nC + 255) / 256, 256>>>(wC1, wC1hi, wC1lo, nC);
    split_w<<<(nC + 255) / 256, 256>>>(wC2, wC2hi, wC2lo, nC);

    // feat = conv(bbox_feat, w_reduce)
    {
        ConvBatch P = {};
        P.in[0] = bbox; P.whi[0] = wRhi; P.wlo[0] = wRlo; P.out[0] = feat;
        P.addsrc = nullptr;
        conv_mma<<<dim3(NSAMP * HW / 128, CH / 128, 1), 256, SMEM_BYTES>>>(P, CIN);
    }

    // q convs (spatially-constant input), both branches
    q_conv2<<<dim3((FEAT_ELEMS + 255) / 256, 2), 256>>>(status, rois, wQ1, wQ2, q1, q2);

    // k/v convs (4 fused in one launch)
    {
        ConvBatch P = {};
        P.in[0] = feat; P.whi[0] = wK1hi; P.wlo[0] = wK1lo; P.out[0] = k1;
        P.in[1] = feat; P.whi[1] = wV1hi; P.wlo[1] = wV1lo; P.out[1] = v1;
        P.in[2] = feat; P.whi[2] = wK2hi; P.wlo[2] = wK2lo; P.out[2] = k2;
        P.in[3] = feat; P.whi[3] = wV2hi; P.wlo[3] = wV2lo; P.out[3] = v2;
        P.addsrc = nullptr;
        conv_mma<<<dim3(NSAMP * HW / 128, CH / 128, 4), 256, SMEM_BYTES>>>(P, CH);
    }

    // attention, both branches
    attn2<<<dim3(HW, NG, 2), 256>>>(q1, k1, v1, vir1, q2, k2, v2, vir2);

    // groupnorm stats, both branches
    gn_stats2<<<512, 256>>>(vir1, vir2, stats);

    // normalize+relu, both branches (reuse q buffers as h)
    norm_relu2<<<dim3((FEAT_ELEMS + 255) / 256, 2), 256>>>(vir1, vir2, stats, gamma, beta, q1, q2);

    // out convs (2 fused): out = feat + conv(h, w_c)
    {
        ConvBatch P = {};
        P.in[0] = q1; P.whi[0] = wC1hi; P.wlo[0] = wC1lo; P.out[0] = out1;
        P.in[1] = q2; P.whi[1] = wC2hi; P.wlo[1] = wC2lo; P.out[1] = out2;
        P.addsrc = feat;
        conv_mma<<<dim3(NSAMP * HW / 128, CH / 128, 2), 256, SMEM_BYTES>>>(P, CH);
    }
}

// round 5
// speedup vs baseline: 3.0902x; 1.2063x over previous
#include <cuda_runtime.h>
#include <cuda_bf16.h>
#include <cstdint>
#include <math.h>

// ---------------- problem constants ----------------
#define NSAMP 256
#define CIN   2304
#define CH    512
#define HW    49
#define NG    16
#define GSZ   16
#define K_RED (CIN*9)    // 20736
#define K_CC  (CH*9)     // 4608
#define FEAT_ELEMS (NSAMP*CH*HW)   // 6422528
#define EPSG  1e-5f
#define ATT_SCALE 0.044194173824159216f  // 1/sqrt(512)

// ---------------- scratch (device globals; no allocation) ----------------
__device__ float g_feat [FEAT_ELEMS];
__device__ float g_q1   [FEAT_ELEMS];
__device__ float g_q2   [FEAT_ELEMS];
__device__ float g_k1   [FEAT_ELEMS];
__device__ float g_v1   [FEAT_ELEMS];
__device__ float g_k2   [FEAT_ELEMS];
__device__ float g_v2   [FEAT_ELEMS];
__device__ float g_vir1 [FEAT_ELEMS];
__device__ float g_vir2 [FEAT_ELEMS];
__device__ float g_stats[1024];

// padded channel-last inputs: [n][81][C], bf16 hi/lo, zero border
__device__ __align__(256) __nv_bfloat16 g_bpad_hi[NSAMP*81*CIN];
__device__ __align__(256) __nv_bfloat16 g_bpad_lo[NSAMP*81*CIN];
__device__ __align__(256) __nv_bfloat16 g_fpad_hi[NSAMP*81*CH];
__device__ __align__(256) __nv_bfloat16 g_fpad_lo[NSAMP*81*CH];
__device__ __align__(256) __nv_bfloat16 g_h1pad_hi[NSAMP*81*CH];
__device__ __align__(256) __nv_bfloat16 g_h1pad_lo[NSAMP*81*CH];
__device__ __align__(256) __nv_bfloat16 g_h2pad_hi[NSAMP*81*CH];
__device__ __align__(256) __nv_bfloat16 g_h2pad_lo[NSAMP*81*CH];

// split weights (bf16 hi/lo), tap-major layout [co][tap][ci]
__device__ __align__(256) __nv_bfloat16 g_wRhi[K_RED*CH],  g_wRlo[K_RED*CH];
__device__ __align__(256) __nv_bfloat16 g_wK1hi[K_CC*CH],  g_wK1lo[K_CC*CH];
__device__ __align__(256) __nv_bfloat16 g_wV1hi[K_CC*CH],  g_wV1lo[K_CC*CH];
__device__ __align__(256) __nv_bfloat16 g_wK2hi[K_CC*CH],  g_wK2lo[K_CC*CH];
__device__ __align__(256) __nv_bfloat16 g_wV2hi[K_CC*CH],  g_wV2lo[K_CC*CH];
__device__ __align__(256) __nv_bfloat16 g_wC1hi[K_CC*CH],  g_wC1lo[K_CC*CH];
__device__ __align__(256) __nv_bfloat16 g_wC2hi[K_CC*CH],  g_wC2lo[K_CC*CH];

// ---------------- helpers ----------------
__device__ __forceinline__ uint32_t smem_u32(const void* p) {
    uint32_t a;
    asm("{ .reg .u64 t; cvta.to.shared.u64 t, %1; cvt.u32.u64 %0, t; }" : "=r"(a) : "l"(p));
    return a;
}
__device__ __forceinline__ void cp_async16(uint32_t dst, const void* src) {
    asm volatile("cp.async.cg.shared.global [%0], [%1], 16;" :: "r"(dst), "l"(src));
}
__device__ __forceinline__ void mma_bf16(float* d, const uint32_t* a, const uint32_t* b) {
    asm volatile(
        "mma.sync.aligned.m16n8k16.row.col.f32.bf16.bf16.f32 "
        "{%0,%1,%2,%3}, {%4,%5,%6,%7}, {%8,%9}, {%0,%1,%2,%3};\n"
        : "+f"(d[0]), "+f"(d[1]), "+f"(d[2]), "+f"(d[3])
        : "r"(a[0]), "r"(a[1]), "r"(a[2]), "r"(a[3]), "r"(b[0]), "r"(b[1]));
}

// ---------------- weight reorder + split: w[co][ci*9+t] -> wt[co][t*C+ci] ----
__global__ void split_w_reorder(const float* __restrict__ w, __nv_bfloat16* __restrict__ hi,
                                __nv_bfloat16* __restrict__ lo, int C, int total) {
    int i = blockIdx.x * 256 + threadIdx.x;
    if (i >= total) return;
    int K9 = 9 * C;
    int co = i / K9, rem = i - co * K9;
    int t = rem / C, ci = rem - t * C;
    float v = w[(size_t)co * K9 + ci * 9 + t];
    __nv_bfloat16 h = __float2bfloat16(v);
    hi[i] = h;
    lo[i] = __float2bfloat16(v - __bfloat162float(h));
}

// ---------------- NCHW float -> padded channel-last bf16 hi/lo ----------------
__global__ void pad_convert(const float* __restrict__ src, __nv_bfloat16* __restrict__ hi,
                            __nv_bfloat16* __restrict__ lo, int C) {
    int n = blockIdx.x, c0 = blockIdx.y * 64;
    __shared__ float tile[64][51];
    int tid = threadIdx.x;
    for (int e = tid; e < 64 * 49; e += 256) {
        int ci = e / 49, p = e - 49 * ci;
        tile[ci][p] = src[((size_t)n * C + c0 + ci) * 49 + p];
    }
    __syncthreads();
    for (int e = tid; e < 81 * 64; e += 256) {
        int pp = e >> 6, ci = e & 63;
        int y = pp / 9, x = pp - 9 * y;
        float v = 0.f;
        if (y >= 1 && y <= 7 && x >= 1 && x <= 7) v = tile[ci][(y - 1) * 7 + (x - 1)];
        __nv_bfloat16 h = __float2bfloat16(v);
        size_t di = ((size_t)n * 81 + pp) * C + c0 + ci;
        hi[di] = h;
        lo[di] = __float2bfloat16(v - __bfloat162float(h));
    }
}

// ---------------- fused GN-normalize + relu + pad-convert (both branches) -----
__global__ void norm_relu_pad(const float* __restrict__ x1, const float* __restrict__ x2,
                              const float* __restrict__ stats,
                              const float* __restrict__ gamma, const float* __restrict__ beta,
                              __nv_bfloat16* __restrict__ h1hi, __nv_bfloat16* __restrict__ h1lo,
                              __nv_bfloat16* __restrict__ h2hi, __nv_bfloat16* __restrict__ h2lo) {
    int n = blockIdx.x, c0 = blockIdx.y * 64, br = blockIdx.z;
    const float* x = br ? x2 : x1;
    __nv_bfloat16* hi = br ? h2hi : h1hi;
    __nv_bfloat16* lo = br ? h2lo : h1lo;
    float mu = stats[br * 512 + n];
    float rs = stats[br * 512 + 256 + n];
    __shared__ float tile[64][51];
    int tid = threadIdx.x;
    for (int e = tid; e < 64 * 49; e += 256) {
        int ci = e / 49, p = e - 49 * ci;
        float v = x[((size_t)n * CH + c0 + ci) * 49 + p];
        tile[ci][p] = fmaxf((v - mu) * rs * gamma[c0 + ci] + beta[c0 + ci], 0.f);
    }
    __syncthreads();
    for (int e = tid; e < 81 * 64; e += 256) {
        int pp = e >> 6, ci = e & 63;
        int y = pp / 9, x9 = pp - 9 * y;
        float v = 0.f;
        if (y >= 1 && y <= 7 && x9 >= 1 && x9 <= 7) v = tile[ci][(y - 1) * 7 + (x9 - 1)];
        __nv_bfloat16 h = __float2bfloat16(v);
        size_t di = ((size_t)n * 81 + pp) * CH + c0 + ci;
        hi[di] = h;
        lo[di] = __float2bfloat16(v - __bfloat162float(h));
    }
}

// ---------------- batched HMMA conv: 9 shifted 1x1 GEMMs over padded input ----
// out[n,co,p] = sum_{t,ci} xpad[n, pp(p,t), ci] * wt[co, t*C+ci]
// CTA tile 128x128, 8 warps (2x4), warp tile 64x32, K chunk 32 (tap-major),
// double-buffered, all tiles loaded via cp.async.
#define KCP  40                     // padded SMEM row stride (bf16 units)
#define MAT  (128*KCP)              // 5120 bf16 per matrix
#define BUFE (4*MAT)                // Ahi,Alo,Bhi,Blo
#define SMEM_BYTES (2*BUFE*2)       // 81920 bytes

struct ConvBatch {
    const __nv_bfloat16* ahi[4];
    const __nv_bfloat16* alo[4];
    const __nv_bfloat16* whi[4];
    const __nv_bfloat16* wlo[4];
    float* out[4];
    const float* addsrc;
};

__global__ void __launch_bounds__(256, 2)
conv_mma(ConvBatch P, int C) {
    extern __shared__ __nv_bfloat16 smem[];
    const int K9 = 9 * C;
    const int NCI = C / 32;
    const int NQ = 9 * NCI;
    const int cv = blockIdx.z;
    const __nv_bfloat16* __restrict__ Ahi = P.ahi[cv];
    const __nv_bfloat16* __restrict__ Alo = P.alo[cv];
    const __nv_bfloat16* __restrict__ Whi = P.whi[cv];
    const __nv_bfloat16* __restrict__ Wlo = P.wlo[cv];
    float* __restrict__ out = P.out[cv];
    const float* addsrc = P.addsrc;

    const int tid = threadIdx.x;
    const int wid = tid >> 5, lane = tid & 31;
    const int g = lane >> 2, tg = lane & 3;
    const int m0 = blockIdx.x * 128;
    const int n0 = blockIdx.y * 128;
    const int wm = (wid & 1) * 64;
    const int wn = (wid >> 1) * 32;

    // fill geometry: thread serves rows r0 and r0+64, 16B segment `seg`
    const int seg = tid & 3;
    const int r0 = tid >> 2;          // 0..63
    size_t abase[2];
#pragma unroll
    for (int h = 0; h < 2; h++) {
        int m = m0 + r0 + 64 * h;
        int n = m / 49, p = m - 49 * n;
        int y = p / 7, x = p - 7 * y;
        abase[h] = ((size_t)n * 81 + y * 9 + x) * C + seg * 8;
    }

    auto fill = [&](int q, __nv_bfloat16* base) {
        int t = q / NCI;
        int ci = (q - t * NCI) * 32;
        int a3 = t / 3, b3 = t - 3 * a3;
        size_t tof = (size_t)(a3 * 9 + b3) * C + ci;
#pragma unroll
        for (int h = 0; h < 2; h++) {
            int r = r0 + 64 * h;
            size_t src = abase[h] + tof;
            uint32_t d = smem_u32(&base[r * KCP + seg * 8]);
            cp_async16(d, Ahi + src);
            cp_async16(d + MAT * 2, Alo + src);      // +MAT bf16 = +2*MAT bytes
        }
#pragma unroll
        for (int h = 0; h < 2; h++) {
            int row = r0 + 64 * h;
            size_t src = (size_t)(n0 + row) * K9 + t * C + ci + seg * 8;
            uint32_t d = smem_u32(&base[2 * MAT + row * KCP + seg * 8]);
            cp_async16(d, Whi + src);
            cp_async16(d + MAT * 2, Wlo + src);
        }
        asm volatile("cp.async.commit_group;" ::: "memory");
    };

    float acc[4][4][4];
#pragma unroll
    for (int t = 0; t < 4; t++)
#pragma unroll
        for (int u = 0; u < 4; u++)
#pragma unroll
            for (int e = 0; e < 4; e++) acc[t][u][e] = 0.f;

    fill(0, smem);

    for (int q = 0; q < NQ; q++) {
        if (q + 1 < NQ) {
            fill(q + 1, smem + ((q + 1) & 1) * BUFE);
            asm volatile("cp.async.wait_group 1;" ::: "memory");
        } else {
            asm volatile("cp.async.wait_group 0;" ::: "memory");
        }
        __syncthreads();

        __nv_bfloat16* cur = smem + (q & 1) * BUFE;
        __nv_bfloat16* sAhi = cur;
        __nv_bfloat16* sAlo = cur + MAT;
        __nv_bfloat16* sBhi = cur + 2 * MAT;
        __nv_bfloat16* sBlo = cur + 3 * MAT;
#pragma unroll
        for (int s = 0; s < 2; s++) {
            uint32_t bhi[4][2], blo[4][2];
            const int bk = 16 * s + tg * 2;
#pragma unroll
            for (int u = 0; u < 4; u++) {
                int bn = wn + 8 * u + g;
                bhi[u][0] = *reinterpret_cast<const uint32_t*>(&sBhi[bn * KCP + bk]);
                bhi[u][1] = *reinterpret_cast<const uint32_t*>(&sBhi[bn * KCP + bk + 8]);
                blo[u][0] = *reinterpret_cast<const uint32_t*>(&sBlo[bn * KCP + bk]);
                blo[u][1] = *reinterpret_cast<const uint32_t*>(&sBlo[bn * KCP + bk + 8]);
            }
#pragma unroll
            for (int t = 0; t < 4; t++) {
                uint32_t ahi[4], alo[4];
                int arow = wm + 16 * t + g;
                int acol = 16 * s + tg * 2;
                ahi[0] = *reinterpret_cast<const uint32_t*>(&sAhi[arow * KCP + acol]);
                ahi[1] = *reinterpret_cast<const uint32_t*>(&sAhi[(arow + 8) * KCP + acol]);
                ahi[2] = *reinterpret_cast<const uint32_t*>(&sAhi[arow * KCP + acol + 8]);
                ahi[3] = *reinterpret_cast<const uint32_t*>(&sAhi[(arow + 8) * KCP + acol + 8]);
                alo[0] = *reinterpret_cast<const uint32_t*>(&sAlo[arow * KCP + acol]);
                alo[1] = *reinterpret_cast<const uint32_t*>(&sAlo[(arow + 8) * KCP + acol]);
                alo[2] = *reinterpret_cast<const uint32_t*>(&sAlo[arow * KCP + acol + 8]);
                alo[3] = *reinterpret_cast<const uint32_t*>(&sAlo[(arow + 8) * KCP + acol + 8]);
#pragma unroll
                for (int u = 0; u < 4; u++) {
                    mma_bf16(acc[t][u], ahi, bhi[u]);
                    mma_bf16(acc[t][u], ahi, blo[u]);
                    mma_bf16(acc[t][u], alo, bhi[u]);
                }
            }
        }
        __syncthreads();
    }

    // ---- epilogue ----
#pragma unroll
    for (int t = 0; t < 4; t++) {
#pragma unroll
        for (int h = 0; h < 2; h++) {
            int row = m0 + wm + 16 * t + g + 8 * h;
            int n = row / 49, p = row - 49 * n;
            size_t base = (size_t)n * CH * 49 + p;
#pragma unroll
            for (int u = 0; u < 4; u++) {
                int col = n0 + wn + 8 * u + tg * 2;
                size_t i0 = base + (size_t)col * 49;
                float v0 = acc[t][u][2 * h];
                float v1 = acc[t][u][2 * h + 1];
                if (addsrc) { v0 += addsrc[i0]; v1 += addsrc[i0 + 49]; }
                out[i0] = v0;
                out[i0 + 49] = v1;
            }
        }
    }
}

// ---------------- q-conv (spatially-constant input), y = branch ----------
__global__ void q_conv2(const float* __restrict__ status, const float* __restrict__ rois,
                        const float* __restrict__ wq1, const float* __restrict__ wq2,
                        float* __restrict__ o1, float* __restrict__ o2) {
    int idx = blockIdx.x * 256 + threadIdx.x;
    if (idx >= NSAMP * CH * HW) return;
    int scol = blockIdx.y;
    const float* wq = scol ? wq2 : wq1;
    float* out = scol ? o2 : o1;
    int p = idx % HW;
    int t2 = idx / HW;
    int co = t2 % CH;
    int n = t2 / CH;
    int y = p / 7, x = p - (p / 7) * 7;
    float s[5];
    s[0] = status[n * 2 + scol];
    s[1] = rois[n * 5 + 1];
    s[2] = rois[n * 5 + 2];
    s[3] = rois[n * 5 + 3];
    s[4] = rois[n * 5 + 4];
    const float* w = wq + co * 45;
    float acc = 0.f;
#pragma unroll
    for (int ci = 0; ci < 5; ci++)
#pragma unroll
        for (int dy = 0; dy < 3; dy++)
#pragma unroll
            for (int dx = 0; dx < 3; dx++) {
                int yy = y + dy - 1, xx = x + dx - 1;
                if ((unsigned)yy < 7u && (unsigned)xx < 7u)
                    acc += w[ci * 9 + dy * 3 + dx] * s[ci];
            }
    out[idx] = acc;
}

// ---------------- attention per (hw, g), z = branch ----------------
#define CCH 256
__global__ void attn2(const float* __restrict__ q1, const float* __restrict__ k1,
                      const float* __restrict__ v1, float* __restrict__ w1,
                      const float* __restrict__ q2, const float* __restrict__ k2,
                      const float* __restrict__ v2, float* __restrict__ w2) {
    int hw = blockIdx.x;
    int gg = blockIdx.y;
    int br = blockIdx.z;
    const float* q = br ? q2 : q1;
    const float* k = br ? k2 : k1;
    const float* v = br ? v2 : v1;
    float* virt = br ? w2 : w1;

    __shared__ float bufA[GSZ][CCH + 1];
    __shared__ float bufB[GSZ][CCH + 1];
    __shared__ float att[GSZ][GSZ + 1];
    __shared__ float attn[GSZ][GSZ + 1];

    int tid = threadIdx.x;
    int i = tid >> 4, j = tid & 15;
    float a = 0.f;

    for (int c0 = 0; c0 < CH; c0 += CCH) {
        for (int e = tid; e < GSZ * CCH; e += 256) {
            int r = e >> 8, c = e & 255;
            int gidx = ((gg * GSZ + r) * CH + c0 + c) * HW + hw;
            bufA[r][c] = q[gidx];
            bufB[r][c] = k[gidx];
        }
        __syncthreads();
#pragma unroll 8
        for (int c = 0; c < CCH; c++)
            a += bufA[i][c] * bufB[j][c];
        __syncthreads();
    }
    att[i][j] = a * ATT_SCALE;
    __syncthreads();

    float mx = att[i][0];
#pragma unroll
    for (int jj = 1; jj < GSZ; jj++) mx = fmaxf(mx, att[i][jj]);
    float sum = 0.f;
#pragma unroll
    for (int jj = 0; jj < GSZ; jj++) sum += expf(att[i][jj] - mx);
    attn[i][j] = expf(att[i][j] - mx) / sum;
    __syncthreads();

    for (int c0 = 0; c0 < CH; c0 += CCH) {
        for (int e = tid; e < GSZ * CCH; e += 256) {
            int r = e >> 8, c = e & 255;
            bufA[r][c] = v[((gg * GSZ + r) * CH + c0 + c) * HW + hw];
        }
        __syncthreads();
        for (int e = tid; e < GSZ * CCH; e += 256) {
            int r = e >> 8, c = e & 255;
            float s = 0.f;
#pragma unroll
            for (int jj = 0; jj < GSZ; jj++) s += attn[r][jj] * bufA[jj][c];
            virt[((gg * GSZ + r) * CH + c0 + c) * HW + hw] = s;
        }
        __syncthreads();
    }
}

// ---------------- groupnorm stats, both branches ----------
__global__ void gn_stats2(const float* __restrict__ x1, const float* __restrict__ x2,
                          float* __restrict__ stats) {
    __shared__ float ss[256], sq[256];
    int blk = blockIdx.x;
    int br = blk >> 8, n = blk & 255;
    const float* p = (br ? x2 : x1) + (size_t)n * CH * HW;
    float a = 0.f, b = 0.f;
    for (int e = threadIdx.x; e < CH * HW; e += 256) {
        float v = p[e];
        a += v; b += v * v;
    }
    ss[threadIdx.x] = a; sq[threadIdx.x] = b;
    __syncthreads();
    for (int s = 128; s > 0; s >>= 1) {
        if (threadIdx.x < s) { ss[threadIdx.x] += ss[threadIdx.x + s]; sq[threadIdx.x] += sq[threadIdx.x + s]; }
        __syncthreads();
    }
    if (threadIdx.x == 0) {
        float m = ss[0] / (float)(CH * HW);
        float var = sq[0] / (float)(CH * HW) - m * m;
        stats[br * 512 + n] = m;
        stats[br * 512 + 256 + n] = rsqrtf(var + EPSG);
    }
}

// ---------------- launcher ----------------
extern "C" void kernel_launch(void* const* d_in, const int* in_sizes, int n_in,
                              void* d_out, int out_size) {
    const float* status = (const float*)d_in[0];
    const float* rois   = (const float*)d_in[1];
    const float* bbox   = (const float*)d_in[2];
    const float* wR     = (const float*)d_in[3];
    const float* wQ1    = (const float*)d_in[4];
    const float* wQ2    = (const float*)d_in[5];
    const float* wK1    = (const float*)d_in[6];
    const float* wV1    = (const float*)d_in[7];
    const float* wK2    = (const float*)d_in[8];
    const float* wV2    = (const float*)d_in[9];
    const float* wC1    = (const float*)d_in[10];
    const float* wC2    = (const float*)d_in[11];
    const float* gamma  = (const float*)d_in[12];
    const float* beta   = (const float*)d_in[13];
    float* out1 = (float*)d_out;
    float* out2 = out1 + FEAT_ELEMS;

    float *feat, *q1, *q2, *k1, *v1, *k2, *v2, *vir1, *vir2, *stats;
    cudaGetSymbolAddress((void**)&feat, g_feat);
    cudaGetSymbolAddress((void**)&q1,   g_q1);
    cudaGetSymbolAddress((void**)&q2,   g_q2);
    cudaGetSymbolAddress((void**)&k1,   g_k1);
    cudaGetSymbolAddress((void**)&v1,   g_v1);
    cudaGetSymbolAddress((void**)&k2,   g_k2);
    cudaGetSymbolAddress((void**)&v2,   g_v2);
    cudaGetSymbolAddress((void**)&vir1, g_vir1);
    cudaGetSymbolAddress((void**)&vir2, g_vir2);
    cudaGetSymbolAddress((void**)&stats, g_stats);

    __nv_bfloat16 *bphi, *bplo, *fphi, *fplo, *h1hi, *h1lo, *h2hi, *h2lo;
    cudaGetSymbolAddress((void**)&bphi, g_bpad_hi); cudaGetSymbolAddress((void**)&bplo, g_bpad_lo);
    cudaGetSymbolAddress((void**)&fphi, g_fpad_hi); cudaGetSymbolAddress((void**)&fplo, g_fpad_lo);
    cudaGetSymbolAddress((void**)&h1hi, g_h1pad_hi); cudaGetSymbolAddress((void**)&h1lo, g_h1pad_lo);
    cudaGetSymbolAddress((void**)&h2hi, g_h2pad_hi); cudaGetSymbolAddress((void**)&h2lo, g_h2pad_lo);

    __nv_bfloat16 *wRhi, *wRlo, *wK1hi, *wK1lo, *wV1hi, *wV1lo;
    __nv_bfloat16 *wK2hi, *wK2lo, *wV2hi, *wV2lo, *wC1hi, *wC1lo, *wC2hi, *wC2lo;
    cudaGetSymbolAddress((void**)&wRhi,  g_wRhi);  cudaGetSymbolAddress((void**)&wRlo,  g_wRlo);
    cudaGetSymbolAddress((void**)&wK1hi, g_wK1hi); cudaGetSymbolAddress((void**)&wK1lo, g_wK1lo);
    cudaGetSymbolAddress((void**)&wV1hi, g_wV1hi); cudaGetSymbolAddress((void**)&wV1lo, g_wV1lo);
    cudaGetSymbolAddress((void**)&wK2hi, g_wK2hi); cudaGetSymbolAddress((void**)&wK2lo, g_wK2lo);
    cudaGetSymbolAddress((void**)&wV2hi, g_wV2hi); cudaGetSymbolAddress((void**)&wV2lo, g_wV2lo);
    cudaGetSymbolAddress((void**)&wC1hi, g_wC1hi); cudaGetSymbolAddress((void**)&wC1lo, g_wC1lo);
    cudaGetSymbolAddress((void**)&wC2hi, g_wC2hi); cudaGetSymbolAddress((void**)&wC2lo, g_wC2lo);

    cudaFuncSetAttribute(conv_mma, cudaFuncAttributeMaxDynamicSharedMemorySize, SMEM_BYTES);

    // weight reorder+split
    const int nR = K_RED * CH, nC = K_CC * CH;
    split_w_reorder<<<(nR + 255) / 256, 256>>>(wR,  wRhi,  wRlo,  CIN, nR);
    split_w_reorder<<<(nC + 255) / 256, 256>>>(wK1, wK1hi, wK1lo, CH,  nC);
    split_w_reorder<<<(nC + 255) / 256, 256>>>(wV1, wV1hi, wV1lo, CH,  nC);
    split_w_reorder<<<(nC + 255) / 256, 256>>>(wK2, wK2hi, wK2lo, CH,  nC);
    split_w_reorder<<<(nC + 255) / 256, 256>>>(wV2, wV2hi, wV2lo, CH,  nC);
    split_w_reorder<<<(nC + 255) / 256, 256>>>(wC1, wC1hi, wC1lo, CH,  nC);
    split_w_reorder<<<(nC + 255) / 256, 256>>>(wC2, wC2hi, wC2lo, CH,  nC);

    // pad-convert bbox
    pad_convert<<<dim3(NSAMP, CIN / 64), 256>>>(bbox, bphi, bplo, CIN);

    // feat = conv(bbox_feat, w_reduce)
    {
        ConvBatch P = {};
        P.ahi[0] = bphi; P.alo[0] = bplo;
        P.whi[0] = wRhi; P.wlo[0] = wRlo; P.out[0] = feat;
        P.addsrc = nullptr;
        conv_mma<<<dim3(NSAMP * HW / 128, CH / 128, 1), 256, SMEM_BYTES>>>(P, CIN);
    }

    // q convs (spatially-constant input), both branches
    q_conv2<<<dim3((FEAT_ELEMS + 255) / 256, 2), 256>>>(status, rois, wQ1, wQ2, q1, q2);

    // pad-convert feat
    pad_convert<<<dim3(NSAMP, CH / 64), 256>>>(feat, fphi, fplo, CH);

    // k/v convs (4 fused)
    {
        ConvBatch P = {};
        for (int i = 0; i < 4; i++) { P.ahi[i] = fphi; P.alo[i] = fplo; }
        P.whi[0] = wK1hi; P.wlo[0] = wK1lo; P.out[0] = k1;
        P.whi[1] = wV1hi; P.wlo[1] = wV1lo; P.out[1] = v1;
        P.whi[2] = wK2hi; P.wlo[2] = wK2lo; P.out[2] = k2;
        P.whi[3] = wV2hi; P.wlo[3] = wV2lo; P.out[3] = v2;
        P.addsrc = nullptr;
        conv_mma<<<dim3(NSAMP * HW / 128, CH / 128, 4), 256, SMEM_BYTES>>>(P, CH);
    }

    // attention, both branches
    attn2<<<dim3(HW, NG, 2), 256>>>(q1, k1, v1, vir1, q2, k2, v2, vir2);

    // groupnorm stats, both branches
    gn_stats2<<<512, 256>>>(vir1, vir2, stats);

    // fused normalize+relu+pad-convert, both branches
    norm_relu_pad<<<dim3(NSAMP, CH / 64, 2), 256>>>(vir1, vir2, stats, gamma, beta,
                                                    h1hi, h1lo, h2hi, h2lo);

    // out convs (2 fused): out = feat + conv(h, w_c)
    {
        ConvBatch P = {};
        P.ahi[0] = h1hi; P.alo[0] = h1lo;
        P.ahi[1] = h2hi; P.alo[1] = h2lo;
        P.whi[0] = wC1hi; P.wlo[0] = wC1lo; P.out[0] = out1;
        P.whi[1] = wC2hi; P.wlo[1] = wC2lo; P.out[1] = out2;
        P.addsrc = feat;
        conv_mma<<<dim3(NSAMP * HW / 128, CH / 128, 2), 256, SMEM_BYTES>>>(P, CH);
    }
}

// round 6
// speedup vs baseline: 4.4385x; 1.4363x over previous
#include <cuda_runtime.h>
#include <cuda_fp16.h>
#include <cstdint>
#include <math.h>

// ---------------- problem constants ----------------
#define NSAMP 256
#define CIN   2304
#define CH    512
#define HW    49
#define NG    16
#define GSZ   16
#define K_RED (CIN*9)    // 20736
#define K_CC  (CH*9)     // 4608
#define FEAT_ELEMS (NSAMP*CH*HW)   // 6422528
#define EPSG  1e-5f
#define ATT_SCALE 0.044194173824159216f  // 1/sqrt(512)

// ---------------- scratch (device globals; no allocation) ----------------
__device__ float g_feat [FEAT_ELEMS];
__device__ float g_q1   [FEAT_ELEMS];
__device__ float g_q2   [FEAT_ELEMS];
__device__ float g_k1   [FEAT_ELEMS];
__device__ float g_v1   [FEAT_ELEMS];
__device__ float g_k2   [FEAT_ELEMS];
__device__ float g_v2   [FEAT_ELEMS];
__device__ float g_vir1 [FEAT_ELEMS];
__device__ float g_vir2 [FEAT_ELEMS];
__device__ float g_stats[1024];

// padded channel-last activations: [n][81][C], fp16 hi/lo, zero border
__device__ __align__(256) __half g_bpad_hi[NSAMP*81*CIN];
__device__ __align__(256) __half g_bpad_lo[NSAMP*81*CIN];
__device__ __align__(256) __half g_fpad_hi[NSAMP*81*CH];
__device__ __align__(256) __half g_fpad_lo[NSAMP*81*CH];
__device__ __align__(256) __half g_h1pad_hi[NSAMP*81*CH];
__device__ __align__(256) __half g_h1pad_lo[NSAMP*81*CH];
__device__ __align__(256) __half g_h2pad_hi[NSAMP*81*CH];
__device__ __align__(256) __half g_h2pad_lo[NSAMP*81*CH];

// fp16 weights, tap-major layout [co][tap][ci]
__device__ __align__(256) __half g_wR [K_RED*CH];
__device__ __align__(256) __half g_wK1[K_CC*CH];
__device__ __align__(256) __half g_wV1[K_CC*CH];
__device__ __align__(256) __half g_wK2[K_CC*CH];
__device__ __align__(256) __half g_wV2[K_CC*CH];
__device__ __align__(256) __half g_wC1[K_CC*CH];
__device__ __align__(256) __half g_wC2[K_CC*CH];

// ---------------- helpers ----------------
__device__ __forceinline__ uint32_t smem_u32(const void* p) {
    uint32_t a;
    asm("{ .reg .u64 t; cvta.to.shared.u64 t, %1; cvt.u32.u64 %0, t; }" : "=r"(a) : "l"(p));
    return a;
}
__device__ __forceinline__ void cp_async16(uint32_t dst, const void* src) {
    asm volatile("cp.async.cg.shared.global [%0], [%1], 16;" :: "r"(dst), "l"(src));
}
__device__ __forceinline__ void ldm_x4(uint32_t* r, uint32_t addr) {
    asm volatile("ldmatrix.sync.aligned.m8n8.x4.shared.b16 {%0,%1,%2,%3}, [%4];"
        : "=r"(r[0]), "=r"(r[1]), "=r"(r[2]), "=r"(r[3]) : "r"(addr));
}
__device__ __forceinline__ void mma_f16(float* d, const uint32_t* a, const uint32_t* b) {
    asm volatile(
        "mma.sync.aligned.m16n8k16.row.col.f32.f16.f16.f32 "
        "{%0,%1,%2,%3}, {%4,%5,%6,%7}, {%8,%9}, {%0,%1,%2,%3};\n"
        : "+f"(d[0]), "+f"(d[1]), "+f"(d[2]), "+f"(d[3])
        : "r"(a[0]), "r"(a[1]), "r"(a[2]), "r"(a[3]), "r"(b[0]), "r"(b[1]));
}

// ---------------- weight reorder + fp16 round: w[co][ci*9+t] -> wh[co][t*C+ci] --
__global__ void conv_w_reorder(const float* __restrict__ w, __half* __restrict__ wh,
                               int C, int total) {
    int i = blockIdx.x * 256 + threadIdx.x;
    if (i >= total) return;
    int K9 = 9 * C;
    int co = i / K9, rem = i - co * K9;
    int t = rem / C, ci = rem - t * C;
    wh[i] = __float2half_rn(w[(size_t)co * K9 + ci * 9 + t]);
}

// ---------------- NCHW float -> padded channel-last fp16 hi/lo ----------------
__global__ void pad_convert(const float* __restrict__ src, __half* __restrict__ hi,
                            __half* __restrict__ lo, int C) {
    int n = blockIdx.x, c0 = blockIdx.y * 64;
    __shared__ float tile[64][51];
    int tid = threadIdx.x;
    for (int e = tid; e < 64 * 49; e += 256) {
        int ci = e / 49, p = e - 49 * ci;
        tile[ci][p] = src[((size_t)n * C + c0 + ci) * 49 + p];
    }
    __syncthreads();
    for (int e = tid; e < 81 * 64; e += 256) {
        int pp = e >> 6, ci = e & 63;
        int y = pp / 9, x = pp - 9 * y;
        float v = 0.f;
        if (y >= 1 && y <= 7 && x >= 1 && x <= 7) v = tile[ci][(y - 1) * 7 + (x - 1)];
        __half h = __float2half_rn(v);
        size_t di = ((size_t)n * 81 + pp) * C + c0 + ci;
        hi[di] = h;
        lo[di] = __float2half_rn(v - __half2float(h));
    }
}

// ---------------- fused GN-normalize + relu + pad-convert (both branches) -----
__global__ void norm_relu_pad(const float* __restrict__ x1, const float* __restrict__ x2,
                              const float* __restrict__ stats,
                              const float* __restrict__ gamma, const float* __restrict__ beta,
                              __half* __restrict__ h1hi, __half* __restrict__ h1lo,
                              __half* __restrict__ h2hi, __half* __restrict__ h2lo) {
    int n = blockIdx.x, c0 = blockIdx.y * 64, br = blockIdx.z;
    const float* x = br ? x2 : x1;
    __half* hi = br ? h2hi : h1hi;
    __half* lo = br ? h2lo : h1lo;
    float mu = stats[br * 512 + n];
    float rs = stats[br * 512 + 256 + n];
    __shared__ float tile[64][51];
    int tid = threadIdx.x;
    for (int e = tid; e < 64 * 49; e += 256) {
        int ci = e / 49, p = e - 49 * ci;
        float v = x[((size_t)n * CH + c0 + ci) * 49 + p];
        tile[ci][p] = fmaxf((v - mu) * rs * gamma[c0 + ci] + beta[c0 + ci], 0.f);
    }
    __syncthreads();
    for (int e = tid; e < 81 * 64; e += 256) {
        int pp = e >> 6, ci = e & 63;
        int y = pp / 9, x9 = pp - 9 * y;
        float v = 0.f;
        if (y >= 1 && y <= 7 && x9 >= 1 && x9 <= 7) v = tile[ci][(y - 1) * 7 + (x9 - 1)];
        __half h = __float2half_rn(v);
        size_t di = ((size_t)n * 81 + pp) * CH + c0 + ci;
        hi[di] = h;
        lo[di] = __float2half_rn(v - __half2float(h));
    }
}

// ---------------- batched HMMA conv: 9 shifted 1x1 GEMMs over padded input ----
// out[n,co,p] = sum_{t,ci} xpad[n, pp(p,t), ci] * wh[co, t*C+ci]
// fp16 2-term activation split: D = (ah + al) * bh  (exact-A x fp16-W)
// CTA tile 128x128, 8 warps (2x4), warp tile 64x32, K chunk 32, double-buffered.
#define KCP  40                      // SMEM row stride (fp16 elems) = 80B
#define MATH (128*KCP)               // 5120 fp16 per matrix
#define BUFE (3*MATH)                // Ahi, Alo, Bh
#define SMEM_BYTES (2*BUFE*2)        // 61440 bytes

struct ConvBatch {
    const __half* ahi[4];
    const __half* alo[4];
    const __half* wh[4];
    float* out[4];
    const float* addsrc;
};

__global__ void __launch_bounds__(256, 2)
conv_mma(ConvBatch P, int C) {
    extern __shared__ __half smem[];
    const int K9 = 9 * C;
    const int NCI = C / 32;
    const int NQ = 9 * NCI;
    const int cv = blockIdx.z;
    const __half* __restrict__ Ahi = P.ahi[cv];
    const __half* __restrict__ Alo = P.alo[cv];
    const __half* __restrict__ Wh  = P.wh[cv];
    float* __restrict__ out = P.out[cv];
    const float* addsrc = P.addsrc;

    const int tid = threadIdx.x;
    const int wid = tid >> 5, lane = tid & 31;
    const int g = lane >> 2, tg = lane & 3;
    const int m0 = blockIdx.x * 128;
    const int n0 = blockIdx.y * 128;
    const int wm = (wid & 1) * 64;
    const int wn = (wid >> 1) * 32;

    // fill geometry: thread serves rows r0 and r0+64, 16B segment `seg`
    const int seg = tid & 3;
    const int r0 = tid >> 2;          // 0..63
    size_t abase[2];
#pragma unroll
    for (int h = 0; h < 2; h++) {
        int m = m0 + r0 + 64 * h;
        int n = m / 49, p = m - 49 * n;
        int y = p / 7, x = p - 7 * y;
        abase[h] = ((size_t)n * 81 + y * 9 + x) * C + seg * 8;
    }

    // ldmatrix lane geometry
    const int aRow = wm + (lane & 15);         // + 16*t
    const int aCol = (lane >> 4) * 8;          // + 16*s
    const int bRow = wn + (lane & 7) + ((lane >> 4) * 8);   // + 16 for second x4
    const int bCol = ((lane >> 3) & 1) * 8;    // + 16*s

    auto fill = [&](int q, __half* base) {
        int t = q / NCI;
        int ci = (q - t * NCI) * 32;
        int a3 = t / 3, b3 = t - 3 * a3;
        size_t tof = (size_t)(a3 * 9 + b3) * C + ci;
#pragma unroll
        for (int h = 0; h < 2; h++) {
            int r = r0 + 64 * h;
            size_t src = abase[h] + tof;
            uint32_t d = smem_u32(&base[r * KCP + seg * 8]);
            cp_async16(d, Ahi + src);
            cp_async16(d + MATH * 2, Alo + src);     // +MATH fp16 = +2*MATH bytes
        }
#pragma unroll
        for (int h = 0; h < 2; h++) {
            int row = r0 + 64 * h;
            size_t src = (size_t)(n0 + row) * K9 + t * C + ci + seg * 8;
            cp_async16(smem_u32(&base[2 * MATH + row * KCP + seg * 8]), Wh + src);
        }
        asm volatile("cp.async.commit_group;" ::: "memory");
    };

    float acc[4][4][4];
#pragma unroll
    for (int t = 0; t < 4; t++)
#pragma unroll
        for (int u = 0; u < 4; u++)
#pragma unroll
            for (int e = 0; e < 4; e++) acc[t][u][e] = 0.f;

    fill(0, smem);

    for (int q = 0; q < NQ; q++) {
        if (q + 1 < NQ) {
            fill(q + 1, smem + ((q + 1) & 1) * BUFE);
            asm volatile("cp.async.wait_group 1;" ::: "memory");
        } else {
            asm volatile("cp.async.wait_group 0;" ::: "memory");
        }
        __syncthreads();

        __half* cur = smem + (q & 1) * BUFE;
        uint32_t aHiB = smem_u32(cur);
        uint32_t aLoB = aHiB + MATH * 2;
        uint32_t bB   = aHiB + 4 * MATH;     // 2*MATH elems * 2 bytes
#pragma unroll
        for (int s = 0; s < 2; s++) {
            uint32_t bregs[8];
            ldm_x4(bregs,     bB + (uint32_t)((bRow)      * KCP + 16 * s + bCol) * 2);
            ldm_x4(bregs + 4, bB + (uint32_t)((bRow + 16) * KCP + 16 * s + bCol) * 2);
#pragma unroll
            for (int t = 0; t < 4; t++) {
                uint32_t ah[4], al[4];
                uint32_t aoff = (uint32_t)((aRow + 16 * t) * KCP + 16 * s + aCol) * 2;
                ldm_x4(ah, aHiB + aoff);
                ldm_x4(al, aLoB + aoff);
#pragma unroll
                for (int u = 0; u < 4; u++) {
                    mma_f16(acc[t][u], ah, bregs + 2 * u);
                    mma_f16(acc[t][u], al, bregs + 2 * u);
                }
            }
        }
        __syncthreads();
    }

    // ---- epilogue ----
#pragma unroll
    for (int t = 0; t < 4; t++) {
#pragma unroll
        for (int h = 0; h < 2; h++) {
            int row = m0 + wm + 16 * t + g + 8 * h;
            int n = row / 49, p = row - 49 * n;
            size_t base = (size_t)n * CH * 49 + p;
#pragma unroll
            for (int u = 0; u < 4; u++) {
                int col = n0 + wn + 8 * u + tg * 2;
                size_t i0 = base + (size_t)col * 49;
                float v0 = acc[t][u][2 * h];
                float v1 = acc[t][u][2 * h + 1];
                if (addsrc) { v0 += addsrc[i0]; v1 += addsrc[i0 + 49]; }
                out[i0] = v0;
                out[i0 + 49] = v1;
            }
        }
    }
}

// ---------------- q-conv (spatially-constant input), y = branch ----------
__global__ void q_conv2(const float* __restrict__ status, const float* __restrict__ rois,
                        const float* __restrict__ wq1, const float* __restrict__ wq2,
                        float* __restrict__ o1, float* __restrict__ o2) {
    int idx = blockIdx.x * 256 + threadIdx.x;
    if (idx >= NSAMP * CH * HW) return;
    int scol = blockIdx.y;
    const float* wq = scol ? wq2 : wq1;
    float* out = scol ? o2 : o1;
    int p = idx % HW;
    int t2 = idx / HW;
    int co = t2 % CH;
    int n = t2 / CH;
    int y = p / 7, x = p - (p / 7) * 7;
    float s[5];
    s[0] = status[n * 2 + scol];
    s[1] = rois[n * 5 + 1];
    s[2] = rois[n * 5 + 2];
    s[3] = rois[n * 5 + 3];
    s[4] = rois[n * 5 + 4];
    const float* w = wq + co * 45;
    float acc = 0.f;
#pragma unroll
    for (int ci = 0; ci < 5; ci++)
#pragma unroll
        for (int dy = 0; dy < 3; dy++)
#pragma unroll
            for (int dx = 0; dx < 3; dx++) {
                int yy = y + dy - 1, xx = x + dx - 1;
                if ((unsigned)yy < 7u && (unsigned)xx < 7u)
                    acc += w[ci * 9 + dy * 3 + dx] * s[ci];
            }
    out[idx] = acc;
}

// ---------------- attention per (hw, g), z = branch ----------------
#define CCH 256
__global__ void attn2(const float* __restrict__ q1, const float* __restrict__ k1,
                      const float* __restrict__ v1, float* __restrict__ w1,
                      const float* __restrict__ q2, const float* __restrict__ k2,
                      const float* __restrict__ v2, float* __restrict__ w2) {
    int hw = blockIdx.x;
    int gg = blockIdx.y;
    int br = blockIdx.z;
    const float* q = br ? q2 : q1;
    const float* k = br ? k2 : k1;
    const float* v = br ? v2 : v1;
    float* virt = br ? w2 : w1;

    __shared__ float bufA[GSZ][CCH + 1];
    __shared__ float bufB[GSZ][CCH + 1];
    __shared__ float att[GSZ][GSZ + 1];
    __shared__ float attn[GSZ][GSZ + 1];

    int tid = threadIdx.x;
    int i = tid >> 4, j = tid & 15;
    float a = 0.f;

    for (int c0 = 0; c0 < CH; c0 += CCH) {
        for (int e = tid; e < GSZ * CCH; e += 256) {
            int r = e >> 8, c = e & 255;
            int gidx = ((gg * GSZ + r) * CH + c0 + c) * HW + hw;
            bufA[r][c] = q[gidx];
            bufB[r][c] = k[gidx];
        }
        __syncthreads();
#pragma unroll 8
        for (int c = 0; c < CCH; c++)
            a += bufA[i][c] * bufB[j][c];
        __syncthreads();
    }
    att[i][j] = a * ATT_SCALE;
    __syncthreads();

    float mx = att[i][0];
#pragma unroll
    for (int jj = 1; jj < GSZ; jj++) mx = fmaxf(mx, att[i][jj]);
    float sum = 0.f;
#pragma unroll
    for (int jj = 0; jj < GSZ; jj++) sum += expf(att[i][jj] - mx);
    attn[i][j] = expf(att[i][j] - mx) / sum;
    __syncthreads();

    for (int c0 = 0; c0 < CH; c0 += CCH) {
        for (int e = tid; e < GSZ * CCH; e += 256) {
            int r = e >> 8, c = e & 255;
            bufA[r][c] = v[((gg * GSZ + r) * CH + c0 + c) * HW + hw];
        }
        __syncthreads();
        for (int e = tid; e < GSZ * CCH; e += 256) {
            int r = e >> 8, c = e & 255;
            float s = 0.f;
#pragma unroll
            for (int jj = 0; jj < GSZ; jj++) s += attn[r][jj] * bufA[jj][c];
            virt[((gg * GSZ + r) * CH + c0 + c) * HW + hw] = s;
        }
        __syncthreads();
    }
}

// ---------------- groupnorm stats, both branches ----------
__global__ void gn_stats2(const float* __restrict__ x1, const float* __restrict__ x2,
                          float* __restrict__ stats) {
    __shared__ float ss[256], sq[256];
    int blk = blockIdx.x;
    int br = blk >> 8, n = blk & 255;
    const float* p = (br ? x2 : x1) + (size_t)n * CH * HW;
    float a = 0.f, b = 0.f;
    for (int e = threadIdx.x; e < CH * HW; e += 256) {
        float v = p[e];
        a += v; b += v * v;
    }
    ss[threadIdx.x] = a; sq[threadIdx.x] = b;
    __syncthreads();
    for (int s = 128; s > 0; s >>= 1) {
        if (threadIdx.x < s) { ss[threadIdx.x] += ss[threadIdx.x + s]; sq[threadIdx.x] += sq[threadIdx.x + s]; }
        __syncthreads();
    }
    if (threadIdx.x == 0) {
        float m = ss[0] / (float)(CH * HW);
        float var = sq[0] / (float)(CH * HW) - m * m;
        stats[br * 512 + n] = m;
        stats[br * 512 + 256 + n] = rsqrtf(var + EPSG);
    }
}

// ---------------- launcher ----------------
extern "C" void kernel_launch(void* const* d_in, const int* in_sizes, int n_in,
                              void* d_out, int out_size) {
    const float* status = (const float*)d_in[0];
    const float* rois   = (const float*)d_in[1];
    const float* bbox   = (const float*)d_in[2];
    const float* wR     = (const float*)d_in[3];
    const float* wQ1    = (const float*)d_in[4];
    const float* wQ2    = (const float*)d_in[5];
    const float* wK1    = (const float*)d_in[6];
    const float* wV1    = (const float*)d_in[7];
    const float* wK2    = (const float*)d_in[8];
    const float* wV2    = (const float*)d_in[9];
    const float* wC1    = (const float*)d_in[10];
    const float* wC2    = (const float*)d_in[11];
    const float* gamma  = (const float*)d_in[12];
    const float* beta   = (const float*)d_in[13];
    float* out1 = (float*)d_out;
    float* out2 = out1 + FEAT_ELEMS;

    float *feat, *q1, *q2, *k1, *v1, *k2, *v2, *vir1, *vir2, *stats;
    cudaGetSymbolAddress((void**)&feat, g_feat);
    cudaGetSymbolAddress((void**)&q1,   g_q1);
    cudaGetSymbolAddress((void**)&q2,   g_q2);
    cudaGetSymbolAddress((void**)&k1,   g_k1);
    cudaGetSymbolAddress((void**)&v1,   g_v1);
    cudaGetSymbolAddress((void**)&k2,   g_k2);
    cudaGetSymbolAddress((void**)&v2,   g_v2);
    cudaGetSymbolAddress((void**)&vir1, g_vir1);
    cudaGetSymbolAddress((void**)&vir2, g_vir2);
    cudaGetSymbolAddress((void**)&stats, g_stats);

    __half *bphi, *bplo, *fphi, *fplo, *h1hi, *h1lo, *h2hi, *h2lo;
    cudaGetSymbolAddress((void**)&bphi, g_bpad_hi); cudaGetSymbolAddress((void**)&bplo, g_bpad_lo);
    cudaGetSymbolAddress((void**)&fphi, g_fpad_hi); cudaGetSymbolAddress((void**)&fplo, g_fpad_lo);
    cudaGetSymbolAddress((void**)&h1hi, g_h1pad_hi); cudaGetSymbolAddress((void**)&h1lo, g_h1pad_lo);
    cudaGetSymbolAddress((void**)&h2hi, g_h2pad_hi); cudaGetSymbolAddress((void**)&h2lo, g_h2pad_lo);

    __half *whR, *whK1, *whV1, *whK2, *whV2, *whC1, *whC2;
    cudaGetSymbolAddress((void**)&whR,  g_wR);
    cudaGetSymbolAddress((void**)&whK1, g_wK1);
    cudaGetSymbolAddress((void**)&whV1, g_wV1);
    cudaGetSymbolAddress((void**)&whK2, g_wK2);
    cudaGetSymbolAddress((void**)&whV2, g_wV2);
    cudaGetSymbolAddress((void**)&whC1, g_wC1);
    cudaGetSymbolAddress((void**)&whC2, g_wC2);

    cudaFuncSetAttribute(conv_mma, cudaFuncAttributeMaxDynamicSharedMemorySize, SMEM_BYTES);

    // weight reorder + fp16 round
    const int nR = K_RED * CH, nC = K_CC * CH;
    conv_w_reorder<<<(nR + 255) / 256, 256>>>(wR,  whR,  CIN, nR);
    conv_w_reorder<<<(nC + 255) / 256, 256>>>(wK1, whK1, CH,  nC);
    conv_w_reorder<<<(nC + 255) / 256, 256>>>(wV1, whV1, CH,  nC);
    conv_w_reorder<<<(nC + 255) / 256, 256>>>(wK2, whK2, CH,  nC);
    conv_w_reorder<<<(nC + 255) / 256, 256>>>(wV2, whV2, CH,  nC);
    conv_w_reorder<<<(nC + 255) / 256, 256>>>(wC1, whC1, CH,  nC);
    conv_w_reorder<<<(nC + 255) / 256, 256>>>(wC2, whC2, CH,  nC);

    // pad-convert bbox
    pad_convert<<<dim3(NSAMP, CIN / 64), 256>>>(bbox, bphi, bplo, CIN);

    // feat = conv(bbox_feat, w_reduce)
    {
        ConvBatch P = {};
        P.ahi[0] = bphi; P.alo[0] = bplo; P.wh[0] = whR; P.out[0] = feat;
        P.addsrc = nullptr;
        conv_mma<<<dim3(NSAMP * HW / 128, CH / 128, 1), 256, SMEM_BYTES>>>(P, CIN);
    }

    // q convs (spatially-constant input), both branches
    q_conv2<<<dim3((FEAT_ELEMS + 255) / 256, 2), 256>>>(status, rois, wQ1, wQ2, q1, q2);

    // pad-convert feat
    pad_convert<<<dim3(NSAMP, CH / 64), 256>>>(feat, fphi, fplo, CH);

    // k/v convs (4 fused)
    {
        ConvBatch P = {};
        for (int i = 0; i < 4; i++) { P.ahi[i] = fphi; P.alo[i] = fplo; }
        P.wh[0] = whK1; P.out[0] = k1;
        P.wh[1] = whV1; P.out[1] = v1;
        P.wh[2] = whK2; P.out[2] = k2;
        P.wh[3] = whV2; P.out[3] = v2;
        P.addsrc = nullptr;
        conv_mma<<<dim3(NSAMP * HW / 128, CH / 128, 4), 256, SMEM_BYTES>>>(P, CH);
    }

    // attention, both branches
    attn2<<<dim3(HW, NG, 2), 256>>>(q1, k1, v1, vir1, q2, k2, v2, vir2);

    // groupnorm stats, both branches
    gn_stats2<<<512, 256>>>(vir1, vir2, stats);

    // fused normalize+relu+pad-convert, both branches
    norm_relu_pad<<<dim3(NSAMP, CH / 64, 2), 256>>>(vir1, vir2, stats, gamma, beta,
                                                    h1hi, h1lo, h2hi, h2lo);

    // out convs (2 fused): out = feat + conv(h, w_c)
    {
        ConvBatch P = {};
        P.ahi[0] = h1hi; P.alo[0] = h1lo; P.wh[0] = whC1; P.out[0] = out1;
        P.ahi[1] = h2hi; P.alo[1] = h2lo; P.wh[1] = whC2; P.out[1] = out2;
        P.addsrc = feat;
        conv_mma<<<dim3(NSAMP * HW / 128, CH / 128, 2), 256, SMEM_BYTES>>>(P, CH);
    }
}

// round 7
// speedup vs baseline: 6.6580x; 1.5001x over previous
#include <cuda_runtime.h>
#include <cuda_fp16.h>
#include <cstdint>
#include <math.h>

// ---------------- problem constants ----------------
#define NSAMP 256
#define CIN   2304
#define CH    512
#define HW    49
#define NG    16
#define GSZ   16
#define K_RED (CIN*9)    // 20736
#define K_CC  (CH*9)     // 4608
#define FEAT_ELEMS (NSAMP*CH*HW)   // 6422528
#define EPSG  1e-5f
#define ATT_SCALE 0.044194173824159216f  // 1/sqrt(512)

// ---------------- scratch (device globals; no allocation) ----------------
__device__ float g_feat [FEAT_ELEMS];
__device__ float g_q1   [FEAT_ELEMS];
__device__ float g_q2   [FEAT_ELEMS];
__device__ float g_k1   [FEAT_ELEMS];
__device__ float g_v1   [FEAT_ELEMS];
__device__ float g_k2   [FEAT_ELEMS];
__device__ float g_v2   [FEAT_ELEMS];
__device__ float g_vir1 [FEAT_ELEMS];
__device__ float g_vir2 [FEAT_ELEMS];
__device__ float g_stats[1024];

// padded channel-last activations: [n][81][C], fp16, zero border
__device__ __align__(256) __half g_bpad [NSAMP*81*CIN];
__device__ __align__(256) __half g_fpad [NSAMP*81*CH];
__device__ __align__(256) __half g_h1pad[NSAMP*81*CH];
__device__ __align__(256) __half g_h2pad[NSAMP*81*CH];

// fp16 weights, tap-major layout [co][tap][ci]
__device__ __align__(256) __half g_wR [K_RED*CH];
__device__ __align__(256) __half g_wK1[K_CC*CH];
__device__ __align__(256) __half g_wV1[K_CC*CH];
__device__ __align__(256) __half g_wK2[K_CC*CH];
__device__ __align__(256) __half g_wV2[K_CC*CH];
__device__ __align__(256) __half g_wC1[K_CC*CH];
__device__ __align__(256) __half g_wC2[K_CC*CH];

// ---------------- helpers ----------------
__device__ __forceinline__ uint32_t smem_u32(const void* p) {
    uint32_t a;
    asm("{ .reg .u64 t; cvta.to.shared.u64 t, %1; cvt.u32.u64 %0, t; }" : "=r"(a) : "l"(p));
    return a;
}
__device__ __forceinline__ void cp_async16(uint32_t dst, const void* src) {
    asm volatile("cp.async.cg.shared.global [%0], [%1], 16;" :: "r"(dst), "l"(src));
}
__device__ __forceinline__ void ldm_x4(uint32_t* r, uint32_t addr) {
    asm volatile("ldmatrix.sync.aligned.m8n8.x4.shared.b16 {%0,%1,%2,%3}, [%4];"
        : "=r"(r[0]), "=r"(r[1]), "=r"(r[2]), "=r"(r[3]) : "r"(addr));
}
__device__ __forceinline__ void mma_f16(float* d, const uint32_t* a, const uint32_t* b) {
    asm volatile(
        "mma.sync.aligned.m16n8k16.row.col.f32.f16.f16.f32 "
        "{%0,%1,%2,%3}, {%4,%5,%6,%7}, {%8,%9}, {%0,%1,%2,%3};\n"
        : "+f"(d[0]), "+f"(d[1]), "+f"(d[2]), "+f"(d[3])
        : "r"(a[0]), "r"(a[1]), "r"(a[2]), "r"(a[3]), "r"(b[0]), "r"(b[1]));
}

// ---------------- weight reorder + fp16 round: w[co][ci*9+t] -> wh[co][t*C+ci] --
__global__ void conv_w_reorder(const float* __restrict__ w, __half* __restrict__ wh,
                               int C, int total) {
    int i = blockIdx.x * 256 + threadIdx.x;
    if (i >= total) return;
    int K9 = 9 * C;
    int co = i / K9, rem = i - co * K9;
    int t = rem / C, ci = rem - t * C;
    wh[i] = __float2half_rn(w[(size_t)co * K9 + ci * 9 + t]);
}

// ---------------- NCHW float -> padded channel-last fp16 ----------------
__global__ void pad_convert(const float* __restrict__ src, __half* __restrict__ hi, int C) {
    int n = blockIdx.x, c0 = blockIdx.y * 64;
    __shared__ float tile[64][51];
    int tid = threadIdx.x;
    for (int e = tid; e < 64 * 49; e += 256) {
        int ci = e / 49, p = e - 49 * ci;
        tile[ci][p] = src[((size_t)n * C + c0 + ci) * 49 + p];
    }
    __syncthreads();
    for (int e = tid; e < 81 * 64; e += 256) {
        int pp = e >> 6, ci = e & 63;
        int y = pp / 9, x = pp - 9 * y;
        float v = 0.f;
        if (y >= 1 && y <= 7 && x >= 1 && x <= 7) v = tile[ci][(y - 1) * 7 + (x - 1)];
        hi[((size_t)n * 81 + pp) * C + c0 + ci] = __float2half_rn(v);
    }
}

// ---------------- fused GN-normalize + relu + pad-convert (both branches) -----
__global__ void norm_relu_pad(const float* __restrict__ x1, const float* __restrict__ x2,
                              const float* __restrict__ stats,
                              const float* __restrict__ gamma, const float* __restrict__ beta,
                              __half* __restrict__ h1, __half* __restrict__ h2) {
    int n = blockIdx.x, c0 = blockIdx.y * 64, br = blockIdx.z;
    const float* x = br ? x2 : x1;
    __half* hp = br ? h2 : h1;
    float mu = stats[br * 512 + n];
    float rs = stats[br * 512 + 256 + n];
    __shared__ float tile[64][51];
    int tid = threadIdx.x;
    for (int e = tid; e < 64 * 49; e += 256) {
        int ci = e / 49, p = e - 49 * ci;
        float v = x[((size_t)n * CH + c0 + ci) * 49 + p];
        tile[ci][p] = fmaxf((v - mu) * rs * gamma[c0 + ci] + beta[c0 + ci], 0.f);
    }
    __syncthreads();
    for (int e = tid; e < 81 * 64; e += 256) {
        int pp = e >> 6, ci = e & 63;
        int y = pp / 9, x9 = pp - 9 * y;
        float v = 0.f;
        if (y >= 1 && y <= 7 && x9 >= 1 && x9 <= 7) v = tile[ci][(y - 1) * 7 + (x9 - 1)];
        hp[((size_t)n * 81 + pp) * CH + c0 + ci] = __float2half_rn(v);
    }
}

// ---------------- batched HMMA conv: 9 shifted 1x1 GEMMs over padded input ----
// out[n,co,p] = sum_{t,ci} xpad[n, pp(p,t), ci] * wh[co, t*C+ci]   (fp16 x fp16, fp32 acc)
// CTA tile 128x128, 8 warps (2x4), warp tile 64x32, K chunk 32, double-buffered.
#define KCP  40                      // SMEM row stride (fp16 elems) = 80B
#define MATH (128*KCP)               // 5120 fp16 per matrix
#define BUFE (2*MATH)                // A, B
#define SMEM_BYTES (2*BUFE*2)        // 40960 bytes

struct ConvBatch {
    const __half* a[4];
    const __half* wh[4];
    float* out[4];
    const float* addsrc;
};

__global__ void __launch_bounds__(256, 2)
conv_mma(ConvBatch P, int C) {
    extern __shared__ __half smem[];
    const int K9 = 9 * C;
    const int NCI = C / 32;
    const int NQ = 9 * NCI;
    const int cv = blockIdx.z;
    const __half* __restrict__ A  = P.a[cv];
    const __half* __restrict__ Wh = P.wh[cv];
    float* __restrict__ out = P.out[cv];
    const float* addsrc = P.addsrc;

    const int tid = threadIdx.x;
    const int wid = tid >> 5, lane = tid & 31;
    const int g = lane >> 2, tg = lane & 3;
    const int m0 = blockIdx.x * 128;
    const int n0 = blockIdx.y * 128;
    const int wm = (wid & 1) * 64;
    const int wn = (wid >> 1) * 32;

    // fill geometry: thread serves rows r0 and r0+64, 16B segment `seg`
    const int seg = tid & 3;
    const int r0 = tid >> 2;          // 0..63
    size_t abase[2];
#pragma unroll
    for (int h = 0; h < 2; h++) {
        int m = m0 + r0 + 64 * h;
        int n = m / 49, p = m - 49 * n;
        int y = p / 7, x = p - 7 * y;
        abase[h] = ((size_t)n * 81 + y * 9 + x) * C + seg * 8;
    }

    // ldmatrix lane geometry
    const int aRow = wm + (lane & 15);         // + 16*t
    const int aCol = (lane >> 4) * 8;          // + 16*s
    const int bRow = wn + (lane & 7) + ((lane >> 4) * 8);   // + 16 for second x4
    const int bCol = ((lane >> 3) & 1) * 8;    // + 16*s

    auto fill = [&](int q, __half* base) {
        int t = q / NCI;
        int ci = (q - t * NCI) * 32;
        int a3 = t / 3, b3 = t - 3 * a3;
        size_t tof = (size_t)(a3 * 9 + b3) * C + ci;
#pragma unroll
        for (int h = 0; h < 2; h++) {
            int r = r0 + 64 * h;
            cp_async16(smem_u32(&base[r * KCP + seg * 8]), A + abase[h] + tof);
        }
#pragma unroll
        for (int h = 0; h < 2; h++) {
            int row = r0 + 64 * h;
            size_t src = (size_t)(n0 + row) * K9 + t * C + ci + seg * 8;
            cp_async16(smem_u32(&base[MATH + row * KCP + seg * 8]), Wh + src);
        }
        asm volatile("cp.async.commit_group;" ::: "memory");
    };

    float acc[4][4][4];
#pragma unroll
    for (int t = 0; t < 4; t++)
#pragma unroll
        for (int u = 0; u < 4; u++)
#pragma unroll
            for (int e = 0; e < 4; e++) acc[t][u][e] = 0.f;

    fill(0, smem);

    for (int q = 0; q < NQ; q++) {
        if (q + 1 < NQ) {
            fill(q + 1, smem + ((q + 1) & 1) * BUFE);
            asm volatile("cp.async.wait_group 1;" ::: "memory");
        } else {
            asm volatile("cp.async.wait_group 0;" ::: "memory");
        }
        __syncthreads();

        __half* cur = smem + (q & 1) * BUFE;
        uint32_t aB = smem_u32(cur);
        uint32_t bB = aB + MATH * 2;    // bytes
#pragma unroll
        for (int s = 0; s < 2; s++) {
            uint32_t bregs[8];
            ldm_x4(bregs,     bB + (uint32_t)((bRow)      * KCP + 16 * s + bCol) * 2);
            ldm_x4(bregs + 4, bB + (uint32_t)((bRow + 16) * KCP + 16 * s + bCol) * 2);
#pragma unroll
            for (int t = 0; t < 4; t++) {
                uint32_t ar[4];
                ldm_x4(ar, aB + (uint32_t)((aRow + 16 * t) * KCP + 16 * s + aCol) * 2);
#pragma unroll
                for (int u = 0; u < 4; u++)
                    mma_f16(acc[t][u], ar, bregs + 2 * u);
            }
        }
        __syncthreads();
    }

    // ---- epilogue ----
#pragma unroll
    for (int t = 0; t < 4; t++) {
#pragma unroll
        for (int h = 0; h < 2; h++) {
            int row = m0 + wm + 16 * t + g + 8 * h;
            int n = row / 49, p = row - 49 * n;
            size_t base = (size_t)n * CH * 49 + p;
#pragma unroll
            for (int u = 0; u < 4; u++) {
                int col = n0 + wn + 8 * u + tg * 2;
                size_t i0 = base + (size_t)col * 49;
                float v0 = acc[t][u][2 * h];
                float v1 = acc[t][u][2 * h + 1];
                if (addsrc) { v0 += addsrc[i0]; v1 += addsrc[i0 + 49]; }
                out[i0] = v0;
                out[i0 + 49] = v1;
            }
        }
    }
}

// ---------------- q-conv (spatially-constant input), y = branch ----------
__global__ void q_conv2(const float* __restrict__ status, const float* __restrict__ rois,
                        const float* __restrict__ wq1, const float* __restrict__ wq2,
                        float* __restrict__ o1, float* __restrict__ o2) {
    int idx = blockIdx.x * 256 + threadIdx.x;
    if (idx >= NSAMP * CH * HW) return;
    int scol = blockIdx.y;
    const float* wq = scol ? wq2 : wq1;
    float* out = scol ? o2 : o1;
    int p = idx % HW;
    int t2 = idx / HW;
    int co = t2 % CH;
    int n = t2 / CH;
    int y = p / 7, x = p - (p / 7) * 7;
    float s[5];
    s[0] = status[n * 2 + scol];
    s[1] = rois[n * 5 + 1];
    s[2] = rois[n * 5 + 2];
    s[3] = rois[n * 5 + 3];
    s[4] = rois[n * 5 + 4];
    const float* w = wq + co * 45;
    float acc = 0.f;
#pragma unroll
    for (int ci = 0; ci < 5; ci++)
#pragma unroll
        for (int dy = 0; dy < 3; dy++)
#pragma unroll
            for (int dx = 0; dx < 3; dx++) {
                int yy = y + dy - 1, xx = x + dx - 1;
                if ((unsigned)yy < 7u && (unsigned)xx < 7u)
                    acc += w[ci * 9 + dy * 3 + dx] * s[ci];
            }
    out[idx] = acc;
}

// ---------------- attention per (hw, g), z = branch ----------------
#define CCH 256
__global__ void attn2(const float* __restrict__ q1, const float* __restrict__ k1,
                      const float* __restrict__ v1, float* __restrict__ w1,
                      const float* __restrict__ q2, const float* __restrict__ k2,
                      const float* __restrict__ v2, float* __restrict__ w2) {
    int hw = blockIdx.x;
    int gg = blockIdx.y;
    int br = blockIdx.z;
    const float* q = br ? q2 : q1;
    const float* k = br ? k2 : k1;
    const float* v = br ? v2 : v1;
    float* virt = br ? w2 : w1;

    __shared__ float bufA[GSZ][CCH + 1];
    __shared__ float bufB[GSZ][CCH + 1];
    __shared__ float att[GSZ][GSZ + 1];
    __shared__ float attn[GSZ][GSZ + 1];

    int tid = threadIdx.x;
    int i = tid >> 4, j = tid & 15;
    float a = 0.f;

    for (int c0 = 0; c0 < CH; c0 += CCH) {
        for (int e = tid; e < GSZ * CCH; e += 256) {
            int r = e >> 8, c = e & 255;
            int gidx = ((gg * GSZ + r) * CH + c0 + c) * HW + hw;
            bufA[r][c] = q[gidx];
            bufB[r][c] = k[gidx];
        }
        __syncthreads();
#pragma unroll 8
        for (int c = 0; c < CCH; c++)
            a += bufA[i][c] * bufB[j][c];
        __syncthreads();
    }
    att[i][j] = a * ATT_SCALE;
    __syncthreads();

    float mx = att[i][0];
#pragma unroll
    for (int jj = 1; jj < GSZ; jj++) mx = fmaxf(mx, att[i][jj]);
    float sum = 0.f;
#pragma unroll
    for (int jj = 0; jj < GSZ; jj++) sum += expf(att[i][jj] - mx);
    attn[i][j] = expf(att[i][j] - mx) / sum;
    __syncthreads();

    for (int c0 = 0; c0 < CH; c0 += CCH) {
        for (int e = tid; e < GSZ * CCH; e += 256) {
            int r = e >> 8, c = e & 255;
            bufA[r][c] = v[((gg * GSZ + r) * CH + c0 + c) * HW + hw];
        }
        __syncthreads();
        for (int e = tid; e < GSZ * CCH; e += 256) {
            int r = e >> 8, c = e & 255;
            float s = 0.f;
#pragma unroll
            for (int jj = 0; jj < GSZ; jj++) s += attn[r][jj] * bufA[jj][c];
            virt[((gg * GSZ + r) * CH + c0 + c) * HW + hw] = s;
        }
        __syncthreads();
    }
}

// ---------------- groupnorm stats, both branches ----------
__global__ void gn_stats2(const float* __restrict__ x1, const float* __restrict__ x2,
                          float* __restrict__ stats) {
    __shared__ float ss[256], sq[256];
    int blk = blockIdx.x;
    int br = blk >> 8, n = blk & 255;
    const float* p = (br ? x2 : x1) + (size_t)n * CH * HW;
    float a = 0.f, b = 0.f;
    for (int e = threadIdx.x; e < CH * HW; e += 256) {
        float v = p[e];
        a += v; b += v * v;
    }
    ss[threadIdx.x] = a; sq[threadIdx.x] = b;
    __syncthreads();
    for (int s = 128; s > 0; s >>= 1) {
        if (threadIdx.x < s) { ss[threadIdx.x] += ss[threadIdx.x + s]; sq[threadIdx.x] += sq[threadIdx.x + s]; }
        __syncthreads();
    }
    if (threadIdx.x == 0) {
        float m = ss[0] / (float)(CH * HW);
        float var = sq[0] / (float)(CH * HW) - m * m;
        stats[br * 512 + n] = m;
        stats[br * 512 + 256 + n] = rsqrtf(var + EPSG);
    }
}

// ---------------- launcher ----------------
extern "C" void kernel_launch(void* const* d_in, const int* in_sizes, int n_in,
                              void* d_out, int out_size) {
    const float* status = (const float*)d_in[0];
    const float* rois   = (const float*)d_in[1];
    const float* bbox   = (const float*)d_in[2];
    const float* wR     = (const float*)d_in[3];
    const float* wQ1    = (const float*)d_in[4];
    const float* wQ2    = (const float*)d_in[5];
    const float* wK1    = (const float*)d_in[6];
    const float* wV1    = (const float*)d_in[7];
    const float* wK2    = (const float*)d_in[8];
    const float* wV2    = (const float*)d_in[9];
    const float* wC1    = (const float*)d_in[10];
    const float* wC2    = (const float*)d_in[11];
    const float* gamma  = (const float*)d_in[12];
    const float* beta   = (const float*)d_in[13];
    float* out1 = (float*)d_out;
    float* out2 = out1 + FEAT_ELEMS;

    float *feat, *q1, *q2, *k1, *v1, *k2, *v2, *vir1, *vir2, *stats;
    cudaGetSymbolAddress((void**)&feat, g_feat);
    cudaGetSymbolAddress((void**)&q1,   g_q1);
    cudaGetSymbolAddress((void**)&q2,   g_q2);
    cudaGetSymbolAddress((void**)&k1,   g_k1);
    cudaGetSymbolAddress((void**)&v1,   g_v1);
    cudaGetSymbolAddress((void**)&k2,   g_k2);
    cudaGetSymbolAddress((void**)&v2,   g_v2);
    cudaGetSymbolAddress((void**)&vir1, g_vir1);
    cudaGetSymbolAddress((void**)&vir2, g_vir2);
    cudaGetSymbolAddress((void**)&stats, g_stats);

    __half *bpad, *fpad, *h1p, *h2p;
    cudaGetSymbolAddress((void**)&bpad, g_bpad);
    cudaGetSymbolAddress((void**)&fpad, g_fpad);
    cudaGetSymbolAddress((void**)&h1p,  g_h1pad);
    cudaGetSymbolAddress((void**)&h2p,  g_h2pad);

    __half *whR, *whK1, *whV1, *whK2, *whV2, *whC1, *whC2;
    cudaGetSymbolAddress((void**)&whR,  g_wR);
    cudaGetSymbolAddress((void**)&whK1, g_wK1);
    cudaGetSymbolAddress((void**)&whV1, g_wV1);
    cudaGetSymbolAddress((void**)&whK2, g_wK2);
    cudaGetSymbolAddress((void**)&whV2, g_wV2);
    cudaGetSymbolAddress((void**)&whC1, g_wC1);
    cudaGetSymbolAddress((void**)&whC2, g_wC2);

    cudaFuncSetAttribute(conv_mma, cudaFuncAttributeMaxDynamicSharedMemorySize, SMEM_BYTES);

    // weight reorder + fp16 round
    const int nR = K_RED * CH, nC = K_CC * CH;
    conv_w_reorder<<<(nR + 255) / 256, 256>>>(wR,  whR,  CIN, nR);
    conv_w_reorder<<<(nC + 255) / 256, 256>>>(wK1, whK1, CH,  nC);
    conv_w_reorder<<<(nC + 255) / 256, 256>>>(wV1, whV1, CH,  nC);
    conv_w_reorder<<<(nC + 255) / 256, 256>>>(wK2, whK2, CH,  nC);
    conv_w_reorder<<<(nC + 255) / 256, 256>>>(wV2, whV2, CH,  nC);
    conv_w_reorder<<<(nC + 255) / 256, 256>>>(wC1, whC1, CH,  nC);
    conv_w_reorder<<<(nC + 255) / 256, 256>>>(wC2, whC2, CH,  nC);

    // pad-convert bbox
    pad_convert<<<dim3(NSAMP, CIN / 64), 256>>>(bbox, bpad, CIN);

    // feat = conv(bbox_feat, w_reduce)
    {
        ConvBatch P = {};
        P.a[0] = bpad; P.wh[0] = whR; P.out[0] = feat;
        P.addsrc = nullptr;
        conv_mma<<<dim3(NSAMP * HW / 128, CH / 128, 1), 256, SMEM_BYTES>>>(P, CIN);
    }

    // q convs (spatially-constant input), both branches
    q_conv2<<<dim3((FEAT_ELEMS + 255) / 256, 2), 256>>>(status, rois, wQ1, wQ2, q1, q2);

    // pad-convert feat
    pad_convert<<<dim3(NSAMP, CH / 64), 256>>>(feat, fpad, CH);

    // k/v convs (4 fused)
    {
        ConvBatch P = {};
        for (int i = 0; i < 4; i++) P.a[i] = fpad;
        P.wh[0] = whK1; P.out[0] = k1;
        P.wh[1] = whV1; P.out[1] = v1;
        P.wh[2] = whK2; P.out[2] = k2;
        P.wh[3] = whV2; P.out[3] = v2;
        P.addsrc = nullptr;
        conv_mma<<<dim3(NSAMP * HW / 128, CH / 128, 4), 256, SMEM_BYTES>>>(P, CH);
    }

    // attention, both branches
    attn2<<<dim3(HW, NG, 2), 256>>>(q1, k1, v1, vir1, q2, k2, v2, vir2);

    // groupnorm stats, both branches
    gn_stats2<<<512, 256>>>(vir1, vir2, stats);

    // fused normalize+relu+pad-convert, both branches
    norm_relu_pad<<<dim3(NSAMP, CH / 64, 2), 256>>>(vir1, vir2, stats, gamma, beta, h1p, h2p);

    // out convs (2 fused): out = feat + conv(h, w_c)
    {
        ConvBatch P = {};
        P.a[0] = h1p; P.wh[0] = whC1; P.out[0] = out1;
        P.a[1] = h2p; P.wh[1] = whC2; P.out[1] = out2;
        P.addsrc = feat;
        conv_mma<<<dim3(NSAMP * HW / 128, CH / 128, 2), 256, SMEM_BYTES>>>(P, CH);
    }
}

// round 8
// speedup vs baseline: 6.9456x; 1.0432x over previous
#include <cuda_runtime.h>
#include <cuda_fp16.h>
#include <cstdint>
#include <math.h>

// ---------------- problem constants ----------------
#define NSAMP 256
#define CIN   2304
#define CH    512
#define HW    49
#define NG    16
#define GSZ   16
#define K_RED (CIN*9)    // 20736
#define K_CC  (CH*9)     // 4608
#define FEAT_ELEMS (NSAMP*CH*HW)   // 6422528
#define EPSG  1e-5f
#define ATT_SCALE 0.044194173824159216f  // 1/sqrt(512)

// ---------------- scratch (device globals; no allocation) ----------------
__device__ float g_feat [FEAT_ELEMS];
__device__ float g_q1   [FEAT_ELEMS];
__device__ float g_q2   [FEAT_ELEMS];
__device__ float g_k1   [FEAT_ELEMS];
__device__ float g_v1   [FEAT_ELEMS];
__device__ float g_k2   [FEAT_ELEMS];
__device__ float g_v2   [FEAT_ELEMS];
__device__ float g_vir1 [FEAT_ELEMS];
__device__ float g_vir2 [FEAT_ELEMS];
__device__ float g_stats[1024];

// padded channel-last activations: [n][81][C], fp16.
// Borders are NEVER written: __device__ globals are zero-initialized at module
// load, so the pad border stays zero forever (deterministic).
__device__ __align__(256) __half g_bpad [NSAMP*81*CIN];
__device__ __align__(256) __half g_fpad [NSAMP*81*CH];
__device__ __align__(256) __half g_h1pad[NSAMP*81*CH];
__device__ __align__(256) __half g_h2pad[NSAMP*81*CH];

// fp16 weights, tap-major layout [co][tap][ci]
__device__ __align__(256) __half g_wR [K_RED*CH];
__device__ __align__(256) __half g_wK1[K_CC*CH];
__device__ __align__(256) __half g_wV1[K_CC*CH];
__device__ __align__(256) __half g_wK2[K_CC*CH];
__device__ __align__(256) __half g_wV2[K_CC*CH];
__device__ __align__(256) __half g_wC1[K_CC*CH];
__device__ __align__(256) __half g_wC2[K_CC*CH];

// ---------------- helpers ----------------
__device__ __forceinline__ uint32_t smem_u32(const void* p) {
    uint32_t a;
    asm("{ .reg .u64 t; cvta.to.shared.u64 t, %1; cvt.u32.u64 %0, t; }" : "=r"(a) : "l"(p));
    return a;
}
__device__ __forceinline__ void cp_async16(uint32_t dst, const void* src) {
    asm volatile("cp.async.cg.shared.global [%0], [%1], 16;" :: "r"(dst), "l"(src));
}
__device__ __forceinline__ void ldm_x4(uint32_t* r, uint32_t addr) {
    asm volatile("ldmatrix.sync.aligned.m8n8.x4.shared.b16 {%0,%1,%2,%3}, [%4];"
        : "=r"(r[0]), "=r"(r[1]), "=r"(r[2]), "=r"(r[3]) : "r"(addr));
}
__device__ __forceinline__ void mma_f16(float* d, const uint32_t* a, const uint32_t* b) {
    asm volatile(
        "mma.sync.aligned.m16n8k16.row.col.f32.f16.f16.f32 "
        "{%0,%1,%2,%3}, {%4,%5,%6,%7}, {%8,%9}, {%0,%1,%2,%3};\n"
        : "+f"(d[0]), "+f"(d[1]), "+f"(d[2]), "+f"(d[3])
        : "r"(a[0]), "r"(a[1]), "r"(a[2]), "r"(a[3]), "r"(b[0]), "r"(b[1]));
}

// ---------------- weight reorder + fp16 round: w[co][ci*9+t] -> wh[co][t*C+ci] --
__global__ void conv_w_reorder(const float* __restrict__ w, __half* __restrict__ wh,
                               int C, int total) {
    int i = blockIdx.x * 256 + threadIdx.x;
    if (i >= total) return;
    int K9 = 9 * C;
    int co = i / K9, rem = i - co * K9;
    int t = rem / C, ci = rem - t * C;
    wh[i] = __float2half_rn(w[(size_t)co * K9 + ci * 9 + t]);
}

// ---------------- NCHW float -> padded channel-last fp16 (interior only) ------
__global__ void pad_convert(const float* __restrict__ src, __half* __restrict__ hi, int C) {
    int n = blockIdx.x, c0 = blockIdx.y * 64;
    __shared__ float tile[64][51];
    int tid = threadIdx.x;
    for (int e = tid; e < 64 * 49; e += 256) {
        int ci = e / 49, p = e - 49 * ci;
        tile[ci][p] = src[((size_t)n * C + c0 + ci) * 49 + p];
    }
    __syncthreads();
    for (int e = tid; e < 49 * 64; e += 256) {
        int p = e >> 6, ci = e & 63;
        int y = p / 7, x = p - 7 * y;
        int pp = (y + 1) * 9 + (x + 1);
        hi[((size_t)n * 81 + pp) * C + c0 + ci] = __float2half_rn(tile[ci][p]);
    }
}

// ---------------- fused GN-normalize + relu + pad-convert (interior only) -----
__global__ void norm_relu_pad(const float* __restrict__ x1, const float* __restrict__ x2,
                              const float* __restrict__ stats,
                              const float* __restrict__ gamma, const float* __restrict__ beta,
                              __half* __restrict__ h1, __half* __restrict__ h2) {
    int n = blockIdx.x, c0 = blockIdx.y * 64, br = blockIdx.z;
    const float* x = br ? x2 : x1;
    __half* hp = br ? h2 : h1;
    float mu = stats[br * 512 + n];
    float rs = stats[br * 512 + 256 + n];
    __shared__ float tile[64][51];
    int tid = threadIdx.x;
    for (int e = tid; e < 64 * 49; e += 256) {
        int ci = e / 49, p = e - 49 * ci;
        float v = x[((size_t)n * CH + c0 + ci) * 49 + p];
        tile[ci][p] = fmaxf((v - mu) * rs * gamma[c0 + ci] + beta[c0 + ci], 0.f);
    }
    __syncthreads();
    for (int e = tid; e < 49 * 64; e += 256) {
        int p = e >> 6, ci = e & 63;
        int y = p / 7, x9 = p - 7 * y;
        int pp = (y + 1) * 9 + (x9 + 1);
        hp[((size_t)n * 81 + pp) * CH + c0 + ci] = __float2half_rn(tile[ci][p]);
    }
}

// ---------------- batched HMMA conv: 9 shifted 1x1 GEMMs over padded input ----
// out[n,co,p] = sum_{t,ci} xpad[n, pp(p,t), ci] * wh[co, t*C+ci]   (fp16 x fp16, fp32 acc)
// CTA tile 128x128, 8 warps (2x4), warp tile 64x32, K chunk 32, 3-stage pipeline.
#define KCP  40                      // SMEM row stride (fp16 elems) = 80B
#define MATH (128*KCP)               // 5120 fp16 per matrix
#define BUFE (2*MATH)                // A, B
#define NSTG 3
#define SMEM_BYTES (NSTG*BUFE*2)     // 61440 bytes

struct ConvBatch {
    const __half* a[4];
    const __half* wh[4];
    float* out[4];
    __half* outpad[4];               // optional fp16 padded mirror (interior)
    const float* addsrc;
};

__global__ void __launch_bounds__(256, 2)
conv_mma(ConvBatch P, int C) {
    extern __shared__ __half smem[];
    const int K9 = 9 * C;
    const int NCI = C / 32;
    const int NQ = 9 * NCI;
    const int cv = blockIdx.z;
    const __half* __restrict__ A  = P.a[cv];
    const __half* __restrict__ Wh = P.wh[cv];
    float* __restrict__ out = P.out[cv];
    __half* outpad = P.outpad[cv];
    const float* addsrc = P.addsrc;

    const int tid = threadIdx.x;
    const int wid = tid >> 5, lane = tid & 31;
    const int g = lane >> 2, tg = lane & 3;
    const int m0 = blockIdx.x * 128;
    const int n0 = blockIdx.y * 128;
    const int wm = (wid & 1) * 64;
    const int wn = (wid >> 1) * 32;

    // fill geometry: thread serves rows r0 and r0+64, 16B segment `seg`
    const int seg = tid & 3;
    const int r0 = tid >> 2;          // 0..63
    size_t abase[2];
#pragma unroll
    for (int h = 0; h < 2; h++) {
        int m = m0 + r0 + 64 * h;
        int n = m / 49, p = m - 49 * n;
        int y = p / 7, x = p - 7 * y;
        abase[h] = ((size_t)n * 81 + y * 9 + x) * C + seg * 8;
    }

    // ldmatrix lane geometry
    const int aRow = wm + (lane & 15);         // + 16*t
    const int aCol = (lane >> 4) * 8;          // + 16*s
    const int bRow = wn + (lane & 7) + ((lane >> 4) * 8);   // + 16 for second x4
    const int bCol = ((lane >> 3) & 1) * 8;    // + 16*s

    auto fill = [&](int q) {
        __half* base = smem + (q % NSTG) * BUFE;
        int t = q / NCI;
        int ci = (q - t * NCI) * 32;
        int a3 = t / 3, b3 = t - 3 * a3;
        size_t tof = (size_t)(a3 * 9 + b3) * C + ci;
#pragma unroll
        for (int h = 0; h < 2; h++) {
            int r = r0 + 64 * h;
            cp_async16(smem_u32(&base[r * KCP + seg * 8]), A + abase[h] + tof);
        }
#pragma unroll
        for (int h = 0; h < 2; h++) {
            int row = r0 + 64 * h;
            size_t src = (size_t)(n0 + row) * K9 + t * C + ci + seg * 8;
            cp_async16(smem_u32(&base[MATH + row * KCP + seg * 8]), Wh + src);
        }
        asm volatile("cp.async.commit_group;" ::: "memory");
    };

    float acc[4][4][4];
#pragma unroll
    for (int t = 0; t < 4; t++)
#pragma unroll
        for (int u = 0; u < 4; u++)
#pragma unroll
            for (int e = 0; e < 4; e++) acc[t][u][e] = 0.f;

    // 3-stage pipeline prologue: two fills in flight
    fill(0);
    fill(1);

    for (int q = 0; q < NQ; q++) {
        if (q + 1 < NQ) {
            asm volatile("cp.async.wait_group 1;" ::: "memory");
        } else {
            asm volatile("cp.async.wait_group 0;" ::: "memory");
        }
        __syncthreads();   // all threads see buf q; all warps done with buf q-1
        if (q + 2 < NQ) fill(q + 2);

        __half* cur = smem + (q % NSTG) * BUFE;
        uint32_t aB = smem_u32(cur);
        uint32_t bB = aB + MATH * 2;    // bytes
#pragma unroll
        for (int s = 0; s < 2; s++) {
            uint32_t bregs[8];
            ldm_x4(bregs,     bB + (uint32_t)((bRow)      * KCP + 16 * s + bCol) * 2);
            ldm_x4(bregs + 4, bB + (uint32_t)((bRow + 16) * KCP + 16 * s + bCol) * 2);
#pragma unroll
            for (int t = 0; t < 4; t++) {
                uint32_t ar[4];
                ldm_x4(ar, aB + (uint32_t)((aRow + 16 * t) * KCP + 16 * s + aCol) * 2);
#pragma unroll
                for (int u = 0; u < 4; u++)
                    mma_f16(acc[t][u], ar, bregs + 2 * u);
            }
        }
    }

    // ---- epilogue ----
#pragma unroll
    for (int t = 0; t < 4; t++) {
#pragma unroll
        for (int h = 0; h < 2; h++) {
            int row = m0 + wm + 16 * t + g + 8 * h;
            int n = row / 49, p = row - 49 * n;
            int y = p / 7, x = p - 7 * y;
            size_t base = (size_t)n * CH * 49 + p;
            size_t pbase = ((size_t)n * 81 + (y + 1) * 9 + (x + 1)) * CH;
#pragma unroll
            for (int u = 0; u < 4; u++) {
                int col = n0 + wn + 8 * u + tg * 2;
                size_t i0 = base + (size_t)col * 49;
                float v0 = acc[t][u][2 * h];
                float v1 = acc[t][u][2 * h + 1];
                if (addsrc) { v0 += addsrc[i0]; v1 += addsrc[i0 + 49]; }
                out[i0] = v0;
                out[i0 + 49] = v1;
                if (outpad) {
                    __half2 hv = __floats2half2_rn(v0, v1);
                    *reinterpret_cast<__half2*>(&outpad[pbase + col]) = hv;
                }
            }
        }
    }
}

// ---------------- q-conv (spatially-constant input), y = branch ----------
__global__ void q_conv2(const float* __restrict__ status, const float* __restrict__ rois,
                        const float* __restrict__ wq1, const float* __restrict__ wq2,
                        float* __restrict__ o1, float* __restrict__ o2) {
    int idx = blockIdx.x * 256 + threadIdx.x;
    if (idx >= NSAMP * CH * HW) return;
    int scol = blockIdx.y;
    const float* wq = scol ? wq2 : wq1;
    float* out = scol ? o2 : o1;
    int p = idx % HW;
    int t2 = idx / HW;
    int co = t2 % CH;
    int n = t2 / CH;
    int y = p / 7, x = p - (p / 7) * 7;
    float s[5];
    s[0] = status[n * 2 + scol];
    s[1] = rois[n * 5 + 1];
    s[2] = rois[n * 5 + 2];
    s[3] = rois[n * 5 + 3];
    s[4] = rois[n * 5 + 4];
    const float* w = wq + co * 45;
    float acc = 0.f;
#pragma unroll
    for (int ci = 0; ci < 5; ci++)
#pragma unroll
        for (int dy = 0; dy < 3; dy++)
#pragma unroll
            for (int dx = 0; dx < 3; dx++) {
                int yy = y + dy - 1, xx = x + dx - 1;
                if ((unsigned)yy < 7u && (unsigned)xx < 7u)
                    acc += w[ci * 9 + dy * 3 + dx] * s[ci];
            }
    out[idx] = acc;
}

// ---------------- attention per (hw, g), z = branch ----------------
#define CCH 256
__global__ void attn2(const float* __restrict__ q1, const float* __restrict__ k1,
                      const float* __restrict__ v1, float* __restrict__ w1,
                      const float* __restrict__ q2, const float* __restrict__ k2,
                      const float* __restrict__ v2, float* __restrict__ w2) {
    int hw = blockIdx.x;
    int gg = blockIdx.y;
    int br = blockIdx.z;
    const float* q = br ? q2 : q1;
    const float* k = br ? k2 : k1;
    const float* v = br ? v2 : v1;
    float* virt = br ? w2 : w1;

    __shared__ float bufA[GSZ][CCH + 1];
    __shared__ float bufB[GSZ][CCH + 1];
    __shared__ float att[GSZ][GSZ + 1];
    __shared__ float attn[GSZ][GSZ + 1];

    int tid = threadIdx.x;
    int i = tid >> 4, j = tid & 15;
    float a = 0.f;

    for (int c0 = 0; c0 < CH; c0 += CCH) {
        for (int e = tid; e < GSZ * CCH; e += 256) {
            int r = e >> 8, c = e & 255;
            int gidx = ((gg * GSZ + r) * CH + c0 + c) * HW + hw;
            bufA[r][c] = q[gidx];
            bufB[r][c] = k[gidx];
        }
        __syncthreads();
#pragma unroll 8
        for (int c = 0; c < CCH; c++)
            a += bufA[i][c] * bufB[j][c];
        __syncthreads();
    }
    att[i][j] = a * ATT_SCALE;
    __syncthreads();

    float mx = att[i][0];
#pragma unroll
    for (int jj = 1; jj < GSZ; jj++) mx = fmaxf(mx, att[i][jj]);
    float sum = 0.f;
#pragma unroll
    for (int jj = 0; jj < GSZ; jj++) sum += expf(att[i][jj] - mx);
    attn[i][j] = expf(att[i][j] - mx) / sum;
    __syncthreads();

    for (int c0 = 0; c0 < CH; c0 += CCH) {
        for (int e = tid; e < GSZ * CCH; e += 256) {
            int r = e >> 8, c = e & 255;
            bufA[r][c] = v[((gg * GSZ + r) * CH + c0 + c) * HW + hw];
        }
        __syncthreads();
        for (int e = tid; e < GSZ * CCH; e += 256) {
            int r = e >> 8, c = e & 255;
            float s = 0.f;
#pragma unroll
            for (int jj = 0; jj < GSZ; jj++) s += attn[r][jj] * bufA[jj][c];
            virt[((gg * GSZ + r) * CH + c0 + c) * HW + hw] = s;
        }
        __syncthreads();
    }
}

// ---------------- groupnorm stats, both branches ----------
__global__ void gn_stats2(const float* __restrict__ x1, const float* __restrict__ x2,
                          float* __restrict__ stats) {
    __shared__ float ss[256], sq[256];
    int blk = blockIdx.x;
    int br = blk >> 8, n = blk & 255;
    const float* p = (br ? x2 : x1) + (size_t)n * CH * HW;
    float a = 0.f, b = 0.f;
    for (int e = threadIdx.x; e < CH * HW; e += 256) {
        float v = p[e];
        a += v; b += v * v;
    }
    ss[threadIdx.x] = a; sq[threadIdx.x] = b;
    __syncthreads();
    for (int s = 128; s > 0; s >>= 1) {
        if (threadIdx.x < s) { ss[threadIdx.x] += ss[threadIdx.x + s]; sq[threadIdx.x] += sq[threadIdx.x + s]; }
        __syncthreads();
    }
    if (threadIdx.x == 0) {
        float m = ss[0] / (float)(CH * HW);
        float var = sq[0] / (float)(CH * HW) - m * m;
        stats[br * 512 + n] = m;
        stats[br * 512 + 256 + n] = rsqrtf(var + EPSG);
    }
}

// ---------------- launcher ----------------
extern "C" void kernel_launch(void* const* d_in, const int* in_sizes, int n_in,
                              void* d_out, int out_size) {
    const float* status = (const float*)d_in[0];
    const float* rois   = (const float*)d_in[1];
    const float* bbox   = (const float*)d_in[2];
    const float* wR     = (const float*)d_in[3];
    const float* wQ1    = (const float*)d_in[4];
    const float* wQ2    = (const float*)d_in[5];
    const float* wK1    = (const float*)d_in[6];
    const float* wV1    = (const float*)d_in[7];
    const float* wK2    = (const float*)d_in[8];
    const float* wV2    = (const float*)d_in[9];
    const float* wC1    = (const float*)d_in[10];
    const float* wC2    = (const float*)d_in[11];
    const float* gamma  = (const float*)d_in[12];
    const float* beta   = (const float*)d_in[13];
    float* out1 = (float*)d_out;
    float* out2 = out1 + FEAT_ELEMS;

    float *feat, *q1, *q2, *k1, *v1, *k2, *v2, *vir1, *vir2, *stats;
    cudaGetSymbolAddress((void**)&feat, g_feat);
    cudaGetSymbolAddress((void**)&q1,   g_q1);
    cudaGetSymbolAddress((void**)&q2,   g_q2);
    cudaGetSymbolAddress((void**)&k1,   g_k1);
    cudaGetSymbolAddress((void**)&v1,   g_v1);
    cudaGetSymbolAddress((void**)&k2,   g_k2);
    cudaGetSymbolAddress((void**)&v2,   g_v2);
    cudaGetSymbolAddress((void**)&vir1, g_vir1);
    cudaGetSymbolAddress((void**)&vir2, g_vir2);
    cudaGetSymbolAddress((void**)&stats, g_stats);

    __half *bpad, *fpad, *h1p, *h2p;
    cudaGetSymbolAddress((void**)&bpad, g_bpad);
    cudaGetSymbolAddress((void**)&fpad, g_fpad);
    cudaGetSymbolAddress((void**)&h1p,  g_h1pad);
    cudaGetSymbolAddress((void**)&h2p,  g_h2pad);

    __half *whR, *whK1, *whV1, *whK2, *whV2, *whC1, *whC2;
    cudaGetSymbolAddress((void**)&whR,  g_wR);
    cudaGetSymbolAddress((void**)&whK1, g_wK1);
    cudaGetSymbolAddress((void**)&whV1, g_wV1);
    cudaGetSymbolAddress((void**)&whK2, g_wK2);
    cudaGetSymbolAddress((void**)&whV2, g_wV2);
    cudaGetSymbolAddress((void**)&whC1, g_wC1);
    cudaGetSymbolAddress((void**)&whC2, g_wC2);

    cudaFuncSetAttribute(conv_mma, cudaFuncAttributeMaxDynamicSharedMemorySize, SMEM_BYTES);

    // weight reorder + fp16 round
    const int nR = K_RED * CH, nC = K_CC * CH;
    conv_w_reorder<<<(nR + 255) / 256, 256>>>(wR,  whR,  CIN, nR);
    conv_w_reorder<<<(nC + 255) / 256, 256>>>(wK1, whK1, CH,  nC);
    conv_w_reorder<<<(nC + 255) / 256, 256>>>(wV1, whV1, CH,  nC);
    conv_w_reorder<<<(nC + 255) / 256, 256>>>(wK2, whK2, CH,  nC);
    conv_w_reorder<<<(nC + 255) / 256, 256>>>(wV2, whV2, CH,  nC);
    conv_w_reorder<<<(nC + 255) / 256, 256>>>(wC1, whC1, CH,  nC);
    conv_w_reorder<<<(nC + 255) / 256, 256>>>(wC2, whC2, CH,  nC);

    // pad-convert bbox
    pad_convert<<<dim3(NSAMP, CIN / 64), 256>>>(bbox, bpad, CIN);

    // feat = conv(bbox_feat, w_reduce); epilogue also emits fpad (fp16 padded)
    {
        ConvBatch P = {};
        P.a[0] = bpad; P.wh[0] = whR; P.out[0] = feat; P.outpad[0] = fpad;
        P.addsrc = nullptr;
        conv_mma<<<dim3(NSAMP * HW / 128, CH / 128, 1), 256, SMEM_BYTES>>>(P, CIN);
    }

    // q convs (spatially-constant input), both branches
    q_conv2<<<dim3((FEAT_ELEMS + 255) / 256, 2), 256>>>(status, rois, wQ1, wQ2, q1, q2);

    // k/v convs (4 fused)
    {
        ConvBatch P = {};
        for (int i = 0; i < 4; i++) P.a[i] = fpad;
        P.wh[0] = whK1; P.out[0] = k1;
        P.wh[1] = whV1; P.out[1] = v1;
        P.wh[2] = whK2; P.out[2] = k2;
        P.wh[3] = whV2; P.out[3] = v2;
        P.addsrc = nullptr;
        conv_mma<<<dim3(NSAMP * HW / 128, CH / 128, 4), 256, SMEM_BYTES>>>(P, CH);
    }

    // attention, both branches
    attn2<<<dim3(HW, NG, 2), 256>>>(q1, k1, v1, vir1, q2, k2, v2, vir2);

    // groupnorm stats, both branches
    gn_stats2<<<512, 256>>>(vir1, vir2, stats);

    // fused normalize+relu+pad-convert, both branches
    norm_relu_pad<<<dim3(NSAMP, CH / 64, 2), 256>>>(vir1, vir2, stats, gamma, beta, h1p, h2p);

    // out convs (2 fused): out = feat + conv(h, w_c)
    {
        ConvBatch P = {};
        P.a[0] = h1p; P.wh[0] = whC1; P.out[0] = out1;
        P.a[1] = h2p; P.wh[1] = whC2; P.out[1] = out2;
        P.addsrc = feat;
        conv_mma<<<dim3(NSAMP * HW / 128, CH / 128, 2), 256, SMEM_BYTES>>>(P, CH);
    }
}

// round 9
// speedup vs baseline: 7.3003x; 1.0511x over previous
#include <cuda_runtime.h>
#include <cuda_fp16.h>
#include <cstdint>
#include <math.h>

// ---------------- problem constants ----------------
#define NSAMP 256
#define CIN   2304
#define CH    512
#define HW    49
#define NG    16
#define GSZ   16
#define K_RED (CIN*9)    // 20736
#define K_CC  (CH*9)     // 4608
#define FEAT_ELEMS (NSAMP*CH*HW)   // 6422528
#define EPSG  1e-5f
#define ATT_SCALE 0.044194173824159216f  // 1/sqrt(512)

// ---------------- scratch (device globals; no allocation) ----------------
__device__ float g_feat [FEAT_ELEMS];
__device__ float g_q1   [FEAT_ELEMS];
__device__ float g_q2   [FEAT_ELEMS];
__device__ float g_k1   [FEAT_ELEMS];   // also reduce-conv partial 0
__device__ float g_v1   [FEAT_ELEMS];   // also reduce-conv partial 1
__device__ float g_k2   [FEAT_ELEMS];   // also reduce-conv partial 2
__device__ float g_v2   [FEAT_ELEMS];
__device__ float g_vir1 [FEAT_ELEMS];
__device__ float g_vir2 [FEAT_ELEMS];
__device__ float g_stats[1024];
__device__ float g_wq[2*9*512*5];       // q-conv collapsed weights

// padded channel-last activations: [n][81][C], fp16.
// Borders are NEVER written: __device__ globals are zero-initialized at module
// load, so the pad border stays zero forever (deterministic).
__device__ __align__(256) __half g_bpad [NSAMP*81*CIN];
__device__ __align__(256) __half g_fpad [NSAMP*81*CH];
__device__ __align__(256) __half g_h1pad[NSAMP*81*CH];
__device__ __align__(256) __half g_h2pad[NSAMP*81*CH];

// fp16 weights, tap-major layout [co][tap][ci]
__device__ __align__(256) __half g_wR [K_RED*CH];
__device__ __align__(256) __half g_wK1[K_CC*CH];
__device__ __align__(256) __half g_wV1[K_CC*CH];
__device__ __align__(256) __half g_wK2[K_CC*CH];
__device__ __align__(256) __half g_wV2[K_CC*CH];
__device__ __align__(256) __half g_wC1[K_CC*CH];
__device__ __align__(256) __half g_wC2[K_CC*CH];

// ---------------- helpers ----------------
__device__ __forceinline__ uint32_t smem_u32(const void* p) {
    uint32_t a;
    asm("{ .reg .u64 t; cvta.to.shared.u64 t, %1; cvt.u32.u64 %0, t; }" : "=r"(a) : "l"(p));
    return a;
}
__device__ __forceinline__ void cp_async16(uint32_t dst, const void* src) {
    asm volatile("cp.async.cg.shared.global [%0], [%1], 16;" :: "r"(dst), "l"(src));
}
__device__ __forceinline__ void ldm_x4(uint32_t* r, uint32_t addr) {
    asm volatile("ldmatrix.sync.aligned.m8n8.x4.shared.b16 {%0,%1,%2,%3}, [%4];"
        : "=r"(r[0]), "=r"(r[1]), "=r"(r[2]), "=r"(r[3]) : "r"(addr));
}
__device__ __forceinline__ void mma_f16(float* d, const uint32_t* a, const uint32_t* b) {
    asm volatile(
        "mma.sync.aligned.m16n8k16.row.col.f32.f16.f16.f32 "
        "{%0,%1,%2,%3}, {%4,%5,%6,%7}, {%8,%9}, {%0,%1,%2,%3};\n"
        : "+f"(d[0]), "+f"(d[1]), "+f"(d[2]), "+f"(d[3])
        : "r"(a[0]), "r"(a[1]), "r"(a[2]), "r"(a[3]), "r"(b[0]), "r"(b[1]));
}

// ---------------- merged weight reorder + fp16 round (all 7 weights) ---------
// w[co][ci*9+t] -> wh[co][t*C+ci]
struct WReorder {
    const float* src[7];
    __half* dst[7];
    int C[7];
    int base[8];      // prefix sums of element counts
};
__global__ void conv_w_reorder_all(WReorder R, int total) {
    int i = blockIdx.x * 256 + threadIdx.x;
    if (i >= total) return;
    int s = 0;
#pragma unroll
    for (int k = 0; k < 6; k++) if (i >= R.base[k + 1]) s = k + 1;
    int j = i - R.base[s];
    int C = R.C[s];
    int K9 = 9 * C;
    int co = j / K9, rem = j - co * K9;
    int t = rem / C, ci = rem - t * C;
    R.dst[s][j] = __float2half_rn(R.src[s][(size_t)co * K9 + ci * 9 + t]);
}

// ---------------- q-conv weight collapse: Wq[br][cls][co][ci] ----------------
__global__ void qw_prep(const float* __restrict__ wq1, const float* __restrict__ wq2,
                        float* __restrict__ Wq) {
    int i = blockIdx.x * 256 + threadIdx.x;
    if (i >= 2 * 9 * 512) return;
    int br = i / (9 * 512);
    int rem = i - br * 9 * 512;
    int cls = rem / 512, co = rem - cls * 512;
    int cy = cls / 3, cx = cls - 3 * cy;
    const float* w = (br ? wq2 : wq1) + co * 45;
#pragma unroll
    for (int ci = 0; ci < 5; ci++) {
        float s = 0.f;
#pragma unroll
        for (int dy = 0; dy < 3; dy++) {
            if (cy == 0 && dy == 0) continue;
            if (cy == 2 && dy == 2) continue;
#pragma unroll
            for (int dx = 0; dx < 3; dx++) {
                if (cx == 0 && dx == 0) continue;
                if (cx == 2 && dx == 2) continue;
                s += w[ci * 9 + dy * 3 + dx];
            }
        }
        Wq[((br * 9 + cls) * 512 + co) * 5 + ci] = s;
    }
}

// ---------------- NCHW float -> padded channel-last fp16 (interior only) ------
__global__ void pad_convert(const float* __restrict__ src, __half* __restrict__ hi, int C) {
    int n = blockIdx.x, c0 = blockIdx.y * 64;
    __shared__ float tile[64][51];
    int tid = threadIdx.x;
    for (int e = tid; e < 64 * 49; e += 256) {
        int ci = e / 49, p = e - 49 * ci;
        tile[ci][p] = src[((size_t)n * C + c0 + ci) * 49 + p];
    }
    __syncthreads();
    for (int e = tid; e < 49 * 64; e += 256) {
        int p = e >> 6, ci = e & 63;
        int y = p / 7, x = p - 7 * y;
        hi[((size_t)n * 81 + (y + 1) * 9 + (x + 1)) * C + c0 + ci] =
            __float2half_rn(tile[ci][p]);
    }
}

// ---------------- combine 3 split-K partials -> feat (float) + fpad (fp16) ----
__global__ void combine3_pad(const float* __restrict__ p0, const float* __restrict__ p1,
                             const float* __restrict__ p2,
                             float* __restrict__ feat, __half* __restrict__ fpad) {
    int n = blockIdx.x, c0 = blockIdx.y * 64;
    __shared__ float tile[64][51];
    int tid = threadIdx.x;
    for (int e = tid; e < 64 * 49; e += 256) {
        int ci = e / 49, p = e - 49 * ci;
        size_t idx = ((size_t)n * CH + c0 + ci) * 49 + p;
        float v = p0[idx] + p1[idx] + p2[idx];
        feat[idx] = v;
        tile[ci][p] = v;
    }
    __syncthreads();
    for (int e = tid; e < 49 * 64; e += 256) {
        int p = e >> 6, ci = e & 63;
        int y = p / 7, x = p - 7 * y;
        fpad[((size_t)n * 81 + (y + 1) * 9 + (x + 1)) * CH + c0 + ci] =
            __float2half_rn(tile[ci][p]);
    }
}

// ---------------- fused GN-normalize + relu + pad-convert (interior only) -----
__global__ void norm_relu_pad(const float* __restrict__ x1, const float* __restrict__ x2,
                              const float* __restrict__ stats,
                              const float* __restrict__ gamma, const float* __restrict__ beta,
                              __half* __restrict__ h1, __half* __restrict__ h2) {
    int n = blockIdx.x, c0 = blockIdx.y * 64, br = blockIdx.z;
    const float* x = br ? x2 : x1;
    __half* hp = br ? h2 : h1;
    float mu = stats[br * 512 + n];
    float rs = stats[br * 512 + 256 + n];
    __shared__ float tile[64][51];
    int tid = threadIdx.x;
    for (int e = tid; e < 64 * 49; e += 256) {
        int ci = e / 49, p = e - 49 * ci;
        float v = x[((size_t)n * CH + c0 + ci) * 49 + p];
        tile[ci][p] = fmaxf((v - mu) * rs * gamma[c0 + ci] + beta[c0 + ci], 0.f);
    }
    __syncthreads();
    for (int e = tid; e < 49 * 64; e += 256) {
        int p = e >> 6, ci = e & 63;
        int y = p / 7, x9 = p - 7 * y;
        hp[((size_t)n * 81 + (y + 1) * 9 + (x9 + 1)) * CH + c0 + ci] =
            __float2half_rn(tile[ci][p]);
    }
}

// ---------------- batched HMMA conv: shifted 1x1 GEMMs over padded input ------
// out[n,co,p] = sum_{t in [tap0,tap0+ntap), ci} xpad[n, pp(p,t), ci] * wh[co, t*C+ci]
// CTA tile 128x128, 8 warps (2x4), warp tile 64x32, K chunk 32, 4-stage pipeline.
#define KCP  40                      // SMEM row stride (fp16 elems) = 80B
#define MATH (128*KCP)               // 5120 fp16 per matrix
#define BUFE (2*MATH)                // A, B
#define NSTG 4
#define SMEM_BYTES (NSTG*BUFE*2)     // 81920 bytes

struct ConvBatch {
    const __half* a[4];
    const __half* wh[4];
    float* out[4];
    const float* addsrc;
    int tap0[4];
};

__global__ void __launch_bounds__(256, 2)
conv_mma(ConvBatch P, int C, int ntap) {
    extern __shared__ __half smem[];
    const int K9 = 9 * C;
    const int NCI = C / 32;
    const int NQ = ntap * NCI;
    const int cv = blockIdx.z;
    const __half* __restrict__ A  = P.a[cv];
    const __half* __restrict__ Wh = P.wh[cv];
    float* __restrict__ out = P.out[cv];
    const float* addsrc = P.addsrc;
    const int tap0 = P.tap0[cv];

    const int tid = threadIdx.x;
    const int wid = tid >> 5, lane = tid & 31;
    const int g = lane >> 2, tg = lane & 3;
    const int m0 = blockIdx.x * 128;
    const int n0 = blockIdx.y * 128;
    const int wm = (wid & 1) * 64;
    const int wn = (wid >> 1) * 32;

    // fill geometry: thread serves rows r0 and r0+64, 16B segment `seg`
    const int seg = tid & 3;
    const int r0 = tid >> 2;          // 0..63
    size_t abase[2];
#pragma unroll
    for (int h = 0; h < 2; h++) {
        int m = m0 + r0 + 64 * h;
        int n = m / 49, p = m - 49 * n;
        int y = p / 7, x = p - 7 * y;
        abase[h] = ((size_t)n * 81 + y * 9 + x) * C + seg * 8;
    }

    // ldmatrix lane geometry
    const int aRow = wm + (lane & 15);         // + 16*t
    const int aCol = (lane >> 4) * 8;          // + 16*s
    const int bRow = wn + (lane & 7) + ((lane >> 4) * 8);   // + 16 for second x4
    const int bCol = ((lane >> 3) & 1) * 8;    // + 16*s

    auto fill = [&](int q) {
        __half* base = smem + (q % NSTG) * BUFE;
        int t = tap0 + q / NCI;
        int ci = (q % NCI) * 32;
        int a3 = t / 3, b3 = t - 3 * a3;
        size_t tof = (size_t)(a3 * 9 + b3) * C + ci;
#pragma unroll
        for (int h = 0; h < 2; h++) {
            int r = r0 + 64 * h;
            cp_async16(smem_u32(&base[r * KCP + seg * 8]), A + abase[h] + tof);
        }
#pragma unroll
        for (int h = 0; h < 2; h++) {
            int row = r0 + 64 * h;
            size_t src = (size_t)(n0 + row) * K9 + t * C + ci + seg * 8;
            cp_async16(smem_u32(&base[MATH + row * KCP + seg * 8]), Wh + src);
        }
        asm volatile("cp.async.commit_group;" ::: "memory");
    };

    float acc[4][4][4];
#pragma unroll
    for (int t = 0; t < 4; t++)
#pragma unroll
        for (int u = 0; u < 4; u++)
#pragma unroll
            for (int e = 0; e < 4; e++) acc[t][u][e] = 0.f;

    // 4-stage pipeline prologue: three fills in flight
    fill(0);
    fill(1);
    fill(2);

    for (int q = 0; q < NQ; q++) {
        int pend = NQ - 1 - q;
        if (pend >= 3) pend = 2;          // at most NSTG-2 allowed pending
        if (pend == 2)      asm volatile("cp.async.wait_group 2;" ::: "memory");
        else if (pend == 1) asm volatile("cp.async.wait_group 1;" ::: "memory");
        else                asm volatile("cp.async.wait_group 0;" ::: "memory");
        __syncthreads();   // all threads see buf q; all warps done with buf q-1
        if (q + 3 < NQ) fill(q + 3);

        __half* cur = smem + (q % NSTG) * BUFE;
        uint32_t aB = smem_u32(cur);
        uint32_t bB = aB + MATH * 2;    // bytes
#pragma unroll
        for (int s = 0; s < 2; s++) {
            uint32_t bregs[8];
            ldm_x4(bregs,     bB + (uint32_t)((bRow)      * KCP + 16 * s + bCol) * 2);
            ldm_x4(bregs + 4, bB + (uint32_t)((bRow + 16) * KCP + 16 * s + bCol) * 2);
#pragma unroll
            for (int t = 0; t < 4; t++) {
                uint32_t ar[4];
                ldm_x4(ar, aB + (uint32_t)((aRow + 16 * t) * KCP + 16 * s + aCol) * 2);
#pragma unroll
                for (int u = 0; u < 4; u++)
                    mma_f16(acc[t][u], ar, bregs + 2 * u);
            }
        }
    }

    // ---- epilogue ----
#pragma unroll
    for (int t = 0; t < 4; t++) {
#pragma unroll
        for (int h = 0; h < 2; h++) {
            int row = m0 + wm + 16 * t + g + 8 * h;
            int n = row / 49, p = row - 49 * n;
            size_t base = (size_t)n * CH * 49 + p;
#pragma unroll
            for (int u = 0; u < 4; u++) {
                int col = n0 + wn + 8 * u + tg * 2;
                size_t i0 = base + (size_t)col * 49;
                float v0 = acc[t][u][2 * h];
                float v1 = acc[t][u][2 * h + 1];
                if (addsrc) { v0 += addsrc[i0]; v1 += addsrc[i0 + 49]; }
                out[i0] = v0;
                out[i0 + 49] = v1;
            }
        }
    }
}

// ---------------- q-conv via collapsed weights, y = branch ----------
__global__ void q_conv2b(const float* __restrict__ status, const float* __restrict__ rois,
                         const float* __restrict__ Wq,
                         float* __restrict__ o1, float* __restrict__ o2) {
    int idx = blockIdx.x * 256 + threadIdx.x;
    if (idx >= NSAMP * CH * HW) return;
    int br = blockIdx.y;
    float* out = br ? o2 : o1;
    int p = idx % HW;
    int t2 = idx / HW;
    int co = t2 % CH;
    int n = t2 / CH;
    int y = p / 7, x = p - 7 * y;
    int cy = (y == 0) ? 0 : ((y == 6) ? 2 : 1);
    int cx = (x == 0) ? 0 : ((x == 6) ? 2 : 1);
    const float* wq = Wq + (((size_t)br * 9 + cy * 3 + cx) * 512 + co) * 5;
    float acc = wq[0] * status[n * 2 + br]
              + wq[1] * rois[n * 5 + 1] + wq[2] * rois[n * 5 + 2]
              + wq[3] * rois[n * 5 + 3] + wq[4] * rois[n * 5 + 4];
    out[idx] = acc;
}

// ---------------- attention per (hw, g), z = branch ----------------
#define CCH 256
__global__ void attn2(const float* __restrict__ q1, const float* __restrict__ k1,
                      const float* __restrict__ v1, float* __restrict__ w1,
                      const float* __restrict__ q2, const float* __restrict__ k2,
                      const float* __restrict__ v2, float* __restrict__ w2) {
    int hw = blockIdx.x;
    int gg = blockIdx.y;
    int br = blockIdx.z;
    const float* q = br ? q2 : q1;
    const float* k = br ? k2 : k1;
    const float* v = br ? v2 : v1;
    float* virt = br ? w2 : w1;

    __shared__ float bufA[GSZ][CCH + 1];
    __shared__ float bufB[GSZ][CCH + 1];
    __shared__ float att[GSZ][GSZ + 1];
    __shared__ float attn[GSZ][GSZ + 1];

    int tid = threadIdx.x;
    int i = tid >> 4, j = tid & 15;
    float a = 0.f;

    for (int c0 = 0; c0 < CH; c0 += CCH) {
        for (int e = tid; e < GSZ * CCH; e += 256) {
            int r = e >> 8, c = e & 255;
            int gidx = ((gg * GSZ + r) * CH + c0 + c) * HW + hw;
            bufA[r][c] = q[gidx];
            bufB[r][c] = k[gidx];
        }
        __syncthreads();
#pragma unroll 8
        for (int c = 0; c < CCH; c++)
            a += bufA[i][c] * bufB[j][c];
        __syncthreads();
    }
    att[i][j] = a * ATT_SCALE;
    __syncthreads();

    float mx = att[i][0];
#pragma unroll
    for (int jj = 1; jj < GSZ; jj++) mx = fmaxf(mx, att[i][jj]);
    float sum = 0.f;
#pragma unroll
    for (int jj = 0; jj < GSZ; jj++) sum += expf(att[i][jj] - mx);
    attn[i][j] = expf(att[i][j] - mx) / sum;
    __syncthreads();

    for (int c0 = 0; c0 < CH; c0 += CCH) {
        for (int e = tid; e < GSZ * CCH; e += 256) {
            int r = e >> 8, c = e & 255;
            bufA[r][c] = v[((gg * GSZ + r) * CH + c0 + c) * HW + hw];
        }
        __syncthreads();
        for (int e = tid; e < GSZ * CCH; e += 256) {
            int r = e >> 8, c = e & 255;
            float s = 0.f;
#pragma unroll
            for (int jj = 0; jj < GSZ; jj++) s += attn[r][jj] * bufA[jj][c];
            virt[((gg * GSZ + r) * CH + c0 + c) * HW + hw] = s;
        }
        __syncthreads();
    }
}

// ---------------- groupnorm stats, both branches ----------
__global__ void gn_stats2(const float* __restrict__ x1, const float* __restrict__ x2,
                          float* __restrict__ stats) {
    __shared__ float ss[256], sq[256];
    int blk = blockIdx.x;
    int br = blk >> 8, n = blk & 255;
    const float* p = (br ? x2 : x1) + (size_t)n * CH * HW;
    float a = 0.f, b = 0.f;
    for (int e = threadIdx.x; e < CH * HW; e += 256) {
        float v = p[e];
        a += v; b += v * v;
    }
    ss[threadIdx.x] = a; sq[threadIdx.x] = b;
    __syncthreads();
    for (int s = 128; s > 0; s >>= 1) {
        if (threadIdx.x < s) { ss[threadIdx.x] += ss[threadIdx.x + s]; sq[threadIdx.x] += sq[threadIdx.x + s]; }
        __syncthreads();
    }
    if (threadIdx.x == 0) {
        float m = ss[0] / (float)(CH * HW);
        float var = sq[0] / (float)(CH * HW) - m * m;
        stats[br * 512 + n] = m;
        stats[br * 512 + 256 + n] = rsqrtf(var + EPSG);
    }
}

// ---------------- launcher ----------------
extern "C" void kernel_launch(void* const* d_in, const int* in_sizes, int n_in,
                              void* d_out, int out_size) {
    const float* status = (const float*)d_in[0];
    const float* rois   = (const float*)d_in[1];
    const float* bbox   = (const float*)d_in[2];
    const float* wR     = (const float*)d_in[3];
    const float* wQ1    = (const float*)d_in[4];
    const float* wQ2    = (const float*)d_in[5];
    const float* wK1    = (const float*)d_in[6];
    const float* wV1    = (const float*)d_in[7];
    const float* wK2    = (const float*)d_in[8];
    const float* wV2    = (const float*)d_in[9];
    const float* wC1    = (const float*)d_in[10];
    const float* wC2    = (const float*)d_in[11];
    const float* gamma  = (const float*)d_in[12];
    const float* beta   = (const float*)d_in[13];
    float* out1 = (float*)d_out;
    float* out2 = out1 + FEAT_ELEMS;

    float *feat, *q1, *q2, *k1, *v1, *k2, *v2, *vir1, *vir2, *stats, *wqv;
    cudaGetSymbolAddress((void**)&feat, g_feat);
    cudaGetSymbolAddress((void**)&q1,   g_q1);
    cudaGetSymbolAddress((void**)&q2,   g_q2);
    cudaGetSymbolAddress((void**)&k1,   g_k1);
    cudaGetSymbolAddress((void**)&v1,   g_v1);
    cudaGetSymbolAddress((void**)&k2,   g_k2);
    cudaGetSymbolAddress((void**)&v2,   g_v2);
    cudaGetSymbolAddress((void**)&vir1, g_vir1);
    cudaGetSymbolAddress((void**)&vir2, g_vir2);
    cudaGetSymbolAddress((void**)&stats, g_stats);
    cudaGetSymbolAddress((void**)&wqv,  g_wq);

    __half *bpad, *fpad, *h1p, *h2p;
    cudaGetSymbolAddress((void**)&bpad, g_bpad);
    cudaGetSymbolAddress((void**)&fpad, g_fpad);
    cudaGetSymbolAddress((void**)&h1p,  g_h1pad);
    cudaGetSymbolAddress((void**)&h2p,  g_h2pad);

    __half *whR, *whK1, *whV1, *whK2, *whV2, *whC1, *whC2;
    cudaGetSymbolAddress((void**)&whR,  g_wR);
    cudaGetSymbolAddress((void**)&whK1, g_wK1);
    cudaGetSymbolAddress((void**)&whV1, g_wV1);
    cudaGetSymbolAddress((void**)&whK2, g_wK2);
    cudaGetSymbolAddress((void**)&whV2, g_wV2);
    cudaGetSymbolAddress((void**)&whC1, g_wC1);
    cudaGetSymbolAddress((void**)&whC2, g_wC2);

    cudaFuncSetAttribute(conv_mma, cudaFuncAttributeMaxDynamicSharedMemorySize, SMEM_BYTES);

    // merged weight reorder + fp16 round (1 launch for all 7)
    const int nR = K_RED * CH, nC = K_CC * CH;
    {
        WReorder R;
        R.src[0] = wR;  R.dst[0] = whR;  R.C[0] = CIN;
        R.src[1] = wK1; R.dst[1] = whK1; R.C[1] = CH;
        R.src[2] = wV1; R.dst[2] = whV1; R.C[2] = CH;
        R.src[3] = wK2; R.dst[3] = whK2; R.C[3] = CH;
        R.src[4] = wV2; R.dst[4] = whV2; R.C[4] = CH;
        R.src[5] = wC1; R.dst[5] = whC1; R.C[5] = CH;
        R.src[6] = wC2; R.dst[6] = whC2; R.C[6] = CH;
        R.base[0] = 0;
        R.base[1] = nR;
        for (int k = 2; k <= 7; k++) R.base[k] = R.base[k - 1] + nC;
        int total = R.base[7];
        conv_w_reorder_all<<<(total + 255) / 256, 256>>>(R, total);
    }

    // q-conv weight collapse
    qw_prep<<<(2 * 9 * 512 + 255) / 256, 256>>>(wQ1, wQ2, wqv);

    // pad-convert bbox
    pad_convert<<<dim3(NSAMP, CIN / 64), 256>>>(bbox, bpad, CIN);

    // reduce conv split-K=3: each z handles 3 taps, writes a partial
    {
        ConvBatch P = {};
        for (int z = 0; z < 3; z++) { P.a[z] = bpad; P.wh[z] = whR; P.tap0[z] = 3 * z; }
        P.out[0] = k1; P.out[1] = v1; P.out[2] = k2;
        P.addsrc = nullptr;
        conv_mma<<<dim3(NSAMP * HW / 128, CH / 128, 3), 256, SMEM_BYTES>>>(P, CIN, 3);
    }

    // combine partials -> feat (float) + fpad (fp16 padded)
    combine3_pad<<<dim3(NSAMP, CH / 64), 256>>>(k1, v1, k2, feat, fpad);

    // q convs (collapsed), both branches
    q_conv2b<<<dim3((FEAT_ELEMS + 255) / 256, 2), 256>>>(status, rois, wqv, q1, q2);

    // k/v convs (4 fused)
    {
        ConvBatch P = {};
        for (int i = 0; i < 4; i++) { P.a[i] = fpad; P.tap0[i] = 0; }
        P.wh[0] = whK1; P.out[0] = k1;
        P.wh[1] = whV1; P.out[1] = v1;
        P.wh[2] = whK2; P.out[2] = k2;
        P.wh[3] = whV2; P.out[3] = v2;
        P.addsrc = nullptr;
        conv_mma<<<dim3(NSAMP * HW / 128, CH / 128, 4), 256, SMEM_BYTES>>>(P, CH, 9);
    }

    // attention, both branches
    attn2<<<dim3(HW, NG, 2), 256>>>(q1, k1, v1, vir1, q2, k2, v2, vir2);

    // groupnorm stats, both branches
    gn_stats2<<<512, 256>>>(vir1, vir2, stats);

    // fused normalize+relu+pad-convert, both branches
    norm_relu_pad<<<dim3(NSAMP, CH / 64, 2), 256>>>(vir1, vir2, stats, gamma, beta, h1p, h2p);

    // out convs (2 fused): out = feat + conv(h, w_c)
    {
        ConvBatch P = {};
        P.a[0] = h1p; P.wh[0] = whC1; P.out[0] = out1; P.tap0[0] = 0;
        P.a[1] = h2p; P.wh[1] = whC2; P.out[1] = out2; P.tap0[1] = 0;
        P.addsrc = feat;
        conv_mma<<<dim3(NSAMP * HW / 128, CH / 128, 2), 256, SMEM_BYTES>>>(P, CH, 9);
    }
}

// round 10
// speedup vs baseline: 7.8468x; 1.0749x over previous
#include <cuda_runtime.h>
#include <cuda_fp16.h>
#include <cstdint>
#include <math.h>

// ---------------- problem constants ----------------
#define NSAMP 256
#define CIN   2304
#define CH    512
#define HW    49
#define NG    16
#define GSZ   16
#define K_RED (CIN*9)    // 20736
#define K_CC  (CH*9)     // 4608
#define FEAT_ELEMS (NSAMP*CH*HW)   // 6422528
#define EPSG  1e-5f
#define ATT_SCALE 0.044194173824159216f  // 1/sqrt(512)

// ---------------- scratch (device globals; no allocation) ----------------
__device__ float g_feat [FEAT_ELEMS];
__device__ float g_q1   [FEAT_ELEMS];
__device__ float g_q2   [FEAT_ELEMS];
__device__ float g_k1   [FEAT_ELEMS];   // also reduce-conv partial 0
__device__ float g_v1   [FEAT_ELEMS];   // also reduce-conv partial 1
__device__ float g_k2   [FEAT_ELEMS];   // also reduce-conv partial 2
__device__ float g_v2   [FEAT_ELEMS];
__device__ float g_vir1 [FEAT_ELEMS];
__device__ float g_vir2 [FEAT_ELEMS];
__device__ float g_stats[1024];
__device__ float g_wq[2*9*512*5];       // q-conv collapsed weights

// padded channel-last activations: [n][81][C], fp16.
// Borders are NEVER written: __device__ globals are zero-initialized at module
// load, so the pad border stays zero forever (deterministic).
__device__ __align__(256) __half g_bpad [NSAMP*81*CIN];
__device__ __align__(256) __half g_fpad [NSAMP*81*CH];
__device__ __align__(256) __half g_h1pad[NSAMP*81*CH];
__device__ __align__(256) __half g_h2pad[NSAMP*81*CH];

// fp16 weights, tap-major layout [co][tap][ci]
__device__ __align__(256) __half g_wR [K_RED*CH];
__device__ __align__(256) __half g_wK1[K_CC*CH];
__device__ __align__(256) __half g_wV1[K_CC*CH];
__device__ __align__(256) __half g_wK2[K_CC*CH];
__device__ __align__(256) __half g_wV2[K_CC*CH];
__device__ __align__(256) __half g_wC1[K_CC*CH];
__device__ __align__(256) __half g_wC2[K_CC*CH];

// ---------------- helpers ----------------
__device__ __forceinline__ uint32_t smem_u32(const void* p) {
    uint32_t a;
    asm("{ .reg .u64 t; cvta.to.shared.u64 t, %1; cvt.u32.u64 %0, t; }" : "=r"(a) : "l"(p));
    return a;
}
__device__ __forceinline__ void cp_async16(uint32_t dst, const void* src) {
    asm volatile("cp.async.cg.shared.global [%0], [%1], 16;" :: "r"(dst), "l"(src));
}
__device__ __forceinline__ void ldm_x4(uint32_t* r, uint32_t addr) {
    asm volatile("ldmatrix.sync.aligned.m8n8.x4.shared.b16 {%0,%1,%2,%3}, [%4];"
        : "=r"(r[0]), "=r"(r[1]), "=r"(r[2]), "=r"(r[3]) : "r"(addr));
}
__device__ __forceinline__ void mma_f16(float* d, const uint32_t* a, const uint32_t* b) {
    asm volatile(
        "mma.sync.aligned.m16n8k16.row.col.f32.f16.f16.f32 "
        "{%0,%1,%2,%3}, {%4,%5,%6,%7}, {%8,%9}, {%0,%1,%2,%3};\n"
        : "+f"(d[0]), "+f"(d[1]), "+f"(d[2]), "+f"(d[3])
        : "r"(a[0]), "r"(a[1]), "r"(a[2]), "r"(a[3]), "r"(b[0]), "r"(b[1]));
}

// ---------------- merged weight reorder + fp16 round (all 7 weights) ---------
// w[co][ci*9+t] -> wh[co][t*C+ci]
struct WReorder {
    const float* src[7];
    __half* dst[7];
    int C[7];
    int base[8];      // prefix sums of element counts
};
__global__ void conv_w_reorder_all(WReorder R, int total) {
    int i = blockIdx.x * 256 + threadIdx.x;
    if (i >= total) return;
    int s = 0;
#pragma unroll
    for (int k = 0; k < 6; k++) if (i >= R.base[k + 1]) s = k + 1;
    int j = i - R.base[s];
    int C = R.C[s];
    int K9 = 9 * C;
    int co = j / K9, rem = j - co * K9;
    int t = rem / C, ci = rem - t * C;
    R.dst[s][j] = __float2half_rn(R.src[s][(size_t)co * K9 + ci * 9 + t]);
}

// ---------------- q-conv weight collapse: Wq[br][cls][co][ci] ----------------
__global__ void qw_prep(const float* __restrict__ wq1, const float* __restrict__ wq2,
                        float* __restrict__ Wq) {
    int i = blockIdx.x * 256 + threadIdx.x;
    if (i >= 2 * 9 * 512) return;
    int br = i / (9 * 512);
    int rem = i - br * 9 * 512;
    int cls = rem / 512, co = rem - cls * 512;
    int cy = cls / 3, cx = cls - 3 * cy;
    const float* w = (br ? wq2 : wq1) + co * 45;
#pragma unroll
    for (int ci = 0; ci < 5; ci++) {
        float s = 0.f;
#pragma unroll
        for (int dy = 0; dy < 3; dy++) {
            if (cy == 0 && dy == 0) continue;
            if (cy == 2 && dy == 2) continue;
#pragma unroll
            for (int dx = 0; dx < 3; dx++) {
                if (cx == 0 && dx == 0) continue;
                if (cx == 2 && dx == 2) continue;
                s += w[ci * 9 + dy * 3 + dx];
            }
        }
        Wq[((br * 9 + cls) * 512 + co) * 5 + ci] = s;
    }
}

// ---------------- NCHW float -> padded channel-last fp16 (interior only) ------
__global__ void pad_convert(const float* __restrict__ src, __half* __restrict__ hi, int C) {
    int n = blockIdx.x, c0 = blockIdx.y * 64;
    __shared__ float tile[64][51];
    int tid = threadIdx.x;
    for (int e = tid; e < 64 * 49; e += 256) {
        int ci = e / 49, p = e - 49 * ci;
        tile[ci][p] = src[((size_t)n * C + c0 + ci) * 49 + p];
    }
    __syncthreads();
    for (int e = tid; e < 49 * 64; e += 256) {
        int p = e >> 6, ci = e & 63;
        int y = p / 7, x = p - 7 * y;
        hi[((size_t)n * 81 + (y + 1) * 9 + (x + 1)) * C + c0 + ci] =
            __float2half_rn(tile[ci][p]);
    }
}

// ---------------- combine 3 split-K partials -> feat (float) + fpad (fp16) ----
__global__ void combine3_pad(const float* __restrict__ p0, const float* __restrict__ p1,
                             const float* __restrict__ p2,
                             float* __restrict__ feat, __half* __restrict__ fpad) {
    int n = blockIdx.x, c0 = blockIdx.y * 64;
    __shared__ float tile[64][51];
    int tid = threadIdx.x;
    for (int e = tid; e < 64 * 49; e += 256) {
        int ci = e / 49, p = e - 49 * ci;
        size_t idx = ((size_t)n * CH + c0 + ci) * 49 + p;
        float v = p0[idx] + p1[idx] + p2[idx];
        feat[idx] = v;
        tile[ci][p] = v;
    }
    __syncthreads();
    for (int e = tid; e < 49 * 64; e += 256) {
        int p = e >> 6, ci = e & 63;
        int y = p / 7, x = p - 7 * y;
        fpad[((size_t)n * 81 + (y + 1) * 9 + (x + 1)) * CH + c0 + ci] =
            __float2half_rn(tile[ci][p]);
    }
}

// ---------------- fused GN-normalize + relu + pad-convert (interior only) -----
__global__ void norm_relu_pad(const float* __restrict__ x1, const float* __restrict__ x2,
                              const float* __restrict__ stats,
                              const float* __restrict__ gamma, const float* __restrict__ beta,
                              __half* __restrict__ h1, __half* __restrict__ h2) {
    int n = blockIdx.x, c0 = blockIdx.y * 64, br = blockIdx.z;
    const float* x = br ? x2 : x1;
    __half* hp = br ? h2 : h1;
    float mu = stats[br * 512 + n];
    float rs = stats[br * 512 + 256 + n];
    __shared__ float tile[64][51];
    int tid = threadIdx.x;
    for (int e = tid; e < 64 * 49; e += 256) {
        int ci = e / 49, p = e - 49 * ci;
        float v = x[((size_t)n * CH + c0 + ci) * 49 + p];
        tile[ci][p] = fmaxf((v - mu) * rs * gamma[c0 + ci] + beta[c0 + ci], 0.f);
    }
    __syncthreads();
    for (int e = tid; e < 49 * 64; e += 256) {
        int p = e >> 6, ci = e & 63;
        int y = p / 7, x9 = p - 7 * y;
        hp[((size_t)n * 81 + (y + 1) * 9 + (x9 + 1)) * CH + c0 + ci] =
            __float2half_rn(tile[ci][p]);
    }
}

// ---------------- batched HMMA conv: shifted 1x1 GEMMs over padded input ------
// out[n,co,p] = sum_{t in [tap0,tap0+ntap), ci} xpad[n, pp(p,t), ci] * wh[co, t*C+ci]
// CTA tile 128x128, 8 warps (2x4), warp tile 64x32, K chunk 64, 3-stage pipeline.
#define KC   64
#define KCP  72                      // SMEM row stride (fp16 elems) = 144B
#define MATH (128*KCP)               // 9216 fp16 per matrix
#define BUFE (2*MATH)                // A, B
#define NSTG 3
#define SMEM_BYTES (NSTG*BUFE*2)     // 110592 bytes

struct ConvBatch {
    const __half* a[4];
    const __half* wh[4];
    float* out[4];
    const float* addsrc;
    int tap0[4];
};

__global__ void __launch_bounds__(256, 2)
conv_mma(ConvBatch P, int C, int ntap) {
    extern __shared__ __half smem[];
    const int K9 = 9 * C;
    const int NCI = C / KC;
    const int NQ = ntap * NCI;
    const int cv = blockIdx.z;
    const __half* __restrict__ A  = P.a[cv];
    const __half* __restrict__ Wh = P.wh[cv];
    float* __restrict__ out = P.out[cv];
    const float* addsrc = P.addsrc;
    const int tap0 = P.tap0[cv];

    const int tid = threadIdx.x;
    const int wid = tid >> 5, lane = tid & 31;
    const int g = lane >> 2, tg = lane & 3;
    const int m0 = blockIdx.x * 128;
    const int n0 = blockIdx.y * 128;
    const int wm = (wid & 1) * 64;
    const int wn = (wid >> 1) * 32;

    // fill geometry: thread serves rows r0+32h (h=0..3), 16B segment `seg` of 128B row
    const int seg = tid & 7;
    const int r0 = tid >> 3;          // 0..31
    size_t abase[4];
#pragma unroll
    for (int h = 0; h < 4; h++) {
        int m = m0 + r0 + 32 * h;
        int n = m / 49, p = m - 49 * n;
        int y = p / 7, x = p - 7 * y;
        abase[h] = ((size_t)n * 81 + y * 9 + x) * C + seg * 8;
    }

    // ldmatrix lane geometry
    const int aRow = wm + (lane & 15);         // + 16*t
    const int aCol = (lane >> 4) * 8;          // + 16*s
    const int bRow = wn + (lane & 7) + ((lane >> 4) * 8);   // + 16 for second x4
    const int bCol = ((lane >> 3) & 1) * 8;    // + 16*s

    auto fill = [&](int q) {
        __half* base = smem + (q % NSTG) * BUFE;
        int t = tap0 + q / NCI;
        int ci = (q % NCI) * KC;
        int a3 = t / 3, b3 = t - 3 * a3;
        size_t tof = (size_t)(a3 * 9 + b3) * C + ci;
#pragma unroll
        for (int h = 0; h < 4; h++) {
            int r = r0 + 32 * h;
            cp_async16(smem_u32(&base[r * KCP + seg * 8]), A + abase[h] + tof);
        }
#pragma unroll
        for (int h = 0; h < 4; h++) {
            int row = r0 + 32 * h;
            size_t src = (size_t)(n0 + row) * K9 + t * C + ci + seg * 8;
            cp_async16(smem_u32(&base[MATH + row * KCP + seg * 8]), Wh + src);
        }
        asm volatile("cp.async.commit_group;" ::: "memory");
    };

    float acc[4][4][4];
#pragma unroll
    for (int t = 0; t < 4; t++)
#pragma unroll
        for (int u = 0; u < 4; u++)
#pragma unroll
            for (int e = 0; e < 4; e++) acc[t][u][e] = 0.f;

    // 3-stage pipeline prologue: two fills in flight
    fill(0);
    if (NQ > 1) fill(1);

    for (int q = 0; q < NQ; q++) {
        if (q + 1 < NQ) asm volatile("cp.async.wait_group 1;" ::: "memory");
        else            asm volatile("cp.async.wait_group 0;" ::: "memory");
        __syncthreads();   // all threads see buf q; all warps done with buf q-1
        if (q + 2 < NQ) fill(q + 2);

        __half* cur = smem + (q % NSTG) * BUFE;
        uint32_t aB = smem_u32(cur);
        uint32_t bB = aB + MATH * 2;    // bytes
#pragma unroll
        for (int s = 0; s < 4; s++) {
            uint32_t bregs[8];
            ldm_x4(bregs,     bB + (uint32_t)((bRow)      * KCP + 16 * s + bCol) * 2);
            ldm_x4(bregs + 4, bB + (uint32_t)((bRow + 16) * KCP + 16 * s + bCol) * 2);
#pragma unroll
            for (int t = 0; t < 4; t++) {
                uint32_t ar[4];
                ldm_x4(ar, aB + (uint32_t)((aRow + 16 * t) * KCP + 16 * s + aCol) * 2);
#pragma unroll
                for (int u = 0; u < 4; u++)
                    mma_f16(acc[t][u], ar, bregs + 2 * u);
            }
        }
    }

    // ---- epilogue ----
#pragma unroll
    for (int t = 0; t < 4; t++) {
#pragma unroll
        for (int h = 0; h < 2; h++) {
            int row = m0 + wm + 16 * t + g + 8 * h;
            int n = row / 49, p = row - 49 * n;
            size_t base = (size_t)n * CH * 49 + p;
#pragma unroll
            for (int u = 0; u < 4; u++) {
                int col = n0 + wn + 8 * u + tg * 2;
                size_t i0 = base + (size_t)col * 49;
                float v0 = acc[t][u][2 * h];
                float v1 = acc[t][u][2 * h + 1];
                if (addsrc) { v0 += addsrc[i0]; v1 += addsrc[i0 + 49]; }
                out[i0] = v0;
                out[i0 + 49] = v1;
            }
        }
    }
}

// ---------------- q-conv via collapsed weights, y = branch ----------
__global__ void q_conv2b(const float* __restrict__ status, const float* __restrict__ rois,
                         const float* __restrict__ Wq,
                         float* __restrict__ o1, float* __restrict__ o2) {
    int idx = blockIdx.x * 256 + threadIdx.x;
    if (idx >= NSAMP * CH * HW) return;
    int br = blockIdx.y;
    float* out = br ? o2 : o1;
    int p = idx % HW;
    int t2 = idx / HW;
    int co = t2 % CH;
    int n = t2 / CH;
    int y = p / 7, x = p - 7 * y;
    int cy = (y == 0) ? 0 : ((y == 6) ? 2 : 1);
    int cx = (x == 0) ? 0 : ((x == 6) ? 2 : 1);
    const float* wq = Wq + (((size_t)br * 9 + cy * 3 + cx) * 512 + co) * 5;
    float acc = wq[0] * status[n * 2 + br]
              + wq[1] * rois[n * 5 + 1] + wq[2] * rois[n * 5 + 2]
              + wq[3] * rois[n * 5 + 3] + wq[4] * rois[n * 5 + 4];
    out[idx] = acc;
}

// ---------------- attention per (hw, g), z = branch ----------------
#define CCH 256
__global__ void attn2(const float* __restrict__ q1, const float* __restrict__ k1,
                      const float* __restrict__ v1, float* __restrict__ w1,
                      const float* __restrict__ q2, const float* __restrict__ k2,
                      const float* __restrict__ v2, float* __restrict__ w2) {
    int hw = blockIdx.x;
    int gg = blockIdx.y;
    int br = blockIdx.z;
    const float* q = br ? q2 : q1;
    const float* k = br ? k2 : k1;
    const float* v = br ? v2 : v1;
    float* virt = br ? w2 : w1;

    __shared__ float bufA[GSZ][CCH + 1];
    __shared__ float bufB[GSZ][CCH + 1];
    __shared__ float att[GSZ][GSZ + 1];
    __shared__ float attn[GSZ][GSZ + 1];

    int tid = threadIdx.x;
    int i = tid >> 4, j = tid & 15;
    float a = 0.f;

    for (int c0 = 0; c0 < CH; c0 += CCH) {
        for (int e = tid; e < GSZ * CCH; e += 256) {
            int r = e >> 8, c = e & 255;
            int gidx = ((gg * GSZ + r) * CH + c0 + c) * HW + hw;
            bufA[r][c] = q[gidx];
            bufB[r][c] = k[gidx];
        }
        __syncthreads();
#pragma unroll 8
        for (int c = 0; c < CCH; c++)
            a += bufA[i][c] * bufB[j][c];
        __syncthreads();
    }
    att[i][j] = a * ATT_SCALE;
    __syncthreads();

    float mx = att[i][0];
#pragma unroll
    for (int jj = 1; jj < GSZ; jj++) mx = fmaxf(mx, att[i][jj]);
    float sum = 0.f;
#pragma unroll
    for (int jj = 0; jj < GSZ; jj++) sum += expf(att[i][jj] - mx);
    attn[i][j] = expf(att[i][j] - mx) / sum;
    __syncthreads();

    for (int c0 = 0; c0 < CH; c0 += CCH) {
        for (int e = tid; e < GSZ * CCH; e += 256) {
            int r = e >> 8, c = e & 255;
            bufA[r][c] = v[((gg * GSZ + r) * CH + c0 + c) * HW + hw];
        }
        __syncthreads();
        for (int e = tid; e < GSZ * CCH; e += 256) {
            int r = e >> 8, c = e & 255;
            float s = 0.f;
#pragma unroll
            for (int jj = 0; jj < GSZ; jj++) s += attn[r][jj] * bufA[jj][c];
            virt[((gg * GSZ + r) * CH + c0 + c) * HW + hw] = s;
        }
        __syncthreads();
    }
}

// ---------------- groupnorm stats, both branches ----------
__global__ void gn_stats2(const float* __restrict__ x1, const float* __restrict__ x2,
                          float* __restrict__ stats) {
    __shared__ float ss[256], sq[256];
    int blk = blockIdx.x;
    int br = blk >> 8, n = blk & 255;
    const float* p = (br ? x2 : x1) + (size_t)n * CH * HW;
    float a = 0.f, b = 0.f;
    for (int e = threadIdx.x; e < CH * HW; e += 256) {
        float v = p[e];
        a += v; b += v * v;
    }
    ss[threadIdx.x] = a; sq[threadIdx.x] = b;
    __syncthreads();
    for (int s = 128; s > 0; s >>= 1) {
        if (threadIdx.x < s) { ss[threadIdx.x] += ss[threadIdx.x + s]; sq[threadIdx.x] += sq[threadIdx.x + s]; }
        __syncthreads();
    }
    if (threadIdx.x == 0) {
        float m = ss[0] / (float)(CH * HW);
        float var = sq[0] / (float)(CH * HW) - m * m;
        stats[br * 512 + n] = m;
        stats[br * 512 + 256 + n] = rsqrtf(var + EPSG);
    }
}

// ---------------- launcher ----------------
extern "C" void kernel_launch(void* const* d_in, const int* in_sizes, int n_in,
                              void* d_out, int out_size) {
    const float* status = (const float*)d_in[0];
    const float* rois   = (const float*)d_in[1];
    const float* bbox   = (const float*)d_in[2];
    const float* wR     = (const float*)d_in[3];
    const float* wQ1    = (const float*)d_in[4];
    const float* wQ2    = (const float*)d_in[5];
    const float* wK1    = (const float*)d_in[6];
    const float* wV1    = (const float*)d_in[7];
    const float* wK2    = (const float*)d_in[8];
    const float* wV2    = (const float*)d_in[9];
    const float* wC1    = (const float*)d_in[10];
    const float* wC2    = (const float*)d_in[11];
    const float* gamma  = (const float*)d_in[12];
    const float* beta   = (const float*)d_in[13];
    float* out1 = (float*)d_out;
    float* out2 = out1 + FEAT_ELEMS;

    float *feat, *q1, *q2, *k1, *v1, *k2, *v2, *vir1, *vir2, *stats, *wqv;
    cudaGetSymbolAddress((void**)&feat, g_feat);
    cudaGetSymbolAddress((void**)&q1,   g_q1);
    cudaGetSymbolAddress((void**)&q2,   g_q2);
    cudaGetSymbolAddress((void**)&k1,   g_k1);
    cudaGetSymbolAddress((void**)&v1,   g_v1);
    cudaGetSymbolAddress((void**)&k2,   g_k2);
    cudaGetSymbolAddress((void**)&v2,   g_v2);
    cudaGetSymbolAddress((void**)&vir1, g_vir1);
    cudaGetSymbolAddress((void**)&vir2, g_vir2);
    cudaGetSymbolAddress((void**)&stats, g_stats);
    cudaGetSymbolAddress((void**)&wqv,  g_wq);

    __half *bpad, *fpad, *h1p, *h2p;
    cudaGetSymbolAddress((void**)&bpad, g_bpad);
    cudaGetSymbolAddress((void**)&fpad, g_fpad);
    cudaGetSymbolAddress((void**)&h1p,  g_h1pad);
    cudaGetSymbolAddress((void**)&h2p,  g_h2pad);

    __half *whR, *whK1, *whV1, *whK2, *whV2, *whC1, *whC2;
    cudaGetSymbolAddress((void**)&whR,  g_wR);
    cudaGetSymbolAddress((void**)&whK1, g_wK1);
    cudaGetSymbolAddress((void**)&whV1, g_wV1);
    cudaGetSymbolAddress((void**)&whK2, g_wK2);
    cudaGetSymbolAddress((void**)&whV2, g_wV2);
    cudaGetSymbolAddress((void**)&whC1, g_wC1);
    cudaGetSymbolAddress((void**)&whC2, g_wC2);

    cudaFuncSetAttribute(conv_mma, cudaFuncAttributeMaxDynamicSharedMemorySize, SMEM_BYTES);

    // merged weight reorder + fp16 round (1 launch for all 7)
    const int nR = K_RED * CH, nC = K_CC * CH;
    {
        WReorder R;
        R.src[0] = wR;  R.dst[0] = whR;  R.C[0] = CIN;
        R.src[1] = wK1; R.dst[1] = whK1; R.C[1] = CH;
        R.src[2] = wV1; R.dst[2] = whV1; R.C[2] = CH;
        R.src[3] = wK2; R.dst[3] = whK2; R.C[3] = CH;
        R.src[4] = wV2; R.dst[4] = whV2; R.C[4] = CH;
        R.src[5] = wC1; R.dst[5] = whC1; R.C[5] = CH;
        R.src[6] = wC2; R.dst[6] = whC2; R.C[6] = CH;
        R.base[0] = 0;
        R.base[1] = nR;
        for (int k = 2; k <= 7; k++) R.base[k] = R.base[k - 1] + nC;
        int total = R.base[7];
        conv_w_reorder_all<<<(total + 255) / 256, 256>>>(R, total);
    }

    // q-conv weight collapse
    qw_prep<<<(2 * 9 * 512 + 255) / 256, 256>>>(wQ1, wQ2, wqv);

    // pad-convert bbox
    pad_convert<<<dim3(NSAMP, CIN / 64), 256>>>(bbox, bpad, CIN);

    // reduce conv split-K=3: each z handles 3 taps, writes a partial
    {
        ConvBatch P = {};
        for (int z = 0; z < 3; z++) { P.a[z] = bpad; P.wh[z] = whR; P.tap0[z] = 3 * z; }
        P.out[0] = k1; P.out[1] = v1; P.out[2] = k2;
        P.addsrc = nullptr;
        conv_mma<<<dim3(NSAMP * HW / 128, CH / 128, 3), 256, SMEM_BYTES>>>(P, CIN, 3);
    }

    // combine partials -> feat (float) + fpad (fp16 padded)
    combine3_pad<<<dim3(NSAMP, CH / 64), 256>>>(k1, v1, k2, feat, fpad);

    // q convs (collapsed), both branches
    q_conv2b<<<dim3((FEAT_ELEMS + 255) / 256, 2), 256>>>(status, rois, wqv, q1, q2);

    // k/v convs (4 fused)
    {
        ConvBatch P = {};
        for (int i = 0; i < 4; i++) { P.a[i] = fpad; P.tap0[i] = 0; }
        P.wh[0] = whK1; P.out[0] = k1;
        P.wh[1] = whV1; P.out[1] = v1;
        P.wh[2] = whK2; P.out[2] = k2;
        P.wh[3] = whV2; P.out[3] = v2;
        P.addsrc = nullptr;
        conv_mma<<<dim3(NSAMP * HW / 128, CH / 128, 4), 256, SMEM_BYTES>>>(P, CH, 9);
    }

    // attention, both branches
    attn2<<<dim3(HW, NG, 2), 256>>>(q1, k1, v1, vir1, q2, k2, v2, vir2);

    // groupnorm stats, both branches
    gn_stats2<<<512, 256>>>(vir1, vir2, stats);

    // fused normalize+relu+pad-convert, both branches
    norm_relu_pad<<<dim3(NSAMP, CH / 64, 2), 256>>>(vir1, vir2, stats, gamma, beta, h1p, h2p);

    // out convs (2 fused): out = feat + conv(h, w_c)
    {
        ConvBatch P = {};
        P.a[0] = h1p; P.wh[0] = whC1; P.out[0] = out1; P.tap0[0] = 0;
        P.a[1] = h2p; P.wh[1] = whC2; P.out[1] = out2; P.tap0[1] = 0;
        P.addsrc = feat;
        conv_mma<<<dim3(NSAMP * HW / 128, CH / 128, 2), 256, SMEM_BYTES>>>(P, CH, 9);
    }
}

// round 11
// speedup vs baseline: 9.3670x; 1.1937x over previous
#include <cuda_runtime.h>
#include <cuda_fp16.h>
#include <cstdint>
#include <math.h>

// ---------------- problem constants ----------------
#define NSAMP 256
#define CIN   2304
#define CH    512
#define HW    49
#define NG    16
#define GSZ   16
#define K_RED (CIN*9)    // 20736
#define K_CC  (CH*9)     // 4608
#define FEAT_ELEMS (NSAMP*CH*HW)   // 6422528
#define EPSG  1e-5f
#define ATT_SCALE 0.044194173824159216f  // 1/sqrt(512)

// ---------------- scratch (device globals; no allocation) ----------------
// feat is NCHW (needed as fp32 residual for the final convs).
// q/k/v and virt are CHANNEL-LAST: [n][p][c] with c contiguous.
__device__ float g_feat [FEAT_ELEMS];
__device__ float g_q1   [FEAT_ELEMS];
__device__ float g_q2   [FEAT_ELEMS];
__device__ float g_k1   [FEAT_ELEMS];   // also reduce-conv partial 0 (NCHW)
__device__ float g_v1   [FEAT_ELEMS];   // also reduce-conv partial 1 (NCHW)
__device__ float g_k2   [FEAT_ELEMS];   // also reduce-conv partial 2 (NCHW)
__device__ float g_v2   [FEAT_ELEMS];
__device__ float g_vir1 [FEAT_ELEMS];
__device__ float g_vir2 [FEAT_ELEMS];
__device__ float g_stats[1024];
__device__ float g_wq[2*9*512*5];       // q-conv collapsed weights

// padded channel-last activations: [n][81][C], fp16.
// Borders are NEVER written: __device__ globals are zero-initialized at module
// load, so the pad border stays zero forever (deterministic).
__device__ __align__(256) __half g_bpad [NSAMP*81*CIN];
__device__ __align__(256) __half g_fpad [NSAMP*81*CH];
__device__ __align__(256) __half g_h1pad[NSAMP*81*CH];
__device__ __align__(256) __half g_h2pad[NSAMP*81*CH];

// fp16 weights, tap-major layout [co][tap][ci]
__device__ __align__(256) __half g_wR [K_RED*CH];
__device__ __align__(256) __half g_wK1[K_CC*CH];
__device__ __align__(256) __half g_wV1[K_CC*CH];
__device__ __align__(256) __half g_wK2[K_CC*CH];
__device__ __align__(256) __half g_wV2[K_CC*CH];
__device__ __align__(256) __half g_wC1[K_CC*CH];
__device__ __align__(256) __half g_wC2[K_CC*CH];

// ---------------- helpers ----------------
__device__ __forceinline__ uint32_t smem_u32(const void* p) {
    uint32_t a;
    asm("{ .reg .u64 t; cvta.to.shared.u64 t, %1; cvt.u32.u64 %0, t; }" : "=r"(a) : "l"(p));
    return a;
}
__device__ __forceinline__ void cp_async16(uint32_t dst, const void* src) {
    asm volatile("cp.async.cg.shared.global [%0], [%1], 16;" :: "r"(dst), "l"(src));
}
__device__ __forceinline__ void ldm_x4(uint32_t* r, uint32_t addr) {
    asm volatile("ldmatrix.sync.aligned.m8n8.x4.shared.b16 {%0,%1,%2,%3}, [%4];"
        : "=r"(r[0]), "=r"(r[1]), "=r"(r[2]), "=r"(r[3]) : "r"(addr));
}
__device__ __forceinline__ void mma_f16(float* d, const uint32_t* a, const uint32_t* b) {
    asm volatile(
        "mma.sync.aligned.m16n8k16.row.col.f32.f16.f16.f32 "
        "{%0,%1,%2,%3}, {%4,%5,%6,%7}, {%8,%9}, {%0,%1,%2,%3};\n"
        : "+f"(d[0]), "+f"(d[1]), "+f"(d[2]), "+f"(d[3])
        : "r"(a[0]), "r"(a[1]), "r"(a[2]), "r"(a[3]), "r"(b[0]), "r"(b[1]));
}

// ---------------- merged weight reorder + fp16 round (all 7 weights) ---------
struct WReorder {
    const float* src[7];
    __half* dst[7];
    int C[7];
    int base[8];
};
__global__ void conv_w_reorder_all(WReorder R, int total) {
    int i = blockIdx.x * 256 + threadIdx.x;
    if (i >= total) return;
    int s = 0;
#pragma unroll
    for (int k = 0; k < 6; k++) if (i >= R.base[k + 1]) s = k + 1;
    int j = i - R.base[s];
    int C = R.C[s];
    int K9 = 9 * C;
    int co = j / K9, rem = j - co * K9;
    int t = rem / C, ci = rem - t * C;
    R.dst[s][j] = __float2half_rn(R.src[s][(size_t)co * K9 + ci * 9 + t]);
}

// ---------------- q-conv weight collapse: Wq[br][cls][co][ci] ----------------
__global__ void qw_prep(const float* __restrict__ wq1, const float* __restrict__ wq2,
                        float* __restrict__ Wq) {
    int i = blockIdx.x * 256 + threadIdx.x;
    if (i >= 2 * 9 * 512) return;
    int br = i / (9 * 512);
    int rem = i - br * 9 * 512;
    int cls = rem / 512, co = rem - cls * 512;
    int cy = cls / 3, cx = cls - 3 * cy;
    const float* w = (br ? wq2 : wq1) + co * 45;
#pragma unroll
    for (int ci = 0; ci < 5; ci++) {
        float s = 0.f;
#pragma unroll
        for (int dy = 0; dy < 3; dy++) {
            if (cy == 0 && dy == 0) continue;
            if (cy == 2 && dy == 2) continue;
#pragma unroll
            for (int dx = 0; dx < 3; dx++) {
                if (cx == 0 && dx == 0) continue;
                if (cx == 2 && dx == 2) continue;
                s += w[ci * 9 + dy * 3 + dx];
            }
        }
        Wq[((br * 9 + cls) * 512 + co) * 5 + ci] = s;
    }
}

// ---------------- NCHW float -> padded channel-last fp16 (interior only) ------
__global__ void pad_convert(const float* __restrict__ src, __half* __restrict__ hi, int C) {
    int n = blockIdx.x, c0 = blockIdx.y * 64;
    __shared__ float tile[64][51];
    int tid = threadIdx.x;
    for (int e = tid; e < 64 * 49; e += 256) {
        int ci = e / 49, p = e - 49 * ci;
        tile[ci][p] = src[((size_t)n * C + c0 + ci) * 49 + p];
    }
    __syncthreads();
    for (int e = tid; e < 49 * 64; e += 256) {
        int p = e >> 6, ci = e & 63;
        int y = p / 7, x = p - 7 * y;
        hi[((size_t)n * 81 + (y + 1) * 9 + (x + 1)) * C + c0 + ci] =
            __float2half_rn(tile[ci][p]);
    }
}

// ---------------- combine 3 split-K partials -> feat (float) + fpad (fp16) ----
__global__ void combine3_pad(const float* __restrict__ p0, const float* __restrict__ p1,
                             const float* __restrict__ p2,
                             float* __restrict__ feat, __half* __restrict__ fpad) {
    int n = blockIdx.x, c0 = blockIdx.y * 64;
    __shared__ float tile[64][51];
    int tid = threadIdx.x;
    for (int e = tid; e < 64 * 49; e += 256) {
        int ci = e / 49, p = e - 49 * ci;
        size_t idx = ((size_t)n * CH + c0 + ci) * 49 + p;
        float v = p0[idx] + p1[idx] + p2[idx];
        feat[idx] = v;
        tile[ci][p] = v;
    }
    __syncthreads();
    for (int e = tid; e < 49 * 64; e += 256) {
        int p = e >> 6, ci = e & 63;
        int y = p / 7, x = p - 7 * y;
        fpad[((size_t)n * 81 + (y + 1) * 9 + (x + 1)) * CH + c0 + ci] =
            __float2half_rn(tile[ci][p]);
    }
}

// ------- fused GN-normalize + relu + pad-convert, channel-last, elementwise ---
__global__ void norm_relu_pad(const float* __restrict__ x1, const float* __restrict__ x2,
                              const float* __restrict__ stats,
                              const float* __restrict__ gamma, const float* __restrict__ beta,
                              __half* __restrict__ h1, __half* __restrict__ h2) {
    int idx = blockIdx.x * 256 + threadIdx.x;
    if (idx >= FEAT_ELEMS) return;
    int br = blockIdx.y;
    const float* x = br ? x2 : x1;
    __half* hp = br ? h2 : h1;
    int c = idx & 511;                  // CH = 512
    int t = idx >> 9;                   // n*49 + p
    int n = t / 49, p = t - 49 * n;
    float mu = stats[br * 512 + n];
    float rs = stats[br * 512 + 256 + n];
    float v = fmaxf((x[idx] - mu) * rs * gamma[c] + beta[c], 0.f);
    int y = p / 7, xq = p - 7 * y;
    hp[((size_t)n * 81 + (y + 1) * 9 + (xq + 1)) * CH + c] = __float2half_rn(v);
}

// ---------------- batched HMMA conv: shifted 1x1 GEMMs over padded input ------
// out layout: chlast=0 -> NCHW [n][co][p];  chlast=1 -> channel-last [n][p][co]
#define KC   64
#define KCP  72                      // SMEM row stride (fp16 elems) = 144B
#define MATH (128*KCP)               // 9216 fp16 per matrix
#define BUFE (2*MATH)                // A, B
#define NSTG 3
#define SMEM_BYTES (NSTG*BUFE*2)     // 110592 bytes

struct ConvBatch {
    const __half* a[4];
    const __half* wh[4];
    float* out[4];
    const float* addsrc;
    int tap0[4];
    int chlast;
};

__global__ void __launch_bounds__(256, 2)
conv_mma(ConvBatch P, int C, int ntap) {
    extern __shared__ __half smem[];
    const int K9 = 9 * C;
    const int NCI = C / KC;
    const int NQ = ntap * NCI;
    const int cv = blockIdx.z;
    const __half* __restrict__ A  = P.a[cv];
    const __half* __restrict__ Wh = P.wh[cv];
    float* __restrict__ out = P.out[cv];
    const float* addsrc = P.addsrc;
    const int tap0 = P.tap0[cv];

    const int tid = threadIdx.x;
    const int wid = tid >> 5, lane = tid & 31;
    const int g = lane >> 2, tg = lane & 3;
    const int m0 = blockIdx.x * 128;
    const int n0 = blockIdx.y * 128;
    const int wm = (wid & 1) * 64;
    const int wn = (wid >> 1) * 32;

    // fill geometry: thread serves rows r0+32h (h=0..3), 16B segment `seg`
    const int seg = tid & 7;
    const int r0 = tid >> 3;          // 0..31
    size_t abase[4];
#pragma unroll
    for (int h = 0; h < 4; h++) {
        int m = m0 + r0 + 32 * h;
        int n = m / 49, p = m - 49 * n;
        int y = p / 7, x = p - 7 * y;
        abase[h] = ((size_t)n * 81 + y * 9 + x) * C + seg * 8;
    }

    // ldmatrix lane geometry
    const int aRow = wm + (lane & 15);
    const int aCol = (lane >> 4) * 8;
    const int bRow = wn + (lane & 7) + ((lane >> 4) * 8);
    const int bCol = ((lane >> 3) & 1) * 8;

    auto fill = [&](int q) {
        __half* base = smem + (q % NSTG) * BUFE;
        int t = tap0 + q / NCI;
        int ci = (q % NCI) * KC;
        int a3 = t / 3, b3 = t - 3 * a3;
        size_t tof = (size_t)(a3 * 9 + b3) * C + ci;
#pragma unroll
        for (int h = 0; h < 4; h++) {
            int r = r0 + 32 * h;
            cp_async16(smem_u32(&base[r * KCP + seg * 8]), A + abase[h] + tof);
        }
#pragma unroll
        for (int h = 0; h < 4; h++) {
            int row = r0 + 32 * h;
            size_t src = (size_t)(n0 + row) * K9 + t * C + ci + seg * 8;
            cp_async16(smem_u32(&base[MATH + row * KCP + seg * 8]), Wh + src);
        }
        asm volatile("cp.async.commit_group;" ::: "memory");
    };

    float acc[4][4][4];
#pragma unroll
    for (int t = 0; t < 4; t++)
#pragma unroll
        for (int u = 0; u < 4; u++)
#pragma unroll
            for (int e = 0; e < 4; e++) acc[t][u][e] = 0.f;

    fill(0);
    if (NQ > 1) fill(1);

    for (int q = 0; q < NQ; q++) {
        if (q + 1 < NQ) asm volatile("cp.async.wait_group 1;" ::: "memory");
        else            asm volatile("cp.async.wait_group 0;" ::: "memory");
        __syncthreads();
        if (q + 2 < NQ) fill(q + 2);

        __half* cur = smem + (q % NSTG) * BUFE;
        uint32_t aB = smem_u32(cur);
        uint32_t bB = aB + MATH * 2;
#pragma unroll
        for (int s = 0; s < 4; s++) {
            uint32_t bregs[8];
            ldm_x4(bregs,     bB + (uint32_t)((bRow)      * KCP + 16 * s + bCol) * 2);
            ldm_x4(bregs + 4, bB + (uint32_t)((bRow + 16) * KCP + 16 * s + bCol) * 2);
#pragma unroll
            for (int t = 0; t < 4; t++) {
                uint32_t ar[4];
                ldm_x4(ar, aB + (uint32_t)((aRow + 16 * t) * KCP + 16 * s + aCol) * 2);
#pragma unroll
                for (int u = 0; u < 4; u++)
                    mma_f16(acc[t][u], ar, bregs + 2 * u);
            }
        }
    }

    // ---- epilogue ----
    if (P.chlast) {
        // channel-last [n][p][c]: v0,v1 are adjacent channels -> float2 store
#pragma unroll
        for (int t = 0; t < 4; t++) {
#pragma unroll
            for (int h = 0; h < 2; h++) {
                int row = m0 + wm + 16 * t + g + 8 * h;
                size_t base = (size_t)row * CH;
#pragma unroll
                for (int u = 0; u < 4; u++) {
                    int col = n0 + wn + 8 * u + tg * 2;
                    float2 v2 = make_float2(acc[t][u][2 * h], acc[t][u][2 * h + 1]);
                    *reinterpret_cast<float2*>(&out[base + col]) = v2;
                }
            }
        }
    } else {
#pragma unroll
        for (int t = 0; t < 4; t++) {
#pragma unroll
            for (int h = 0; h < 2; h++) {
                int row = m0 + wm + 16 * t + g + 8 * h;
                int n = row / 49, p = row - 49 * n;
                size_t base = (size_t)n * CH * 49 + p;
#pragma unroll
                for (int u = 0; u < 4; u++) {
                    int col = n0 + wn + 8 * u + tg * 2;
                    size_t i0 = base + (size_t)col * 49;
                    float v0 = acc[t][u][2 * h];
                    float v1 = acc[t][u][2 * h + 1];
                    if (addsrc) { v0 += addsrc[i0]; v1 += addsrc[i0 + 49]; }
                    out[i0] = v0;
                    out[i0 + 49] = v1;
                }
            }
        }
    }
}

// ---------------- q-conv via collapsed weights, channel-last out ----------
__global__ void q_conv2b(const float* __restrict__ status, const float* __restrict__ rois,
                         const float* __restrict__ Wq,
                         float* __restrict__ o1, float* __restrict__ o2) {
    int idx = blockIdx.x * 256 + threadIdx.x;
    if (idx >= NSAMP * CH * HW) return;
    int br = blockIdx.y;
    float* out = br ? o2 : o1;
    int c = idx & 511;
    int t2 = idx >> 9;            // n*49 + p
    int n = t2 / 49, p = t2 - 49 * n;
    int y = p / 7, x = p - 7 * y;
    int cy = (y == 0) ? 0 : ((y == 6) ? 2 : 1);
    int cx = (x == 0) ? 0 : ((x == 6) ? 2 : 1);
    const float* wq = Wq + (((size_t)br * 9 + cy * 3 + cx) * 512 + c) * 5;
    float acc = wq[0] * status[n * 2 + br]
              + wq[1] * rois[n * 5 + 1] + wq[2] * rois[n * 5 + 2]
              + wq[3] * rois[n * 5 + 3] + wq[4] * rois[n * 5 + 4];
    out[idx] = acc;
}

// ---------------- attention per (hw, g), z = branch; channel-last I/O --------
#define CCH 256
__global__ void attn2(const float* __restrict__ q1, const float* __restrict__ k1,
                      const float* __restrict__ v1, float* __restrict__ w1,
                      const float* __restrict__ q2, const float* __restrict__ k2,
                      const float* __restrict__ v2, float* __restrict__ w2) {
    int hw = blockIdx.x;
    int gg = blockIdx.y;
    int br = blockIdx.z;
    const float* q = br ? q2 : q1;
    const float* k = br ? k2 : k1;
    const float* v = br ? v2 : v1;
    float* virt = br ? w2 : w1;

    __shared__ float bufA[GSZ][CCH + 1];
    __shared__ float bufB[GSZ][CCH + 1];
    __shared__ float att[GSZ][GSZ + 1];
    __shared__ float attn[GSZ][GSZ + 1];

    int tid = threadIdx.x;
    int i = tid >> 4, j = tid & 15;
    float a = 0.f;

    for (int c0 = 0; c0 < CH; c0 += CCH) {
        for (int e = tid; e < GSZ * CCH; e += 256) {
            int r = e >> 8, c = e & 255;
            size_t gidx = ((size_t)(gg * GSZ + r) * 49 + hw) * CH + c0 + c;   // coalesced
            bufA[r][c] = q[gidx];
            bufB[r][c] = k[gidx];
        }
        __syncthreads();
#pragma unroll 8
        for (int c = 0; c < CCH; c++)
            a += bufA[i][c] * bufB[j][c];
        __syncthreads();
    }
    att[i][j] = a * ATT_SCALE;
    __syncthreads();

    float mx = att[i][0];
#pragma unroll
    for (int jj = 1; jj < GSZ; jj++) mx = fmaxf(mx, att[i][jj]);
    float sum = 0.f;
#pragma unroll
    for (int jj = 0; jj < GSZ; jj++) sum += expf(att[i][jj] - mx);
    attn[i][j] = expf(att[i][j] - mx) / sum;
    __syncthreads();

    for (int c0 = 0; c0 < CH; c0 += CCH) {
        for (int e = tid; e < GSZ * CCH; e += 256) {
            int r = e >> 8, c = e & 255;
            bufA[r][c] = v[((size_t)(gg * GSZ + r) * 49 + hw) * CH + c0 + c];
        }
        __syncthreads();
        for (int e = tid; e < GSZ * CCH; e += 256) {
            int r = e >> 8, c = e & 255;
            float s = 0.f;
#pragma unroll
            for (int jj = 0; jj < GSZ; jj++) s += attn[r][jj] * bufA[jj][c];
            virt[((size_t)(gg * GSZ + r) * 49 + hw) * CH + c0 + c] = s;
        }
        __syncthreads();
    }
}

// ---------------- groupnorm stats, both branches (layout-agnostic) ----------
__global__ void gn_stats2(const float* __restrict__ x1, const float* __restrict__ x2,
                          float* __restrict__ stats) {
    __shared__ float ss[256], sq[256];
    int blk = blockIdx.x;
    int br = blk >> 8, n = blk & 255;
    const float* p = (br ? x2 : x1) + (size_t)n * CH * HW;
    float a = 0.f, b = 0.f;
    for (int e = threadIdx.x; e < CH * HW; e += 256) {
        float v = p[e];
        a += v; b += v * v;
    }
    ss[threadIdx.x] = a; sq[threadIdx.x] = b;
    __syncthreads();
    for (int s = 128; s > 0; s >>= 1) {
        if (threadIdx.x < s) { ss[threadIdx.x] += ss[threadIdx.x + s]; sq[threadIdx.x] += sq[threadIdx.x + s]; }
        __syncthreads();
    }
    if (threadIdx.x == 0) {
        float m = ss[0] / (float)(CH * HW);
        float var = sq[0] / (float)(CH * HW) - m * m;
        stats[br * 512 + n] = m;
        stats[br * 512 + 256 + n] = rsqrtf(var + EPSG);
    }
}

// ---------------- launcher ----------------
extern "C" void kernel_launch(void* const* d_in, const int* in_sizes, int n_in,
                              void* d_out, int out_size) {
    const float* status = (const float*)d_in[0];
    const float* rois   = (const float*)d_in[1];
    const float* bbox   = (const float*)d_in[2];
    const float* wR     = (const float*)d_in[3];
    const float* wQ1    = (const float*)d_in[4];
    const float* wQ2    = (const float*)d_in[5];
    const float* wK1    = (const float*)d_in[6];
    const float* wV1    = (const float*)d_in[7];
    const float* wK2    = (const float*)d_in[8];
    const float* wV2    = (const float*)d_in[9];
    const float* wC1    = (const float*)d_in[10];
    const float* wC2    = (const float*)d_in[11];
    const float* gamma  = (const float*)d_in[12];
    const float* beta   = (const float*)d_in[13];
    float* out1 = (float*)d_out;
    float* out2 = out1 + FEAT_ELEMS;

    float *feat, *q1, *q2, *k1, *v1, *k2, *v2, *vir1, *vir2, *stats, *wqv;
    cudaGetSymbolAddress((void**)&feat, g_feat);
    cudaGetSymbolAddress((void**)&q1,   g_q1);
    cudaGetSymbolAddress((void**)&q2,   g_q2);
    cudaGetSymbolAddress((void**)&k1,   g_k1);
    cudaGetSymbolAddress((void**)&v1,   g_v1);
    cudaGetSymbolAddress((void**)&k2,   g_k2);
    cudaGetSymbolAddress((void**)&v2,   g_v2);
    cudaGetSymbolAddress((void**)&vir1, g_vir1);
    cudaGetSymbolAddress((void**)&vir2, g_vir2);
    cudaGetSymbolAddress((void**)&stats, g_stats);
    cudaGetSymbolAddress((void**)&wqv,  g_wq);

    __half *bpad, *fpad, *h1p, *h2p;
    cudaGetSymbolAddress((void**)&bpad, g_bpad);
    cudaGetSymbolAddress((void**)&fpad, g_fpad);
    cudaGetSymbolAddress((void**)&h1p,  g_h1pad);
    cudaGetSymbolAddress((void**)&h2p,  g_h2pad);

    __half *whR, *whK1, *whV1, *whK2, *whV2, *whC1, *whC2;
    cudaGetSymbolAddress((void**)&whR,  g_wR);
    cudaGetSymbolAddress((void**)&whK1, g_wK1);
    cudaGetSymbolAddress((void**)&whV1, g_wV1);
    cudaGetSymbolAddress((void**)&whK2, g_wK2);
    cudaGetSymbolAddress((void**)&whV2, g_wV2);
    cudaGetSymbolAddress((void**)&whC1, g_wC1);
    cudaGetSymbolAddress((void**)&whC2, g_wC2);

    cudaFuncSetAttribute(conv_mma, cudaFuncAttributeMaxDynamicSharedMemorySize, SMEM_BYTES);

    // merged weight reorder + fp16 round (1 launch for all 7)
    const int nR = K_RED * CH, nC = K_CC * CH;
    {
        WReorder R;
        R.src[0] = wR;  R.dst[0] = whR;  R.C[0] = CIN;
        R.src[1] = wK1; R.dst[1] = whK1; R.C[1] = CH;
        R.src[2] = wV1; R.dst[2] = whV1; R.C[2] = CH;
        R.src[3] = wK2; R.dst[3] = whK2; R.C[3] = CH;
        R.src[4] = wV2; R.dst[4] = whV2; R.C[4] = CH;
        R.src[5] = wC1; R.dst[5] = whC1; R.C[5] = CH;
        R.src[6] = wC2; R.dst[6] = whC2; R.C[6] = CH;
        R.base[0] = 0;
        R.base[1] = nR;
        for (int k = 2; k <= 7; k++) R.base[k] = R.base[k - 1] + nC;
        int total = R.base[7];
        conv_w_reorder_all<<<(total + 255) / 256, 256>>>(R, total);
    }

    // q-conv weight collapse
    qw_prep<<<(2 * 9 * 512 + 255) / 256, 256>>>(wQ1, wQ2, wqv);

    // pad-convert bbox
    pad_convert<<<dim3(NSAMP, CIN / 64), 256>>>(bbox, bpad, CIN);

    // reduce conv split-K=3 (NCHW partials)
    {
        ConvBatch P = {};
        for (int z = 0; z < 3; z++) { P.a[z] = bpad; P.wh[z] = whR; P.tap0[z] = 3 * z; }
        P.out[0] = k1; P.out[1] = v1; P.out[2] = k2;
        P.addsrc = nullptr; P.chlast = 0;
        conv_mma<<<dim3(NSAMP * HW / 128, CH / 128, 3), 256, SMEM_BYTES>>>(P, CIN, 3);
    }

    // combine partials -> feat (NCHW float) + fpad (fp16 padded channel-last)
    combine3_pad<<<dim3(NSAMP, CH / 64), 256>>>(k1, v1, k2, feat, fpad);

    // q convs (collapsed), channel-last, both branches
    q_conv2b<<<dim3((FEAT_ELEMS + 255) / 256, 2), 256>>>(status, rois, wqv, q1, q2);

    // k/v convs (4 fused), channel-last outputs
    {
        ConvBatch P = {};
        for (int i = 0; i < 4; i++) { P.a[i] = fpad; P.tap0[i] = 0; }
        P.wh[0] = whK1; P.out[0] = k1;
        P.wh[1] = whV1; P.out[1] = v1;
        P.wh[2] = whK2; P.out[2] = k2;
        P.wh[3] = whV2; P.out[3] = v2;
        P.addsrc = nullptr; P.chlast = 1;
        conv_mma<<<dim3(NSAMP * HW / 128, CH / 128, 4), 256, SMEM_BYTES>>>(P, CH, 9);
    }

    // attention, both branches (channel-last coalesced)
    attn2<<<dim3(HW, NG, 2), 256>>>(q1, k1, v1, vir1, q2, k2, v2, vir2);

    // groupnorm stats, both branches
    gn_stats2<<<512, 256>>>(vir1, vir2, stats);

    // fused normalize+relu+pad-convert, elementwise channel-last
    norm_relu_pad<<<dim3((FEAT_ELEMS + 255) / 256, 2), 256>>>(vir1, vir2, stats,
                                                              gamma, beta, h1p, h2p);

    // out convs (2 fused): out = feat + conv(h, w_c), NCHW
    {
        ConvBatch P = {};
        P.a[0] = h1p; P.wh[0] = whC1; P.out[0] = out1; P.tap0[0] = 0;
        P.a[1] = h2p; P.wh[1] = whC2; P.out[1] = out2; P.tap0[1] = 0;
        P.addsrc = feat; P.chlast = 0;
        conv_mma<<<dim3(NSAMP * HW / 128, CH / 128, 2), 256, SMEM_BYTES>>>(P, CH, 9);
    }
}

// round 12
// speedup vs baseline: 9.7695x; 1.0430x over previous
#include <cuda_runtime.h>
#include <cuda_fp16.h>
#include <cstdint>
#include <math.h>

// ---------------- problem constants ----------------
#define NSAMP 256
#define CIN   2304
#define CH    512
#define HW    49
#define NG    16
#define GSZ   16
#define K_RED (CIN*9)    // 20736
#define K_CC  (CH*9)     // 4608
#define FEAT_ELEMS (NSAMP*CH*HW)   // 6422528
#define EPSG  1e-5f
#define ATT_SCALE 0.044194173824159216f  // 1/sqrt(512)

// ---------------- scratch (device globals; no allocation) ----------------
// feat is NCHW (fp32 residual for the final convs).
// k/v and virt are CHANNEL-LAST: [n][p][c] with c contiguous.
__device__ float g_feat [FEAT_ELEMS];
__device__ float g_k1   [FEAT_ELEMS];   // also reduce-conv partial 0 (NCHW)
__device__ float g_v1   [FEAT_ELEMS];   // also reduce-conv partial 1 (NCHW)
__device__ float g_k2   [FEAT_ELEMS];   // also reduce-conv partial 2 (NCHW)
__device__ float g_v2   [FEAT_ELEMS];
__device__ float g_vir1 [FEAT_ELEMS];
__device__ float g_vir2 [FEAT_ELEMS];
__device__ float g_stats[1024];
__device__ float g_wq[2*9*512*5];       // q-conv collapsed weights

// padded channel-last activations: [n][81][C], fp16.
// Borders are NEVER written: __device__ globals are zero-initialized at module
// load, so the pad border stays zero forever (deterministic).
__device__ __align__(256) __half g_bpad [NSAMP*81*CIN];
__device__ __align__(256) __half g_fpad [NSAMP*81*CH];
__device__ __align__(256) __half g_h1pad[NSAMP*81*CH];
__device__ __align__(256) __half g_h2pad[NSAMP*81*CH];

// fp16 weights, tap-major layout [co][tap][ci]
__device__ __align__(256) __half g_wR [K_RED*CH];
__device__ __align__(256) __half g_wK1[K_CC*CH];
__device__ __align__(256) __half g_wV1[K_CC*CH];
__device__ __align__(256) __half g_wK2[K_CC*CH];
__device__ __align__(256) __half g_wV2[K_CC*CH];
__device__ __align__(256) __half g_wC1[K_CC*CH];
__device__ __align__(256) __half g_wC2[K_CC*CH];

// ---------------- helpers ----------------
__device__ __forceinline__ uint32_t smem_u32(const void* p) {
    uint32_t a;
    asm("{ .reg .u64 t; cvta.to.shared.u64 t, %1; cvt.u32.u64 %0, t; }" : "=r"(a) : "l"(p));
    return a;
}
__device__ __forceinline__ void cp_async16(uint32_t dst, const void* src) {
    asm volatile("cp.async.cg.shared.global [%0], [%1], 16;" :: "r"(dst), "l"(src));
}
__device__ __forceinline__ void ldm_x4(uint32_t* r, uint32_t addr) {
    asm volatile("ldmatrix.sync.aligned.m8n8.x4.shared.b16 {%0,%1,%2,%3}, [%4];"
        : "=r"(r[0]), "=r"(r[1]), "=r"(r[2]), "=r"(r[3]) : "r"(addr));
}
__device__ __forceinline__ void mma_f16(float* d, const uint32_t* a, const uint32_t* b) {
    asm volatile(
        "mma.sync.aligned.m16n8k16.row.col.f32.f16.f16.f32 "
        "{%0,%1,%2,%3}, {%4,%5,%6,%7}, {%8,%9}, {%0,%1,%2,%3};\n"
        : "+f"(d[0]), "+f"(d[1]), "+f"(d[2]), "+f"(d[3])
        : "r"(a[0]), "r"(a[1]), "r"(a[2]), "r"(a[3]), "r"(b[0]), "r"(b[1]));
}

// -------- coalesced weight reorder + fp16 round: w[co][ci*9+t] -> wh[co][t*C+ci]
// One block per (x-slot, co). Each x-slot = (weight s, ci0 range of 256 channels).
// Loads a contiguous 2304-float slice, stores 9 coalesced 256-half runs.
struct WReorder2 {
    const float* src[7];
    __half* dst[7];
    int C[7];
    int sidx[21];
    int ci0[21];
};
__global__ void conv_w_reorder2(WReorder2 R) {
    int s = R.sidx[blockIdx.x];
    int ci0 = R.ci0[blockIdx.x];
    int co = blockIdx.y;
    int C = R.C[s];
    int K9 = 9 * C;
    const float* src = R.src[s] + (size_t)co * K9 + (size_t)ci0 * 9;
    __half* dst = R.dst[s] + (size_t)co * K9;
    __shared__ float sm[2304];
    int tid = threadIdx.x;
#pragma unroll
    for (int i = 0; i < 9; i++) sm[tid + 256 * i] = src[tid + 256 * i];
    __syncthreads();
#pragma unroll
    for (int t = 0; t < 9; t++)
        dst[t * C + ci0 + tid] = __float2half_rn(sm[tid * 9 + t]);   // stride 9: conflict-free
}

// ---------------- q-conv weight collapse: Wq[br][cls][co][ci] ----------------
__global__ void qw_prep(const float* __restrict__ wq1, const float* __restrict__ wq2,
                        float* __restrict__ Wq) {
    int i = blockIdx.x * 256 + threadIdx.x;
    if (i >= 2 * 9 * 512) return;
    int br = i / (9 * 512);
    int rem = i - br * 9 * 512;
    int cls = rem / 512, co = rem - cls * 512;
    int cy = cls / 3, cx = cls - 3 * cy;
    const float* w = (br ? wq2 : wq1) + co * 45;
#pragma unroll
    for (int ci = 0; ci < 5; ci++) {
        float s = 0.f;
#pragma unroll
        for (int dy = 0; dy < 3; dy++) {
            if (cy == 0 && dy == 0) continue;
            if (cy == 2 && dy == 2) continue;
#pragma unroll
            for (int dx = 0; dx < 3; dx++) {
                if (cx == 0 && dx == 0) continue;
                if (cx == 2 && dx == 2) continue;
                s += w[ci * 9 + dy * 3 + dx];
            }
        }
        Wq[((br * 9 + cls) * 512 + co) * 5 + ci] = s;
    }
}

// ---------------- NCHW float -> padded channel-last fp16 (interior only) ------
__global__ void pad_convert(const float* __restrict__ src, __half* __restrict__ hi, int C) {
    int n = blockIdx.x, c0 = blockIdx.y * 64;
    __shared__ float tile[64][51];
    int tid = threadIdx.x;
    for (int e = tid; e < 64 * 49; e += 256) {
        int ci = e / 49, p = e - 49 * ci;
        tile[ci][p] = src[((size_t)n * C + c0 + ci) * 49 + p];
    }
    __syncthreads();
    for (int e = tid; e < 49 * 64; e += 256) {
        int p = e >> 6, ci = e & 63;
        int y = p / 7, x = p - 7 * y;
        hi[((size_t)n * 81 + (y + 1) * 9 + (x + 1)) * C + c0 + ci] =
            __float2half_rn(tile[ci][p]);
    }
}

// ---------------- combine 3 split-K partials -> feat (float) + fpad (fp16) ----
__global__ void combine3_pad(const float* __restrict__ p0, const float* __restrict__ p1,
                             const float* __restrict__ p2,
                             float* __restrict__ feat, __half* __restrict__ fpad) {
    int n = blockIdx.x, c0 = blockIdx.y * 64;
    __shared__ float tile[64][51];
    int tid = threadIdx.x;
    for (int e = tid; e < 64 * 49; e += 256) {
        int ci = e / 49, p = e - 49 * ci;
        size_t idx = ((size_t)n * CH + c0 + ci) * 49 + p;
        float v = p0[idx] + p1[idx] + p2[idx];
        feat[idx] = v;
        tile[ci][p] = v;
    }
    __syncthreads();
    for (int e = tid; e < 49 * 64; e += 256) {
        int p = e >> 6, ci = e & 63;
        int y = p / 7, x = p - 7 * y;
        fpad[((size_t)n * 81 + (y + 1) * 9 + (x + 1)) * CH + c0 + ci] =
            __float2half_rn(tile[ci][p]);
    }
}

// ------- fused GN-normalize + relu + pad-convert, channel-last, elementwise ---
__global__ void norm_relu_pad(const float* __restrict__ x1, const float* __restrict__ x2,
                              const float* __restrict__ stats,
                              const float* __restrict__ gamma, const float* __restrict__ beta,
                              __half* __restrict__ h1, __half* __restrict__ h2) {
    int idx = blockIdx.x * 256 + threadIdx.x;
    if (idx >= FEAT_ELEMS) return;
    int br = blockIdx.y;
    const float* x = br ? x2 : x1;
    __half* hp = br ? h2 : h1;
    int c = idx & 511;
    int t = idx >> 9;
    int n = t / 49, p = t - 49 * n;
    float mu = stats[br * 512 + n];
    float rs = stats[br * 512 + 256 + n];
    float v = fmaxf((x[idx] - mu) * rs * gamma[c] + beta[c], 0.f);
    int y = p / 7, xq = p - 7 * y;
    hp[((size_t)n * 81 + (y + 1) * 9 + (xq + 1)) * CH + c] = __float2half_rn(v);
}

// ---------------- batched HMMA conv: shifted 1x1 GEMMs over padded input ------
#define KC   64
#define KCP  72
#define MATH (128*KCP)
#define BUFE (2*MATH)
#define NSTG 3
#define SMEM_BYTES (NSTG*BUFE*2)     // 110592 bytes

struct ConvBatch {
    const __half* a[4];
    const __half* wh[4];
    float* out[4];
    const float* addsrc;
    int tap0[4];
    int chlast;
};

__global__ void __launch_bounds__(256, 2)
conv_mma(ConvBatch P, int C, int ntap) {
    extern __shared__ __half smem[];
    const int K9 = 9 * C;
    const int NCI = C / KC;
    const int NQ = ntap * NCI;
    const int cv = blockIdx.z;
    const __half* __restrict__ A  = P.a[cv];
    const __half* __restrict__ Wh = P.wh[cv];
    float* __restrict__ out = P.out[cv];
    const float* addsrc = P.addsrc;
    const int tap0 = P.tap0[cv];

    const int tid = threadIdx.x;
    const int wid = tid >> 5, lane = tid & 31;
    const int g = lane >> 2, tg = lane & 3;
    const int m0 = blockIdx.x * 128;
    const int n0 = blockIdx.y * 128;
    const int wm = (wid & 1) * 64;
    const int wn = (wid >> 1) * 32;

    const int seg = tid & 7;
    const int r0 = tid >> 3;
    size_t abase[4];
#pragma unroll
    for (int h = 0; h < 4; h++) {
        int m = m0 + r0 + 32 * h;
        int n = m / 49, p = m - 49 * n;
        int y = p / 7, x = p - 7 * y;
        abase[h] = ((size_t)n * 81 + y * 9 + x) * C + seg * 8;
    }

    const int aRow = wm + (lane & 15);
    const int aCol = (lane >> 4) * 8;
    const int bRow = wn + (lane & 7) + ((lane >> 4) * 8);
    const int bCol = ((lane >> 3) & 1) * 8;

    auto fill = [&](int q) {
        __half* base = smem + (q % NSTG) * BUFE;
        int t = tap0 + q / NCI;
        int ci = (q % NCI) * KC;
        int a3 = t / 3, b3 = t - 3 * a3;
        size_t tof = (size_t)(a3 * 9 + b3) * C + ci;
#pragma unroll
        for (int h = 0; h < 4; h++) {
            int r = r0 + 32 * h;
            cp_async16(smem_u32(&base[r * KCP + seg * 8]), A + abase[h] + tof);
        }
#pragma unroll
        for (int h = 0; h < 4; h++) {
            int row = r0 + 32 * h;
            size_t src = (size_t)(n0 + row) * K9 + t * C + ci + seg * 8;
            cp_async16(smem_u32(&base[MATH + row * KCP + seg * 8]), Wh + src);
        }
        asm volatile("cp.async.commit_group;" ::: "memory");
    };

    float acc[4][4][4];
#pragma unroll
    for (int t = 0; t < 4; t++)
#pragma unroll
        for (int u = 0; u < 4; u++)
#pragma unroll
            for (int e = 0; e < 4; e++) acc[t][u][e] = 0.f;

    fill(0);
    if (NQ > 1) fill(1);

    for (int q = 0; q < NQ; q++) {
        if (q + 1 < NQ) asm volatile("cp.async.wait_group 1;" ::: "memory");
        else            asm volatile("cp.async.wait_group 0;" ::: "memory");
        __syncthreads();
        if (q + 2 < NQ) fill(q + 2);

        __half* cur = smem + (q % NSTG) * BUFE;
        uint32_t aB = smem_u32(cur);
        uint32_t bB = aB + MATH * 2;
#pragma unroll
        for (int s = 0; s < 4; s++) {
            uint32_t bregs[8];
            ldm_x4(bregs,     bB + (uint32_t)((bRow)      * KCP + 16 * s + bCol) * 2);
            ldm_x4(bregs + 4, bB + (uint32_t)((bRow + 16) * KCP + 16 * s + bCol) * 2);
#pragma unroll
            for (int t = 0; t < 4; t++) {
                uint32_t ar[4];
                ldm_x4(ar, aB + (uint32_t)((aRow + 16 * t) * KCP + 16 * s + aCol) * 2);
#pragma unroll
                for (int u = 0; u < 4; u++)
                    mma_f16(acc[t][u], ar, bregs + 2 * u);
            }
        }
    }

    // ---- epilogue ----
    if (P.chlast) {
#pragma unroll
        for (int t = 0; t < 4; t++) {
#pragma unroll
            for (int h = 0; h < 2; h++) {
                int row = m0 + wm + 16 * t + g + 8 * h;
                size_t base = (size_t)row * CH;
#pragma unroll
                for (int u = 0; u < 4; u++) {
                    int col = n0 + wn + 8 * u + tg * 2;
                    float2 v2 = make_float2(acc[t][u][2 * h], acc[t][u][2 * h + 1]);
                    *reinterpret_cast<float2*>(&out[base + col]) = v2;
                }
            }
        }
    } else {
#pragma unroll
        for (int t = 0; t < 4; t++) {
#pragma unroll
            for (int h = 0; h < 2; h++) {
                int row = m0 + wm + 16 * t + g + 8 * h;
                int n = row / 49, p = row - 49 * n;
                size_t base = (size_t)n * CH * 49 + p;
#pragma unroll
                for (int u = 0; u < 4; u++) {
                    int col = n0 + wn + 8 * u + tg * 2;
                    size_t i0 = base + (size_t)col * 49;
                    float v0 = acc[t][u][2 * h];
                    float v1 = acc[t][u][2 * h + 1];
                    if (addsrc) { v0 += addsrc[i0]; v1 += addsrc[i0 + 49]; }
                    out[i0] = v0;
                    out[i0 + 49] = v1;
                }
            }
        }
    }
}

// ------- attention per (hw, g, br); q computed on the fly from Wq x s5 --------
#define CCH 256
__global__ void attn2(const float* __restrict__ status, const float* __restrict__ rois,
                      const float* __restrict__ Wq,
                      const float* __restrict__ k1, const float* __restrict__ v1,
                      float* __restrict__ w1,
                      const float* __restrict__ k2, const float* __restrict__ v2,
                      float* __restrict__ w2) {
    int hw = blockIdx.x;
    int gg = blockIdx.y;
    int br = blockIdx.z;
    const float* k = br ? k2 : k1;
    const float* v = br ? v2 : v1;
    float* virt = br ? w2 : w1;

    int yy = hw / 7, xx = hw - 7 * yy;
    int cy = (yy == 0) ? 0 : ((yy == 6) ? 2 : 1);
    int cx = (xx == 0) ? 0 : ((xx == 6) ? 2 : 1);
    const float* WqBase = Wq + ((size_t)(br * 9 + cy * 3 + cx) * 512) * 5;

    __shared__ float bufA[GSZ][CCH + 1];
    __shared__ float bufB[GSZ][CCH + 1];
    __shared__ float att[GSZ][GSZ + 1];
    __shared__ float attn[GSZ][GSZ + 1];
    __shared__ float s5[GSZ][5];
    __shared__ float wqs[CCH][5];

    int tid = threadIdx.x;
    int i = tid >> 4, j = tid & 15;

    if (tid < GSZ * 5) {
        int r = tid / 5, ci = tid - 5 * r;
        int n = gg * GSZ + r;
        s5[r][ci] = (ci == 0) ? status[n * 2 + br] : rois[n * 5 + ci];
    }
    __syncthreads();

    float a = 0.f;
    for (int c0 = 0; c0 < CH; c0 += CCH) {
        // load Wq chunk + k chunk
        for (int e = tid; e < CCH * 5; e += 256)
            wqs[e / 5][e % 5] = WqBase[(size_t)(c0 + e / 5) * 5 + (e % 5)];
        for (int e = tid; e < GSZ * CCH; e += 256) {
            int r = e >> 8, c = e & 255;
            bufB[r][c] = k[((size_t)(gg * GSZ + r) * 49 + hw) * CH + c0 + c];
        }
        __syncthreads();
        // materialize q chunk: bufA[r][c] = Wq[c] . s5[r]
        for (int e = tid; e < GSZ * CCH; e += 256) {
            int r = e >> 8, c = e & 255;
            bufA[r][c] = wqs[c][0] * s5[r][0] + wqs[c][1] * s5[r][1]
                       + wqs[c][2] * s5[r][2] + wqs[c][3] * s5[r][3]
                       + wqs[c][4] * s5[r][4];
        }
        __syncthreads();
#pragma unroll 8
        for (int c = 0; c < CCH; c++)
            a += bufA[i][c] * bufB[j][c];
        __syncthreads();
    }
    att[i][j] = a * ATT_SCALE;
    __syncthreads();

    float mx = att[i][0];
#pragma unroll
    for (int jj = 1; jj < GSZ; jj++) mx = fmaxf(mx, att[i][jj]);
    float sum = 0.f;
#pragma unroll
    for (int jj = 0; jj < GSZ; jj++) sum += expf(att[i][jj] - mx);
    attn[i][j] = expf(att[i][j] - mx) / sum;
    __syncthreads();

    for (int c0 = 0; c0 < CH; c0 += CCH) {
        for (int e = tid; e < GSZ * CCH; e += 256) {
            int r = e >> 8, c = e & 255;
            bufA[r][c] = v[((size_t)(gg * GSZ + r) * 49 + hw) * CH + c0 + c];
        }
        __syncthreads();
        for (int e = tid; e < GSZ * CCH; e += 256) {
            int r = e >> 8, c = e & 255;
            float s = 0.f;
#pragma unroll
            for (int jj = 0; jj < GSZ; jj++) s += attn[r][jj] * bufA[jj][c];
            virt[((size_t)(gg * GSZ + r) * 49 + hw) * CH + c0 + c] = s;
        }
        __syncthreads();
    }
}

// ---------------- groupnorm stats, both branches ----------
__global__ void gn_stats2(const float* __restrict__ x1, const float* __restrict__ x2,
                          float* __restrict__ stats) {
    __shared__ float ss[256], sq[256];
    int blk = blockIdx.x;
    int br = blk >> 8, n = blk & 255;
    const float* p = (br ? x2 : x1) + (size_t)n * CH * HW;
    float a = 0.f, b = 0.f;
    for (int e = threadIdx.x; e < CH * HW; e += 256) {
        float v = p[e];
        a += v; b += v * v;
    }
    ss[threadIdx.x] = a; sq[threadIdx.x] = b;
    __syncthreads();
    for (int s = 128; s > 0; s >>= 1) {
        if (threadIdx.x < s) { ss[threadIdx.x] += ss[threadIdx.x + s]; sq[threadIdx.x] += sq[threadIdx.x + s]; }
        __syncthreads();
    }
    if (threadIdx.x == 0) {
        float m = ss[0] / (float)(CH * HW);
        float var = sq[0] / (float)(CH * HW) - m * m;
        stats[br * 512 + n] = m;
        stats[br * 512 + 256 + n] = rsqrtf(var + EPSG);
    }
}

// ---------------- launcher ----------------
extern "C" void kernel_launch(void* const* d_in, const int* in_sizes, int n_in,
                              void* d_out, int out_size) {
    const float* status = (const float*)d_in[0];
    const float* rois   = (const float*)d_in[1];
    const float* bbox   = (const float*)d_in[2];
    const float* wR     = (const float*)d_in[3];
    const float* wQ1    = (const float*)d_in[4];
    const float* wQ2    = (const float*)d_in[5];
    const float* wK1    = (const float*)d_in[6];
    const float* wV1    = (const float*)d_in[7];
    const float* wK2    = (const float*)d_in[8];
    const float* wV2    = (const float*)d_in[9];
    const float* wC1    = (const float*)d_in[10];
    const float* wC2    = (const float*)d_in[11];
    const float* gamma  = (const float*)d_in[12];
    const float* beta   = (const float*)d_in[13];
    float* out1 = (float*)d_out;
    float* out2 = out1 + FEAT_ELEMS;

    float *feat, *k1, *v1, *k2, *v2, *vir1, *vir2, *stats, *wqv;
    cudaGetSymbolAddress((void**)&feat, g_feat);
    cudaGetSymbolAddress((void**)&k1,   g_k1);
    cudaGetSymbolAddress((void**)&v1,   g_v1);
    cudaGetSymbolAddress((void**)&k2,   g_k2);
    cudaGetSymbolAddress((void**)&v2,   g_v2);
    cudaGetSymbolAddress((void**)&vir1, g_vir1);
    cudaGetSymbolAddress((void**)&vir2, g_vir2);
    cudaGetSymbolAddress((void**)&stats, g_stats);
    cudaGetSymbolAddress((void**)&wqv,  g_wq);

    __half *bpad, *fpad, *h1p, *h2p;
    cudaGetSymbolAddress((void**)&bpad, g_bpad);
    cudaGetSymbolAddress((void**)&fpad, g_fpad);
    cudaGetSymbolAddress((void**)&h1p,  g_h1pad);
    cudaGetSymbolAddress((void**)&h2p,  g_h2pad);

    __half *whR, *whK1, *whV1, *whK2, *whV2, *whC1, *whC2;
    cudaGetSymbolAddress((void**)&whR,  g_wR);
    cudaGetSymbolAddress((void**)&whK1, g_wK1);
    cudaGetSymbolAddress((void**)&whV1, g_wV1);
    cudaGetSymbolAddress((void**)&whK2, g_wK2);
    cudaGetSymbolAddress((void**)&whV2, g_wV2);
    cudaGetSymbolAddress((void**)&whC1, g_wC1);
    cudaGetSymbolAddress((void**)&whC2, g_wC2);

    cudaFuncSetAttribute(conv_mma, cudaFuncAttributeMaxDynamicSharedMemorySize, SMEM_BYTES);

    // coalesced weight reorder + fp16 round (1 launch, all 7 weights)
    {
        WReorder2 R;
        R.src[0] = wR;  R.dst[0] = whR;  R.C[0] = CIN;
        R.src[1] = wK1; R.dst[1] = whK1; R.C[1] = CH;
        R.src[2] = wV1; R.dst[2] = whV1; R.C[2] = CH;
        R.src[3] = wK2; R.dst[3] = whK2; R.C[3] = CH;
        R.src[4] = wV2; R.dst[4] = whV2; R.C[4] = CH;
        R.src[5] = wC1; R.dst[5] = whC1; R.C[5] = CH;
        R.src[6] = wC2; R.dst[6] = whC2; R.C[6] = CH;
        int x = 0;
        for (int ci0 = 0; ci0 < CIN; ci0 += 256) { R.sidx[x] = 0; R.ci0[x] = ci0; x++; }
        for (int s = 1; s < 7; s++)
            for (int ci0 = 0; ci0 < CH; ci0 += 256) { R.sidx[x] = s; R.ci0[x] = ci0; x++; }
        conv_w_reorder2<<<dim3(x, CH), 256>>>(R);   // x = 21
    }

    // q-conv weight collapse
    qw_prep<<<(2 * 9 * 512 + 255) / 256, 256>>>(wQ1, wQ2, wqv);

    // pad-convert bbox
    pad_convert<<<dim3(NSAMP, CIN / 64), 256>>>(bbox, bpad, CIN);

    // reduce conv split-K=3 (NCHW partials)
    {
        ConvBatch P = {};
        for (int z = 0; z < 3; z++) { P.a[z] = bpad; P.wh[z] = whR; P.tap0[z] = 3 * z; }
        P.out[0] = k1; P.out[1] = v1; P.out[2] = k2;
        P.addsrc = nullptr; P.chlast = 0;
        conv_mma<<<dim3(NSAMP * HW / 128, CH / 128, 3), 256, SMEM_BYTES>>>(P, CIN, 3);
    }

    // combine partials -> feat (NCHW float) + fpad (fp16 padded channel-last)
    combine3_pad<<<dim3(NSAMP, CH / 64), 256>>>(k1, v1, k2, feat, fpad);

    // k/v convs (4 fused), channel-last outputs
    {
        ConvBatch P = {};
        for (int i = 0; i < 4; i++) { P.a[i] = fpad; P.tap0[i] = 0; }
        P.wh[0] = whK1; P.out[0] = k1;
        P.wh[1] = whV1; P.out[1] = v1;
        P.wh[2] = whK2; P.out[2] = k2;
        P.wh[3] = whV2; P.out[3] = v2;
        P.addsrc = nullptr; P.chlast = 1;
        conv_mma<<<dim3(NSAMP * HW / 128, CH / 128, 4), 256, SMEM_BYTES>>>(P, CH, 9);
    }

    // attention (q fused from Wq x s5), both branches
    attn2<<<dim3(HW, NG, 2), 256>>>(status, rois, wqv, k1, v1, vir1, k2, v2, vir2);

    // groupnorm stats, both branches
    gn_stats2<<<512, 256>>>(vir1, vir2, stats);

    // fused normalize+relu+pad-convert, elementwise channel-last
    norm_relu_pad<<<dim3((FEAT_ELEMS + 255) / 256, 2), 256>>>(vir1, vir2, stats,
                                                              gamma, beta, h1p, h2p);

    // out convs (2 fused): out = feat + conv(h, w_c), NCHW
    {
        ConvBatch P = {};
        P.a[0] = h1p; P.wh[0] = whC1; P.out[0] = out1; P.tap0[0] = 0;
        P.a[1] = h2p; P.wh[1] = whC2; P.out[1] = out2; P.tap0[1] = 0;
        P.addsrc = feat; P.chlast = 0;
        conv_mma<<<dim3(NSAMP * HW / 128, CH / 128, 2), 256, SMEM_BYTES>>>(P, CH, 9);
    }
}